// round 1
// baseline (speedup 1.0000x reference)
#include <cuda_runtime.h>
#include <cstdint>

// ---------------- problem constants ----------------
#define BB   2
#define TT   2048
#define DD   1024
#define HH   16
#define HDIM 64
#define FF   4096
#define ROWS (BB*TT)          // 4096

// ---------------- scratch (device globals; no allocs allowed) ----------------
__device__ float g_xa  [ROWS*DD];   // rmsnorm output (reused for both norms)
__device__ float g_q   [ROWS*DD];
__device__ float g_k   [ROWS*DD];
__device__ float g_v   [ROWS*DD];
__device__ float g_at  [ROWS*DD];   // attention output (B,T,D)
__device__ float g_x1  [ROWS*DD];   // x + attn@Wo + bo
__device__ float g_h   [ROWS*FF];   // FFN hidden

// ---------------- rmsnorm ----------------
__global__ __launch_bounds__(256)
void rmsnorm_kernel(const float* __restrict__ x, const float* __restrict__ g,
                    float* __restrict__ out) {
    __shared__ float red[256];
    const int row = blockIdx.x;
    const int tid = threadIdx.x;
    const float4 v = ((const float4*)(x + (size_t)row * DD))[tid];
    float ss = v.x*v.x + v.y*v.y + v.z*v.z + v.w*v.w;
    red[tid] = ss;
    __syncthreads();
    #pragma unroll
    for (int s = 128; s > 0; s >>= 1) {
        if (tid < s) red[tid] += red[tid + s];
        __syncthreads();
    }
    const float norm = rsqrtf(red[0] * (1.0f / DD) + 1e-5f);
    const float4 gv = ((const float4*)g)[tid];
    float4 o;
    o.x = v.x * norm * gv.x;
    o.y = v.y * norm * gv.y;
    o.z = v.z * norm * gv.z;
    o.w = v.w * norm * gv.w;
    ((float4*)(out + (size_t)row * DD))[tid] = o;
}

// ---------------- SGEMM: C = A[M,K] @ W[K,N] (+epilogue) ----------------
// EPI 0: none.  EPI 1: C = res + acc + bias.  EPI 2: C = silu(acc + bias).
// BM=BN=128, BK=16, 256 threads, 8x8 per thread. blockIdx.z selects {W,C} set.
template <int EPI>
__global__ __launch_bounds__(256)
void gemm_kernel(const float* __restrict__ A,
                 const float* __restrict__ W0, const float* __restrict__ W1,
                 const float* __restrict__ W2,
                 float* __restrict__ C0, float* __restrict__ C1, float* __restrict__ C2,
                 const float* __restrict__ bias, const float* __restrict__ res,
                 int M, int N, int K) {
    __shared__ float As[16 * 128];
    __shared__ float Bs[16 * 128];

    const float* W = (blockIdx.z == 0) ? W0 : (blockIdx.z == 1 ? W1 : W2);
    float*       C = (blockIdx.z == 0) ? C0 : (blockIdx.z == 1 ? C1 : C2);

    const int tid = threadIdx.x;
    const int bm = blockIdx.y, bn = blockIdx.x;
    const int ty = tid >> 4, tx = tid & 15;

    float acc[8][8];
    #pragma unroll
    for (int i = 0; i < 8; i++)
        #pragma unroll
        for (int j = 0; j < 8; j++) acc[i][j] = 0.f;

    const float* Ab = A + (size_t)bm * 128 * K;
    const float* Wb = W + (size_t)bn * 128;

    for (int kb = 0; kb < K; kb += 16) {
        // load A tile (128x16), store transposed As[k][m]
        #pragma unroll
        for (int t = 0; t < 2; t++) {
            int qi  = tid + t * 256;
            int row = qi >> 2;
            int c4  = (qi & 3) << 2;
            float4 v = *(const float4*)(Ab + (size_t)row * K + kb + c4);
            As[(c4 + 0) * 128 + row] = v.x;
            As[(c4 + 1) * 128 + row] = v.y;
            As[(c4 + 2) * 128 + row] = v.z;
            As[(c4 + 3) * 128 + row] = v.w;
        }
        // load B tile (16x128)
        #pragma unroll
        for (int t = 0; t < 2; t++) {
            int qi  = tid + t * 256;
            int row = qi >> 5;
            int c4  = (qi & 31) << 2;
            *(float4*)(Bs + row * 128 + c4) =
                *(const float4*)(Wb + (size_t)(kb + row) * N + c4);
        }
        __syncthreads();

        #pragma unroll
        for (int k = 0; k < 16; k++) {
            float a[8], b[8];
            *(float4*)(a)     = *(const float4*)(As + k * 128 + ty * 8);
            *(float4*)(a + 4) = *(const float4*)(As + k * 128 + ty * 8 + 4);
            *(float4*)(b)     = *(const float4*)(Bs + k * 128 + tx * 8);
            *(float4*)(b + 4) = *(const float4*)(Bs + k * 128 + tx * 8 + 4);
            #pragma unroll
            for (int i = 0; i < 8; i++)
                #pragma unroll
                for (int j = 0; j < 8; j++)
                    acc[i][j] += a[i] * b[j];
        }
        __syncthreads();
    }

    // epilogue
    const int crow = bm * 128 + ty * 8;
    const int ccol = bn * 128 + tx * 8;
    float bv[8];
    if (EPI != 0) {
        *(float4*)(bv)     = *(const float4*)(bias + ccol);
        *(float4*)(bv + 4) = *(const float4*)(bias + ccol + 4);
    }
    #pragma unroll
    for (int i = 0; i < 8; i++) {
        float* crow_ptr = C + (size_t)(crow + i) * N + ccol;
        #pragma unroll
        for (int jq = 0; jq < 8; jq += 4) {
            float4 r;
            float vals[4];
            #pragma unroll
            for (int u = 0; u < 4; u++) {
                float val = acc[i][jq + u];
                if (EPI == 1) {
                    val += bv[jq + u];
                    val += res[(size_t)(crow + i) * N + ccol + jq + u];
                } else if (EPI == 2) {
                    val += bv[jq + u];
                    val = val / (1.0f + __expf(-val));   // silu
                }
                vals[u] = val;
            }
            r.x = vals[0]; r.y = vals[1]; r.z = vals[2]; r.w = vals[3];
            *(float4*)(crow_ptr + jq) = r;
        }
    }
}

// ---------------- flash attention (fp32, causal) ----------------
// Block = (qtile 64 rows, head, batch). 256 threads.
// Thread -> row i = tid/4, lane quarter lq = tid%3? no: tid&3.
//   S entries:   j = lq + 4*jj (16 per thread)
//   O columns:   c0 = lq*16 .. +15
#define APAD 68
#define ATT_SMEM ((4 * 64 * APAD + 128) * 4)

__global__ __launch_bounds__(256)
void attn_kernel(const float* __restrict__ q, const float* __restrict__ k,
                 const float* __restrict__ v, float* __restrict__ o) {
    extern __shared__ float sm[];
    float* Qs = sm;
    float* Ks = Qs + 64 * APAD;
    float* Vs = Ks + 64 * APAD;
    float* Ss = Vs + 64 * APAD;
    float* rm = Ss + 64 * APAD;   // 64
    float* rl = rm + 64;          // 64

    const int tid = threadIdx.x;
    const int qt = blockIdx.x, h = blockIdx.y, b = blockIdx.z;
    const int lr = tid >> 2;      // row within tile
    const int lq = tid & 3;
    const int i  = lr;
    const int c0 = lq * 16;

    const size_t base = ((size_t)b * TT) * DD + (size_t)h * HDIM;

    // load Q tile, pre-scaled by 1/sqrt(HD)
    {
        const float* qrow = q + base + (size_t)(qt * 64 + lr) * DD;
        #pragma unroll
        for (int u = 0; u < 4; u++) {
            float4 vv = *(const float4*)(qrow + lq * 16 + u * 4);
            float* dst = Qs + lr * APAD + lq * 16 + u * 4;
            dst[0] = vv.x * 0.125f; dst[1] = vv.y * 0.125f;
            dst[2] = vv.z * 0.125f; dst[3] = vv.w * 0.125f;
        }
    }
    if (tid < 64) { rm[tid] = -INFINITY; rl[tid] = 0.f; }

    float oacc[16];
    #pragma unroll
    for (int u = 0; u < 16; u++) oacc[u] = 0.f;

    __syncthreads();

    for (int kt = 0; kt <= qt; kt++) {
        // load K,V tiles
        {
            const float* krow = k + base + (size_t)(kt * 64 + lr) * DD;
            const float* vrow = v + base + (size_t)(kt * 64 + lr) * DD;
            #pragma unroll
            for (int u = 0; u < 4; u++) {
                *(float4*)(Ks + lr * APAD + lq * 16 + u * 4) =
                    *(const float4*)(krow + lq * 16 + u * 4);
                *(float4*)(Vs + lr * APAD + lq * 16 + u * 4) =
                    *(const float4*)(vrow + lq * 16 + u * 4);
            }
        }
        __syncthreads();

        // S = Q K^T for my 16 entries (j = lq + 4*jj)
        float s[16];
        #pragma unroll
        for (int jj = 0; jj < 16; jj++) s[jj] = 0.f;
        #pragma unroll 4
        for (int d = 0; d < 64; d += 4) {
            float4 qv = *(const float4*)(Qs + i * APAD + d);
            #pragma unroll
            for (int jj = 0; jj < 16; jj++) {
                float4 kv = *(const float4*)(Ks + (lq + 4 * jj) * APAD + d);
                s[jj] += qv.x * kv.x + qv.y * kv.y + qv.z * kv.z + qv.w * kv.w;
            }
        }
        if (kt == qt) {
            #pragma unroll
            for (int jj = 0; jj < 16; jj++)
                if (lq + 4 * jj > i) s[jj] = -INFINITY;
        }

        // online softmax stats for row i (group of 4 lanes)
        const float m_old = rm[i];
        const float l_old = rl[i];
        float mmax = -INFINITY;
        #pragma unroll
        for (int jj = 0; jj < 16; jj++) mmax = fmaxf(mmax, s[jj]);
        mmax = fmaxf(mmax, __shfl_xor_sync(0xFFFFFFFFu, mmax, 1));
        mmax = fmaxf(mmax, __shfl_xor_sync(0xFFFFFFFFu, mmax, 2));
        const float m_new = fmaxf(m_old, mmax);
        const float alpha = __expf(m_old - m_new);

        float lsum = 0.f;
        #pragma unroll
        for (int jj = 0; jj < 16; jj++) {
            float p = __expf(s[jj] - m_new);
            Ss[i * APAD + lq + 4 * jj] = p;
            lsum += p;
        }
        lsum += __shfl_xor_sync(0xFFFFFFFFu, lsum, 1);
        lsum += __shfl_xor_sync(0xFFFFFFFFu, lsum, 2);
        __syncwarp();
        if (lq == 0) { rm[i] = m_new; rl[i] = l_old * alpha + lsum; }

        // O = O*alpha + P @ V (my 16 d-columns)
        #pragma unroll
        for (int u = 0; u < 16; u++) oacc[u] *= alpha;
        #pragma unroll 4
        for (int j = 0; j < 64; j++) {
            float p = Ss[i * APAD + j];
            #pragma unroll
            for (int u4 = 0; u4 < 4; u4++) {
                float4 vv = *(const float4*)(Vs + j * APAD + c0 + u4 * 4);
                oacc[u4 * 4 + 0] += p * vv.x;
                oacc[u4 * 4 + 1] += p * vv.y;
                oacc[u4 * 4 + 2] += p * vv.z;
                oacc[u4 * 4 + 3] += p * vv.w;
            }
        }
        __syncthreads();
    }

    const float linv = 1.0f / rl[i];
    float* orow = o + base + (size_t)(qt * 64 + i) * DD + c0;
    #pragma unroll
    for (int u4 = 0; u4 < 4; u4++) {
        float4 r;
        r.x = oacc[u4 * 4 + 0] * linv;
        r.y = oacc[u4 * 4 + 1] * linv;
        r.z = oacc[u4 * 4 + 2] * linv;
        r.w = oacc[u4 * 4 + 3] * linv;
        *(float4*)(orow + u4 * 4) = r;
    }
}

// ---------------- launch ----------------
extern "C" void kernel_launch(void* const* d_in, const int* in_sizes, int n_in,
                              void* d_out, int out_size) {
    const float* x     = (const float*)d_in[0];
    // d_in[1] = causal_mask (int32) — causality computed analytically, ignored
    const float* Wq    = (const float*)d_in[2];
    const float* Wk    = (const float*)d_in[3];
    const float* Wv    = (const float*)d_in[4];
    const float* Wo    = (const float*)d_in[5];
    const float* bo    = (const float*)d_in[6];
    const float* W1    = (const float*)d_in[7];
    const float* b1    = (const float*)d_in[8];
    const float* W2    = (const float*)d_in[9];
    const float* b2    = (const float*)d_in[10];
    const float* gattn = (const float*)d_in[11];
    const float* gff   = (const float*)d_in[12];
    float* out = (float*)d_out;

    float *xa, *q, *k, *v, *at, *x1, *hb;
    cudaGetSymbolAddress((void**)&xa, g_xa);
    cudaGetSymbolAddress((void**)&q,  g_q);
    cudaGetSymbolAddress((void**)&k,  g_k);
    cudaGetSymbolAddress((void**)&v,  g_v);
    cudaGetSymbolAddress((void**)&at, g_at);
    cudaGetSymbolAddress((void**)&x1, g_x1);
    cudaGetSymbolAddress((void**)&hb, g_h);

    cudaFuncSetAttribute(attn_kernel, cudaFuncAttributeMaxDynamicSharedMemorySize,
                         ATT_SMEM);

    // 1. rmsnorm(x, g_attn) -> xa
    rmsnorm_kernel<<<ROWS, 256>>>(x, gattn, xa);

    // 2. fused QKV projections (z picks the weight/output)
    {
        dim3 grid(DD / 128, ROWS / 128, 3);
        gemm_kernel<0><<<grid, 256>>>(xa, Wq, Wk, Wv, q, k, v,
                                      nullptr, nullptr, ROWS, DD, DD);
    }

    // 3. causal attention
    {
        dim3 grid(TT / 64, HH, BB);
        attn_kernel<<<grid, 256, ATT_SMEM>>>(q, k, v, at);
    }

    // 4. x1 = x + at @ Wo + bo
    {
        dim3 grid(DD / 128, ROWS / 128, 1);
        gemm_kernel<1><<<grid, 256>>>(at, Wo, Wo, Wo, x1, x1, x1,
                                      bo, x, ROWS, DD, DD);
    }

    // 5. rmsnorm(x1, g_ff) -> xa
    rmsnorm_kernel<<<ROWS, 256>>>(x1, gff, xa);

    // 6. h = silu(xa @ W1 + b1)
    {
        dim3 grid(FF / 128, ROWS / 128, 1);
        gemm_kernel<2><<<grid, 256>>>(xa, W1, W1, W1, hb, hb, hb,
                                      b1, nullptr, ROWS, FF, DD);
    }

    // 7. out = x1 + h @ W2 + b2
    {
        dim3 grid(DD / 128, ROWS / 128, 1);
        gemm_kernel<1><<<grid, 256>>>(hb, W2, W2, W2, out, out, out,
                                      b2, x1, ROWS, DD, FF);
    }
}

// round 2
// speedup vs baseline: 1.7091x; 1.7091x over previous
#include <cuda_runtime.h>
#include <cstdint>

// ---------------- problem constants ----------------
#define BB   2
#define TT   2048
#define DD   1024
#define HH   16
#define HDIM 64
#define FF   4096
#define ROWS (BB*TT)          // 4096

// ---------------- scratch (device globals) ----------------
__device__ float g_xa  [ROWS*DD];
__device__ float g_q   [ROWS*DD];
__device__ float g_k   [ROWS*DD];
__device__ float g_v   [ROWS*DD];
__device__ float g_at  [ROWS*DD];
__device__ float g_x1  [ROWS*DD];
__device__ float g_h   [(size_t)ROWS*FF];

// ---------------- rmsnorm ----------------
__global__ __launch_bounds__(256)
void rmsnorm_kernel(const float* __restrict__ x, const float* __restrict__ g,
                    float* __restrict__ out) {
    __shared__ float red[256];
    const int row = blockIdx.x;
    const int tid = threadIdx.x;
    const float4 v = ((const float4*)(x + (size_t)row * DD))[tid];
    float ss = v.x*v.x + v.y*v.y + v.z*v.z + v.w*v.w;
    red[tid] = ss;
    __syncthreads();
    #pragma unroll
    for (int s = 128; s > 0; s >>= 1) {
        if (tid < s) red[tid] += red[tid + s];
        __syncthreads();
    }
    const float norm = rsqrtf(red[0] * (1.0f / DD) + 1e-5f);
    const float4 gv = ((const float4*)g)[tid];
    float4 o;
    o.x = v.x * norm * gv.x;
    o.y = v.y * norm * gv.y;
    o.z = v.z * norm * gv.z;
    o.w = v.w * norm * gv.w;
    ((float4*)(out + (size_t)row * DD))[tid] = o;
}

// ---------------- tf32 tensor-core GEMM ----------------
// C[M,N] = A[M,K] @ W[K,N], EPI 0: none; 1: +bias+res; 2: silu(+bias)
// BM=128 BN=128 BK=16, 256 thr, warps 2(M)x4(N), warp tile 64x32.
__device__ __forceinline__ uint32_t f2tf(float f) {
    uint32_t u; asm("cvt.rna.tf32.f32 %0, %1;" : "=r"(u) : "f"(f)); return u;
}

__device__ __forceinline__ void mma_tf32(float* c, const uint32_t* a, const uint32_t* b) {
    asm volatile(
        "mma.sync.aligned.m16n8k8.row.col.f32.tf32.tf32.f32 "
        "{%0,%1,%2,%3},{%4,%5,%6,%7},{%8,%9},{%0,%1,%2,%3};\n"
        : "+f"(c[0]), "+f"(c[1]), "+f"(c[2]), "+f"(c[3])
        : "r"(a[0]), "r"(a[1]), "r"(a[2]), "r"(a[3]), "r"(b[0]), "r"(b[1]));
}

template <int EPI>
__global__ __launch_bounds__(256, 2)
void gemm_tc(const float* __restrict__ A,
             const float* __restrict__ W0, const float* __restrict__ W1,
             const float* __restrict__ W2,
             float* __restrict__ C0, float* __restrict__ C1, float* __restrict__ C2,
             const float* __restrict__ bias, const float* __restrict__ res,
             int M, int N, int K) {
    // A tile: [m][k] rows of 32 words, k-index XOR-swizzled by (m&7)<<2
    __shared__ uint32_t As[128 * 32];
    // B tile: [k][n], row stride 136 words
    __shared__ uint32_t Bs[16 * 136];

    const float* W = (blockIdx.z == 0) ? W0 : (blockIdx.z == 1 ? W1 : W2);
    float*       C = (blockIdx.z == 0) ? C0 : (blockIdx.z == 1 ? C1 : C2);

    const int tid   = threadIdx.x;
    const int lane  = tid & 31;
    const int warp  = tid >> 5;
    const int warpM = warp & 1;      // 0..1
    const int warpN = warp >> 1;     // 0..3
    const int gid   = lane >> 2;     // 0..7
    const int tig   = lane & 3;      // 0..3

    const int bm = blockIdx.y, bn = blockIdx.x;
    const float* Ab = A + (size_t)bm * 128 * K;
    const float* Wb = W + (size_t)bn * 128;

    // per-thread copy indices (2 float4 each for A and B)
    const int maA[2] = { tid >> 2, (tid + 256) >> 2 };          // rows 0..127
    const int kcA    = (tid & 3) << 2;                          // 0,4,8,12
    const int krB[2] = { tid >> 5, (tid + 256) >> 5 };          // rows 0..15
    const int ncB    = (tid & 31) << 2;                         // 0..124

    float4 ra[2], rb[2];
    #pragma unroll
    for (int i = 0; i < 2; i++) {
        ra[i] = *(const float4*)(Ab + (size_t)maA[i] * K + kcA);
        rb[i] = *(const float4*)(Wb + (size_t)krB[i] * N + ncB);
    }

    float c[4][4][4];
    #pragma unroll
    for (int mi = 0; mi < 4; mi++)
        #pragma unroll
        for (int ni = 0; ni < 4; ni++)
            #pragma unroll
            for (int u = 0; u < 4; u++) c[mi][ni][u] = 0.f;

    for (int kb = 0; kb < K; kb += 16) {
        // store staged tile (convert to tf32 once per element)
        #pragma unroll
        for (int i = 0; i < 2; i++) {
            uint4 ua;
            ua.x = f2tf(ra[i].x); ua.y = f2tf(ra[i].y);
            ua.z = f2tf(ra[i].z); ua.w = f2tf(ra[i].w);
            int sa = maA[i] * 32 + (kcA ^ ((maA[i] & 7) << 2));
            *(uint4*)(As + sa) = ua;
            uint4 ub;
            ub.x = f2tf(rb[i].x); ub.y = f2tf(rb[i].y);
            ub.z = f2tf(rb[i].z); ub.w = f2tf(rb[i].w);
            *(uint4*)(Bs + krB[i] * 136 + ncB) = ub;
        }
        __syncthreads();

        // prefetch next tile
        if (kb + 16 < K) {
            #pragma unroll
            for (int i = 0; i < 2; i++) {
                ra[i] = *(const float4*)(Ab + (size_t)maA[i] * K + kb + 16 + kcA);
                rb[i] = *(const float4*)(Wb + (size_t)(kb + 16 + krB[i]) * N + ncB);
            }
        }

        // compute: two k8 steps
        #pragma unroll
        for (int k0 = 0; k0 < 16; k0 += 8) {
            uint32_t af[4][4], bf[4][2];
            const int sw = gid << 2;
            #pragma unroll
            for (int mi = 0; mi < 4; mi++) {
                int m = warpM * 64 + mi * 16 + gid;       // m&7 == gid
                int base = m * 32;
                int x0 = (k0 + tig) ^ sw;
                int x1 = (k0 + tig + 4) ^ sw;
                af[mi][0] = As[base + x0];
                af[mi][1] = As[base + 8 * 32 + x0];
                af[mi][2] = As[base + x1];
                af[mi][3] = As[base + 8 * 32 + x1];
            }
            #pragma unroll
            for (int ni = 0; ni < 4; ni++) {
                int nb = warpN * 32 + ni * 8 + gid;
                bf[ni][0] = Bs[(k0 + tig) * 136 + nb];
                bf[ni][1] = Bs[(k0 + tig + 4) * 136 + nb];
            }
            #pragma unroll
            for (int mi = 0; mi < 4; mi++)
                #pragma unroll
                for (int ni = 0; ni < 4; ni++)
                    mma_tf32(c[mi][ni], af[mi], bf[ni]);
        }
        __syncthreads();
    }

    // ---------------- epilogue ----------------
    #pragma unroll
    for (int mi = 0; mi < 4; mi++) {
        const int r0 = bm * 128 + warpM * 64 + mi * 16 + gid;
        const int r1 = r0 + 8;
        #pragma unroll
        for (int ni = 0; ni < 4; ni++) {
            const int col = bn * 128 + warpN * 32 + ni * 8 + 2 * tig;
            float v0 = c[mi][ni][0], v1 = c[mi][ni][1];
            float v2 = c[mi][ni][2], v3 = c[mi][ni][3];
            if (EPI == 1) {
                const float b0 = bias[col], b1 = bias[col + 1];
                const float2 rA = *(const float2*)(res + (size_t)r0 * N + col);
                const float2 rB = *(const float2*)(res + (size_t)r1 * N + col);
                v0 += b0 + rA.x; v1 += b1 + rA.y;
                v2 += b0 + rB.x; v3 += b1 + rB.y;
            } else if (EPI == 2) {
                const float b0 = bias[col], b1 = bias[col + 1];
                v0 += b0; v1 += b1; v2 += b0; v3 += b1;
                v0 = v0 / (1.0f + __expf(-v0));
                v1 = v1 / (1.0f + __expf(-v1));
                v2 = v2 / (1.0f + __expf(-v2));
                v3 = v3 / (1.0f + __expf(-v3));
            }
            float2 o0; o0.x = v0; o0.y = v1;
            float2 o1; o1.x = v2; o1.y = v3;
            *(float2*)(C + (size_t)r0 * N + col) = o0;
            *(float2*)(C + (size_t)r1 * N + col) = o1;
        }
    }
}

// ---------------- flash attention (fp32, causal) ----------------
#define APAD 68
#define ATT_SMEM ((4 * 64 * APAD + 128) * 4)

__global__ __launch_bounds__(256)
void attn_kernel(const float* __restrict__ q, const float* __restrict__ k,
                 const float* __restrict__ v, float* __restrict__ o) {
    extern __shared__ float sm[];
    float* Qs = sm;
    float* Ks = Qs + 64 * APAD;
    float* Vs = Ks + 64 * APAD;
    float* Ss = Vs + 64 * APAD;
    float* rm = Ss + 64 * APAD;   // 64
    float* rl = rm + 64;          // 64

    const int tid = threadIdx.x;
    const int qt = blockIdx.x, h = blockIdx.y, b = blockIdx.z;
    const int lr = tid >> 2;
    const int lq = tid & 3;
    const int i  = lr;
    const int c0 = lq * 16;

    const size_t base = ((size_t)b * TT) * DD + (size_t)h * HDIM;

    {
        const float* qrow = q + base + (size_t)(qt * 64 + lr) * DD;
        #pragma unroll
        for (int u = 0; u < 4; u++) {
            float4 vv = *(const float4*)(qrow + lq * 16 + u * 4);
            float* dst = Qs + lr * APAD + lq * 16 + u * 4;
            dst[0] = vv.x * 0.125f; dst[1] = vv.y * 0.125f;
            dst[2] = vv.z * 0.125f; dst[3] = vv.w * 0.125f;
        }
    }
    if (tid < 64) { rm[tid] = -INFINITY; rl[tid] = 0.f; }

    float oacc[16];
    #pragma unroll
    for (int u = 0; u < 16; u++) oacc[u] = 0.f;

    __syncthreads();

    for (int kt = 0; kt <= qt; kt++) {
        {
            const float* krow = k + base + (size_t)(kt * 64 + lr) * DD;
            const float* vrow = v + base + (size_t)(kt * 64 + lr) * DD;
            #pragma unroll
            for (int u = 0; u < 4; u++) {
                *(float4*)(Ks + lr * APAD + lq * 16 + u * 4) =
                    *(const float4*)(krow + lq * 16 + u * 4);
                *(float4*)(Vs + lr * APAD + lq * 16 + u * 4) =
                    *(const float4*)(vrow + lq * 16 + u * 4);
            }
        }
        __syncthreads();

        float s[16];
        #pragma unroll
        for (int jj = 0; jj < 16; jj++) s[jj] = 0.f;
        #pragma unroll 4
        for (int d = 0; d < 64; d += 4) {
            float4 qv = *(const float4*)(Qs + i * APAD + d);
            #pragma unroll
            for (int jj = 0; jj < 16; jj++) {
                float4 kv = *(const float4*)(Ks + (lq + 4 * jj) * APAD + d);
                s[jj] += qv.x * kv.x + qv.y * kv.y + qv.z * kv.z + qv.w * kv.w;
            }
        }
        if (kt == qt) {
            #pragma unroll
            for (int jj = 0; jj < 16; jj++)
                if (lq + 4 * jj > i) s[jj] = -INFINITY;
        }

        const float m_old = rm[i];
        const float l_old = rl[i];
        float mmax = -INFINITY;
        #pragma unroll
        for (int jj = 0; jj < 16; jj++) mmax = fmaxf(mmax, s[jj]);
        mmax = fmaxf(mmax, __shfl_xor_sync(0xFFFFFFFFu, mmax, 1));
        mmax = fmaxf(mmax, __shfl_xor_sync(0xFFFFFFFFu, mmax, 2));
        const float m_new = fmaxf(m_old, mmax);
        const float alpha = __expf(m_old - m_new);

        float lsum = 0.f;
        #pragma unroll
        for (int jj = 0; jj < 16; jj++) {
            float p = __expf(s[jj] - m_new);
            Ss[i * APAD + lq + 4 * jj] = p;
            lsum += p;
        }
        lsum += __shfl_xor_sync(0xFFFFFFFFu, lsum, 1);
        lsum += __shfl_xor_sync(0xFFFFFFFFu, lsum, 2);
        __syncwarp();
        if (lq == 0) { rm[i] = m_new; rl[i] = l_old * alpha + lsum; }

        #pragma unroll
        for (int u = 0; u < 16; u++) oacc[u] *= alpha;
        #pragma unroll 4
        for (int j = 0; j < 64; j++) {
            float p = Ss[i * APAD + j];
            #pragma unroll
            for (int u4 = 0; u4 < 4; u4++) {
                float4 vv = *(const float4*)(Vs + j * APAD + c0 + u4 * 4);
                oacc[u4 * 4 + 0] += p * vv.x;
                oacc[u4 * 4 + 1] += p * vv.y;
                oacc[u4 * 4 + 2] += p * vv.z;
                oacc[u4 * 4 + 3] += p * vv.w;
            }
        }
        __syncthreads();
    }

    const float linv = 1.0f / rl[i];
    float* orow = o + base + (size_t)(qt * 64 + i) * DD + c0;
    #pragma unroll
    for (int u4 = 0; u4 < 4; u4++) {
        float4 r;
        r.x = oacc[u4 * 4 + 0] * linv;
        r.y = oacc[u4 * 4 + 1] * linv;
        r.z = oacc[u4 * 4 + 2] * linv;
        r.w = oacc[u4 * 4 + 3] * linv;
        *(float4*)(orow + u4 * 4) = r;
    }
}

// ---------------- launch ----------------
extern "C" void kernel_launch(void* const* d_in, const int* in_sizes, int n_in,
                              void* d_out, int out_size) {
    const float* x     = (const float*)d_in[0];
    const float* Wq    = (const float*)d_in[2];
    const float* Wk    = (const float*)d_in[3];
    const float* Wv    = (const float*)d_in[4];
    const float* Wo    = (const float*)d_in[5];
    const float* bo    = (const float*)d_in[6];
    const float* W1    = (const float*)d_in[7];
    const float* b1    = (const float*)d_in[8];
    const float* W2    = (const float*)d_in[9];
    const float* b2    = (const float*)d_in[10];
    const float* gattn = (const float*)d_in[11];
    const float* gff   = (const float*)d_in[12];
    float* out = (float*)d_out;

    float *xa, *q, *k, *v, *at, *x1, *hb;
    cudaGetSymbolAddress((void**)&xa, g_xa);
    cudaGetSymbolAddress((void**)&q,  g_q);
    cudaGetSymbolAddress((void**)&k,  g_k);
    cudaGetSymbolAddress((void**)&v,  g_v);
    cudaGetSymbolAddress((void**)&at, g_at);
    cudaGetSymbolAddress((void**)&x1, g_x1);
    cudaGetSymbolAddress((void**)&hb, g_h);

    cudaFuncSetAttribute(attn_kernel, cudaFuncAttributeMaxDynamicSharedMemorySize,
                         ATT_SMEM);

    // 1. rmsnorm(x, g_attn) -> xa
    rmsnorm_kernel<<<ROWS, 256>>>(x, gattn, xa);

    // 2. fused QKV projections
    {
        dim3 grid(DD / 128, ROWS / 128, 3);
        gemm_tc<0><<<grid, 256>>>(xa, Wq, Wk, Wv, q, k, v,
                                  nullptr, nullptr, ROWS, DD, DD);
    }

    // 3. causal attention
    {
        dim3 grid(TT / 64, HH, BB);
        attn_kernel<<<grid, 256, ATT_SMEM>>>(q, k, v, at);
    }

    // 4. x1 = x + at @ Wo + bo
    {
        dim3 grid(DD / 128, ROWS / 128, 1);
        gemm_tc<1><<<grid, 256>>>(at, Wo, Wo, Wo, x1, x1, x1,
                                  bo, x, ROWS, DD, DD);
    }

    // 5. rmsnorm(x1, g_ff) -> xa
    rmsnorm_kernel<<<ROWS, 256>>>(x1, gff, xa);

    // 6. h = silu(xa @ W1 + b1)
    {
        dim3 grid(FF / 128, ROWS / 128, 1);
        gemm_tc<2><<<grid, 256>>>(xa, W1, W1, W1, hb, hb, hb,
                                  b1, nullptr, ROWS, FF, DD);
    }

    // 7. out = x1 + h @ W2 + b2
    {
        dim3 grid(DD / 128, ROWS / 128, 1);
        gemm_tc<1><<<grid, 256>>>(hb, W2, W2, W2, out, out, out,
                                  b2, x1, ROWS, DD, FF);
    }
}

// round 3
// speedup vs baseline: 4.3915x; 2.5695x over previous
#include <cuda_runtime.h>
#include <cstdint>

// ---------------- problem constants ----------------
#define BB   2
#define TT   2048
#define DD   1024
#define HH   16
#define HDIM 64
#define FF   4096
#define ROWS (BB*TT)          // 4096

// ---------------- scratch (device globals) ----------------
__device__ float g_xa  [ROWS*DD];
__device__ float g_q   [ROWS*DD];
__device__ float g_k   [ROWS*DD];
__device__ float g_v   [ROWS*DD];
__device__ float g_at  [ROWS*DD];
__device__ float g_x1  [ROWS*DD];
__device__ float g_h   [(size_t)ROWS*FF];

// ---------------- helpers ----------------
__device__ __forceinline__ uint32_t f2tf(float f) {
    uint32_t u; asm("cvt.rna.tf32.f32 %0, %1;" : "=r"(u) : "f"(f)); return u;
}
__device__ __forceinline__ void mma_tf32(float* c, const uint32_t* a, const uint32_t* b) {
    asm volatile(
        "mma.sync.aligned.m16n8k8.row.col.f32.tf32.tf32.f32 "
        "{%0,%1,%2,%3},{%4,%5,%6,%7},{%8,%9},{%0,%1,%2,%3};\n"
        : "+f"(c[0]), "+f"(c[1]), "+f"(c[2]), "+f"(c[3])
        : "r"(a[0]), "r"(a[1]), "r"(a[2]), "r"(a[3]), "r"(b[0]), "r"(b[1]));
}

// ---------------- rmsnorm ----------------
__global__ __launch_bounds__(256)
void rmsnorm_kernel(const float* __restrict__ x, const float* __restrict__ g,
                    float* __restrict__ out) {
    __shared__ float red[256];
    const int row = blockIdx.x;
    const int tid = threadIdx.x;
    const float4 v = ((const float4*)(x + (size_t)row * DD))[tid];
    float ss = v.x*v.x + v.y*v.y + v.z*v.z + v.w*v.w;
    red[tid] = ss;
    __syncthreads();
    #pragma unroll
    for (int s = 128; s > 0; s >>= 1) {
        if (tid < s) red[tid] += red[tid + s];
        __syncthreads();
    }
    const float norm = rsqrtf(red[0] * (1.0f / DD) + 1e-5f);
    const float4 gv = ((const float4*)g)[tid];
    float4 o;
    o.x = v.x * norm * gv.x;
    o.y = v.y * norm * gv.y;
    o.z = v.z * norm * gv.z;
    o.w = v.w * norm * gv.w;
    ((float4*)(out + (size_t)row * DD))[tid] = o;
}

// ---------------- tf32 tensor-core GEMM ----------------
template <int EPI>
__global__ __launch_bounds__(256, 2)
void gemm_tc(const float* __restrict__ A,
             const float* __restrict__ W0, const float* __restrict__ W1,
             const float* __restrict__ W2,
             float* __restrict__ C0, float* __restrict__ C1, float* __restrict__ C2,
             const float* __restrict__ bias, const float* __restrict__ res,
             int M, int N, int K) {
    __shared__ uint32_t As[128 * 32];
    __shared__ uint32_t Bs[16 * 136];

    const float* W = (blockIdx.z == 0) ? W0 : (blockIdx.z == 1 ? W1 : W2);
    float*       C = (blockIdx.z == 0) ? C0 : (blockIdx.z == 1 ? C1 : C2);

    const int tid   = threadIdx.x;
    const int lane  = tid & 31;
    const int warp  = tid >> 5;
    const int warpM = warp & 1;
    const int warpN = warp >> 1;
    const int gid   = lane >> 2;
    const int tig   = lane & 3;

    const int bm = blockIdx.y, bn = blockIdx.x;
    const float* Ab = A + (size_t)bm * 128 * K;
    const float* Wb = W + (size_t)bn * 128;

    const int maA[2] = { tid >> 2, (tid + 256) >> 2 };
    const int kcA    = (tid & 3) << 2;
    const int krB[2] = { tid >> 5, (tid + 256) >> 5 };
    const int ncB    = (tid & 31) << 2;

    float4 ra[2], rb[2];
    #pragma unroll
    for (int i = 0; i < 2; i++) {
        ra[i] = *(const float4*)(Ab + (size_t)maA[i] * K + kcA);
        rb[i] = *(const float4*)(Wb + (size_t)krB[i] * N + ncB);
    }

    float c[4][4][4];
    #pragma unroll
    for (int mi = 0; mi < 4; mi++)
        #pragma unroll
        for (int ni = 0; ni < 4; ni++)
            #pragma unroll
            for (int u = 0; u < 4; u++) c[mi][ni][u] = 0.f;

    for (int kb = 0; kb < K; kb += 16) {
        #pragma unroll
        for (int i = 0; i < 2; i++) {
            uint4 ua;
            ua.x = f2tf(ra[i].x); ua.y = f2tf(ra[i].y);
            ua.z = f2tf(ra[i].z); ua.w = f2tf(ra[i].w);
            int sa = maA[i] * 32 + (kcA ^ ((maA[i] & 7) << 2));
            *(uint4*)(As + sa) = ua;
            uint4 ub;
            ub.x = f2tf(rb[i].x); ub.y = f2tf(rb[i].y);
            ub.z = f2tf(rb[i].z); ub.w = f2tf(rb[i].w);
            *(uint4*)(Bs + krB[i] * 136 + ncB) = ub;
        }
        __syncthreads();

        if (kb + 16 < K) {
            #pragma unroll
            for (int i = 0; i < 2; i++) {
                ra[i] = *(const float4*)(Ab + (size_t)maA[i] * K + kb + 16 + kcA);
                rb[i] = *(const float4*)(Wb + (size_t)(kb + 16 + krB[i]) * N + ncB);
            }
        }

        #pragma unroll
        for (int k0 = 0; k0 < 16; k0 += 8) {
            uint32_t af[4][4], bf[4][2];
            const int sw = gid << 2;
            #pragma unroll
            for (int mi = 0; mi < 4; mi++) {
                int m = warpM * 64 + mi * 16 + gid;
                int base = m * 32;
                int x0 = (k0 + tig) ^ sw;
                int x1 = (k0 + tig + 4) ^ sw;
                af[mi][0] = As[base + x0];
                af[mi][1] = As[base + 8 * 32 + x0];
                af[mi][2] = As[base + x1];
                af[mi][3] = As[base + 8 * 32 + x1];
            }
            #pragma unroll
            for (int ni = 0; ni < 4; ni++) {
                int nb = warpN * 32 + ni * 8 + gid;
                bf[ni][0] = Bs[(k0 + tig) * 136 + nb];
                bf[ni][1] = Bs[(k0 + tig + 4) * 136 + nb];
            }
            #pragma unroll
            for (int mi = 0; mi < 4; mi++)
                #pragma unroll
                for (int ni = 0; ni < 4; ni++)
                    mma_tf32(c[mi][ni], af[mi], bf[ni]);
        }
        __syncthreads();
    }

    #pragma unroll
    for (int mi = 0; mi < 4; mi++) {
        const int r0 = bm * 128 + warpM * 64 + mi * 16 + gid;
        const int r1 = r0 + 8;
        #pragma unroll
        for (int ni = 0; ni < 4; ni++) {
            const int col = bn * 128 + warpN * 32 + ni * 8 + 2 * tig;
            float v0 = c[mi][ni][0], v1 = c[mi][ni][1];
            float v2 = c[mi][ni][2], v3 = c[mi][ni][3];
            if (EPI == 1) {
                const float b0 = bias[col], b1 = bias[col + 1];
                const float2 rA = *(const float2*)(res + (size_t)r0 * N + col);
                const float2 rB = *(const float2*)(res + (size_t)r1 * N + col);
                v0 += b0 + rA.x; v1 += b1 + rA.y;
                v2 += b0 + rB.x; v3 += b1 + rB.y;
            } else if (EPI == 2) {
                const float b0 = bias[col], b1 = bias[col + 1];
                v0 += b0; v1 += b1; v2 += b0; v3 += b1;
                v0 = v0 / (1.0f + __expf(-v0));
                v1 = v1 / (1.0f + __expf(-v1));
                v2 = v2 / (1.0f + __expf(-v2));
                v3 = v3 / (1.0f + __expf(-v3));
            }
            float2 o0; o0.x = v0; o0.y = v1;
            float2 o1; o1.x = v2; o1.y = v3;
            *(float2*)(C + (size_t)r0 * N + col) = o0;
            *(float2*)(C + (size_t)r1 * N + col) = o1;
        }
    }
}

// ---------------- tensor-core flash attention (tf32, causal) ----------------
// Block: 64 q-rows x (head, batch). 4 warps, each 16 q-rows.
// Q fragments live in registers for the whole kernel.
#define KS_STR 68
#define VS_STR 72
#define PS_STR 68
#define ATT_SMEM ((64*KS_STR + 64*VS_STR + 64*PS_STR) * 4)

__global__ __launch_bounds__(128)
void attn_tc(const float* __restrict__ q, const float* __restrict__ k,
             const float* __restrict__ v, float* __restrict__ o) {
    extern __shared__ uint32_t smu[];
    uint32_t* Ks = smu;
    uint32_t* Vs = Ks + 64 * KS_STR;
    uint32_t* Ps = Vs + 64 * VS_STR;

    const int tid  = threadIdx.x;
    const int lane = tid & 31;
    const int warp = tid >> 5;
    const int gid  = lane >> 2;
    const int tig  = lane & 3;
    const int qt = blockIdx.x, h = blockIdx.y, b = blockIdx.z;
    const size_t base = ((size_t)b * TT) * DD + (size_t)h * HDIM;

    // stage Q tile (scaled by 1/sqrt(64), tf32) into Ps, then grab fragments
    for (int idx = tid; idx < 64 * 16; idx += 128) {
        int row = idx >> 4, c4 = (idx & 15) << 2;
        float4 qv = *(const float4*)(q + base + (size_t)(qt * 64 + row) * DD + c4);
        uint32_t* dst = Ps + row * PS_STR + c4;
        dst[0] = f2tf(qv.x * 0.125f); dst[1] = f2tf(qv.y * 0.125f);
        dst[2] = f2tf(qv.z * 0.125f); dst[3] = f2tf(qv.w * 0.125f);
    }
    __syncthreads();

    uint32_t qf[8][4];
    {
        const uint32_t* Qw = Ps + (warp * 16) * PS_STR;
        #pragma unroll
        for (int k8 = 0; k8 < 8; k8++) {
            int col = k8 * 8 + tig;
            qf[k8][0] = Qw[gid * PS_STR + col];
            qf[k8][1] = Qw[(gid + 8) * PS_STR + col];
            qf[k8][2] = Qw[gid * PS_STR + col + 4];
            qf[k8][3] = Qw[(gid + 8) * PS_STR + col + 4];
        }
    }
    __syncthreads();

    float oacc[8][4];
    #pragma unroll
    for (int nt = 0; nt < 8; nt++)
        #pragma unroll
        for (int u = 0; u < 4; u++) oacc[nt][u] = 0.f;

    float m0 = -INFINITY, m1 = -INFINITY, l0 = 0.f, l1 = 0.f;
    const int r0 = qt * 64 + warp * 16 + gid;
    const int r1 = r0 + 8;
    uint32_t* Pw = Ps + (warp * 16) * PS_STR;

    for (int kt = 0; kt <= qt; kt++) {
        // load K,V tiles (tf32-converted)
        for (int idx = tid; idx < 64 * 16; idx += 128) {
            int row = idx >> 4, c4 = (idx & 15) << 2;
            const float* kp = k + base + (size_t)(kt * 64 + row) * DD + c4;
            const float* vp = v + base + (size_t)(kt * 64 + row) * DD + c4;
            float4 kv = *(const float4*)kp;
            float4 vv = *(const float4*)vp;
            uint32_t* kd = Ks + row * KS_STR + c4;
            kd[0] = f2tf(kv.x); kd[1] = f2tf(kv.y); kd[2] = f2tf(kv.z); kd[3] = f2tf(kv.w);
            uint32_t* vd = Vs + row * VS_STR + c4;
            vd[0] = f2tf(vv.x); vd[1] = f2tf(vv.y); vd[2] = f2tf(vv.z); vd[3] = f2tf(vv.w);
        }
        __syncthreads();

        // S = Q @ K^T  (16x64 per warp)
        float s[8][4];
        #pragma unroll
        for (int nt = 0; nt < 8; nt++) {
            s[nt][0] = s[nt][1] = s[nt][2] = s[nt][3] = 0.f;
            #pragma unroll
            for (int k8 = 0; k8 < 8; k8++) {
                uint32_t bf[2];
                const uint32_t* kr = Ks + (nt * 8 + gid) * KS_STR + k8 * 8 + tig;
                bf[0] = kr[0];
                bf[1] = kr[4];
                mma_tf32(s[nt], qf[k8], bf);
            }
        }

        // causal mask on diagonal tile
        if (kt == qt) {
            #pragma unroll
            for (int nt = 0; nt < 8; nt++) {
                int cc = kt * 64 + nt * 8 + 2 * tig;
                if (cc     > r0) s[nt][0] = -INFINITY;
                if (cc + 1 > r0) s[nt][1] = -INFINITY;
                if (cc     > r1) s[nt][2] = -INFINITY;
                if (cc + 1 > r1) s[nt][3] = -INFINITY;
            }
        }

        // online softmax (rows r0, r1)
        float mt0 = -INFINITY, mt1 = -INFINITY;
        #pragma unroll
        for (int nt = 0; nt < 8; nt++) {
            mt0 = fmaxf(mt0, fmaxf(s[nt][0], s[nt][1]));
            mt1 = fmaxf(mt1, fmaxf(s[nt][2], s[nt][3]));
        }
        mt0 = fmaxf(mt0, __shfl_xor_sync(0xFFFFFFFFu, mt0, 1));
        mt0 = fmaxf(mt0, __shfl_xor_sync(0xFFFFFFFFu, mt0, 2));
        mt1 = fmaxf(mt1, __shfl_xor_sync(0xFFFFFFFFu, mt1, 1));
        mt1 = fmaxf(mt1, __shfl_xor_sync(0xFFFFFFFFu, mt1, 2));
        const float mn0 = fmaxf(m0, mt0), mn1 = fmaxf(m1, mt1);
        const float a0 = __expf(m0 - mn0), a1 = __expf(m1 - mn1);

        float ls0 = 0.f, ls1 = 0.f;
        #pragma unroll
        for (int nt = 0; nt < 8; nt++) {
            float p0 = __expf(s[nt][0] - mn0);
            float p1 = __expf(s[nt][1] - mn0);
            float p2 = __expf(s[nt][2] - mn1);
            float p3 = __expf(s[nt][3] - mn1);
            ls0 += p0 + p1; ls1 += p2 + p3;
            uint32_t* d0 = Pw + gid * PS_STR + nt * 8 + 2 * tig;
            d0[0] = f2tf(p0); d0[1] = f2tf(p1);
            uint32_t* d1 = Pw + (gid + 8) * PS_STR + nt * 8 + 2 * tig;
            d1[0] = f2tf(p2); d1[1] = f2tf(p3);
        }
        ls0 += __shfl_xor_sync(0xFFFFFFFFu, ls0, 1);
        ls0 += __shfl_xor_sync(0xFFFFFFFFu, ls0, 2);
        ls1 += __shfl_xor_sync(0xFFFFFFFFu, ls1, 1);
        ls1 += __shfl_xor_sync(0xFFFFFFFFu, ls1, 2);
        l0 = l0 * a0 + ls0;
        l1 = l1 * a1 + ls1;
        m0 = mn0; m1 = mn1;

        // rescale O accumulators
        #pragma unroll
        for (int nt = 0; nt < 8; nt++) {
            oacc[nt][0] *= a0; oacc[nt][1] *= a0;
            oacc[nt][2] *= a1; oacc[nt][3] *= a1;
        }
        __syncwarp();

        // O += P @ V
        #pragma unroll
        for (int k8 = 0; k8 < 8; k8++) {
            uint32_t af[4];
            af[0] = Pw[gid * PS_STR + k8 * 8 + tig];
            af[1] = Pw[(gid + 8) * PS_STR + k8 * 8 + tig];
            af[2] = Pw[gid * PS_STR + k8 * 8 + tig + 4];
            af[3] = Pw[(gid + 8) * PS_STR + k8 * 8 + tig + 4];
            #pragma unroll
            for (int nt = 0; nt < 8; nt++) {
                uint32_t bf[2];
                bf[0] = Vs[(k8 * 8 + tig) * VS_STR + nt * 8 + gid];
                bf[1] = Vs[(k8 * 8 + tig + 4) * VS_STR + nt * 8 + gid];
                mma_tf32(oacc[nt], af, bf);
            }
        }
        __syncthreads();
    }

    // write O
    const float li0 = 1.0f / l0, li1 = 1.0f / l1;
    #pragma unroll
    for (int nt = 0; nt < 8; nt++) {
        const int col = nt * 8 + 2 * tig;
        float2 w0; w0.x = oacc[nt][0] * li0; w0.y = oacc[nt][1] * li0;
        float2 w1; w1.x = oacc[nt][2] * li1; w1.y = oacc[nt][3] * li1;
        *(float2*)(o + base + (size_t)r0 * DD + col) = w0;
        *(float2*)(o + base + (size_t)r1 * DD + col) = w1;
    }
}

// ---------------- launch ----------------
extern "C" void kernel_launch(void* const* d_in, const int* in_sizes, int n_in,
                              void* d_out, int out_size) {
    const float* x     = (const float*)d_in[0];
    const float* Wq    = (const float*)d_in[2];
    const float* Wk    = (const float*)d_in[3];
    const float* Wv    = (const float*)d_in[4];
    const float* Wo    = (const float*)d_in[5];
    const float* bo    = (const float*)d_in[6];
    const float* W1    = (const float*)d_in[7];
    const float* b1    = (const float*)d_in[8];
    const float* W2    = (const float*)d_in[9];
    const float* b2    = (const float*)d_in[10];
    const float* gattn = (const float*)d_in[11];
    const float* gff   = (const float*)d_in[12];
    float* out = (float*)d_out;

    float *xa, *q, *k, *v, *at, *x1, *hb;
    cudaGetSymbolAddress((void**)&xa, g_xa);
    cudaGetSymbolAddress((void**)&q,  g_q);
    cudaGetSymbolAddress((void**)&k,  g_k);
    cudaGetSymbolAddress((void**)&v,  g_v);
    cudaGetSymbolAddress((void**)&at, g_at);
    cudaGetSymbolAddress((void**)&x1, g_x1);
    cudaGetSymbolAddress((void**)&hb, g_h);

    cudaFuncSetAttribute(attn_tc, cudaFuncAttributeMaxDynamicSharedMemorySize,
                         ATT_SMEM);

    // 1. rmsnorm(x, g_attn) -> xa
    rmsnorm_kernel<<<ROWS, 256>>>(x, gattn, xa);

    // 2. fused QKV projections
    {
        dim3 grid(DD / 128, ROWS / 128, 3);
        gemm_tc<0><<<grid, 256>>>(xa, Wq, Wk, Wv, q, k, v,
                                  nullptr, nullptr, ROWS, DD, DD);
    }

    // 3. causal attention (tensor cores)
    {
        dim3 grid(TT / 64, HH, BB);
        attn_tc<<<grid, 128, ATT_SMEM>>>(q, k, v, at);
    }

    // 4. x1 = x + at @ Wo + bo
    {
        dim3 grid(DD / 128, ROWS / 128, 1);
        gemm_tc<1><<<grid, 256>>>(at, Wo, Wo, Wo, x1, x1, x1,
                                  bo, x, ROWS, DD, DD);
    }

    // 5. rmsnorm(x1, g_ff) -> xa
    rmsnorm_kernel<<<ROWS, 256>>>(x1, gff, xa);

    // 6. h = silu(xa @ W1 + b1)
    {
        dim3 grid(FF / 128, ROWS / 128, 1);
        gemm_tc<2><<<grid, 256>>>(xa, W1, W1, W1, hb, hb, hb,
                                  b1, nullptr, ROWS, FF, DD);
    }

    // 7. out = x1 + h @ W2 + b2
    {
        dim3 grid(DD / 128, ROWS / 128, 1);
        gemm_tc<1><<<grid, 256>>>(hb, W2, W2, W2, out, out, out,
                                  b2, x1, ROWS, DD, FF);
    }
}

// round 4
// speedup vs baseline: 4.9929x; 1.1370x over previous
#include <cuda_runtime.h>
#include <cstdint>

// ---------------- problem constants ----------------
#define BB   2
#define TT   2048
#define DD   1024
#define HH   16
#define HDIM 64
#define FF   4096
#define ROWS (BB*TT)          // 4096

// ---------------- scratch (device globals) ----------------
__device__ float g_xa  [ROWS*DD];
__device__ float g_q   [ROWS*DD];
__device__ float g_k   [ROWS*DD];
__device__ float g_v   [ROWS*DD];
__device__ float g_at  [ROWS*DD];
__device__ float g_x1  [ROWS*DD];
__device__ float g_h   [(size_t)ROWS*FF];
__device__ float g_wr  [12*1024*1024];   // tf32-rounded weights

// ---------------- helpers ----------------
__device__ __forceinline__ uint32_t f2tf(float f) {
    uint32_t u; asm("cvt.rna.tf32.f32 %0, %1;" : "=r"(u) : "f"(f)); return u;
}
__device__ __forceinline__ float f2tff(float f) {
    return __uint_as_float(f2tf(f));
}
__device__ __forceinline__ void mma_tf32(float* c, const uint32_t* a, const uint32_t* b) {
    asm volatile(
        "mma.sync.aligned.m16n8k8.row.col.f32.tf32.tf32.f32 "
        "{%0,%1,%2,%3},{%4,%5,%6,%7},{%8,%9},{%0,%1,%2,%3};\n"
        : "+f"(c[0]), "+f"(c[1]), "+f"(c[2]), "+f"(c[3])
        : "r"(a[0]), "r"(a[1]), "r"(a[2]), "r"(a[3]), "r"(b[0]), "r"(b[1]));
}
__device__ __forceinline__ void cp16(uint32_t* smem, const void* g) {
    uint32_t s = (uint32_t)__cvta_generic_to_shared(smem);
    asm volatile("cp.async.cg.shared.global [%0], [%1], 16;\n" :: "r"(s), "l"(g));
}

// ---------------- weight pre-rounding to tf32 ----------------
__global__ __launch_bounds__(256)
void round4_kernel(const float4* __restrict__ in, float4* __restrict__ out, int n4) {
    int i = blockIdx.x * 256 + threadIdx.x;
    if (i < n4) {
        float4 v = in[i];
        v.x = f2tff(v.x); v.y = f2tff(v.y);
        v.z = f2tff(v.z); v.w = f2tff(v.w);
        out[i] = v;
    }
}

// ---------------- rmsnorm (output pre-rounded to tf32) ----------------
__global__ __launch_bounds__(256)
void rmsnorm_kernel(const float* __restrict__ x, const float* __restrict__ g,
                    float* __restrict__ out) {
    __shared__ float red[256];
    const int row = blockIdx.x;
    const int tid = threadIdx.x;
    const float4 v = ((const float4*)(x + (size_t)row * DD))[tid];
    float ss = v.x*v.x + v.y*v.y + v.z*v.z + v.w*v.w;
    red[tid] = ss;
    __syncthreads();
    #pragma unroll
    for (int s = 128; s > 0; s >>= 1) {
        if (tid < s) red[tid] += red[tid + s];
        __syncthreads();
    }
    const float norm = rsqrtf(red[0] * (1.0f / DD) + 1e-5f);
    const float4 gv = ((const float4*)g)[tid];
    float4 o;
    o.x = f2tff(v.x * norm * gv.x);
    o.y = f2tff(v.y * norm * gv.y);
    o.z = f2tff(v.z * norm * gv.z);
    o.w = f2tff(v.w * norm * gv.w);
    ((float4*)(out + (size_t)row * DD))[tid] = o;
}

// ---------------- tf32 tensor-core GEMM, cp.async 4-stage pipeline ----------
// Inputs must be pre-rounded to tf32 values (stored as fp32).
#define STAGES 4
#define ASZ (128*32)
#define BSZ (16*136)
#define GEMM_SMEM (STAGES * (ASZ + BSZ) * 4)

template <int EPI>
__global__ __launch_bounds__(256, 2)
void gemm_tc(const float* __restrict__ A,
             const float* __restrict__ W0, const float* __restrict__ W1,
             const float* __restrict__ W2,
             float* __restrict__ C0, float* __restrict__ C1, float* __restrict__ C2,
             const float* __restrict__ bias, const float* __restrict__ res,
             int M, int N, int K) {
    extern __shared__ uint32_t dynsm[];
    uint32_t* Asm = dynsm;                    // STAGES * ASZ
    uint32_t* Bsm = dynsm + STAGES * ASZ;     // STAGES * BSZ

    const float* W = (blockIdx.z == 0) ? W0 : (blockIdx.z == 1 ? W1 : W2);
    float*       C = (blockIdx.z == 0) ? C0 : (blockIdx.z == 1 ? C1 : C2);

    const int tid   = threadIdx.x;
    const int lane  = tid & 31;
    const int warp  = tid >> 5;
    const int warpM = warp & 1;
    const int warpN = warp >> 1;
    const int gid   = lane >> 2;
    const int tig   = lane & 3;

    const int bm = blockIdx.y, bn = blockIdx.x;
    const float* Ab = A + (size_t)bm * 128 * K;
    const float* Wb = W + (size_t)bn * 128;

    const int maA[2] = { tid >> 2, (tid + 256) >> 2 };
    const int kcA    = (tid & 3) << 2;
    const int krB[2] = { tid >> 5, (tid + 256) >> 5 };
    const int ncB    = (tid & 31) << 2;

    // swizzled A dst offsets (stage-relative), B dst offsets
    const int adst[2] = { maA[0] * 32 + (kcA ^ ((maA[0] & 7) << 2)),
                          maA[1] * 32 + (kcA ^ ((maA[1] & 7) << 2)) };
    const int bdst[2] = { krB[0] * 136 + ncB, krB[1] * 136 + ncB };

#define ISSUE_TILE(kb, st)                                                     \
    {                                                                          \
        uint32_t* A_s = Asm + (st) * ASZ;                                      \
        uint32_t* B_s = Bsm + (st) * BSZ;                                      \
        cp16(A_s + adst[0], Ab + (size_t)maA[0] * K + (kb) + kcA);             \
        cp16(A_s + adst[1], Ab + (size_t)maA[1] * K + (kb) + kcA);             \
        cp16(B_s + bdst[0], Wb + (size_t)((kb) + krB[0]) * N + ncB);           \
        cp16(B_s + bdst[1], Wb + (size_t)((kb) + krB[1]) * N + ncB);           \
        asm volatile("cp.async.commit_group;\n");                              \
    }

    float c[4][4][4];
    #pragma unroll
    for (int mi = 0; mi < 4; mi++)
        #pragma unroll
        for (int ni = 0; ni < 4; ni++)
            #pragma unroll
            for (int u = 0; u < 4; u++) c[mi][ni][u] = 0.f;

    // prologue: fill STAGES-1 tiles
    ISSUE_TILE(0, 0);
    ISSUE_TILE(16, 1);
    ISSUE_TILE(32, 2);

    int st = 0;
    for (int kb = 0; kb < K; kb += 16) {
        asm volatile("cp.async.wait_group %0;\n" :: "n"(STAGES - 2));
        __syncthreads();

        if (kb + (STAGES - 1) * 16 < K)
            ISSUE_TILE(kb + (STAGES - 1) * 16, (st + STAGES - 1) & 3);

        const uint32_t* A_c = Asm + st * ASZ;
        const uint32_t* B_c = Bsm + st * BSZ;
        const int sw = gid << 2;

        #pragma unroll
        for (int k0 = 0; k0 < 16; k0 += 8) {
            uint32_t af[4][4], bf[4][2];
            #pragma unroll
            for (int mi = 0; mi < 4; mi++) {
                int m = warpM * 64 + mi * 16 + gid;
                int base = m * 32;
                int x0 = (k0 + tig) ^ sw;
                int x1 = (k0 + tig + 4) ^ sw;
                af[mi][0] = A_c[base + x0];
                af[mi][1] = A_c[base + 8 * 32 + x0];
                af[mi][2] = A_c[base + x1];
                af[mi][3] = A_c[base + 8 * 32 + x1];
            }
            #pragma unroll
            for (int ni = 0; ni < 4; ni++) {
                int nb = warpN * 32 + ni * 8 + gid;
                bf[ni][0] = B_c[(k0 + tig) * 136 + nb];
                bf[ni][1] = B_c[(k0 + tig + 4) * 136 + nb];
            }
            #pragma unroll
            for (int mi = 0; mi < 4; mi++)
                #pragma unroll
                for (int ni = 0; ni < 4; ni++)
                    mma_tf32(c[mi][ni], af[mi], bf[ni]);
        }
        st = (st + 1) & 3;
    }
#undef ISSUE_TILE

    // ---------------- epilogue ----------------
    #pragma unroll
    for (int mi = 0; mi < 4; mi++) {
        const int r0 = bm * 128 + warpM * 64 + mi * 16 + gid;
        const int r1 = r0 + 8;
        #pragma unroll
        for (int ni = 0; ni < 4; ni++) {
            const int col = bn * 128 + warpN * 32 + ni * 8 + 2 * tig;
            float v0 = c[mi][ni][0], v1 = c[mi][ni][1];
            float v2 = c[mi][ni][2], v3 = c[mi][ni][3];
            if (EPI == 1) {
                const float b0 = bias[col], b1 = bias[col + 1];
                const float2 rA = *(const float2*)(res + (size_t)r0 * N + col);
                const float2 rB = *(const float2*)(res + (size_t)r1 * N + col);
                v0 += b0 + rA.x; v1 += b1 + rA.y;
                v2 += b0 + rB.x; v3 += b1 + rB.y;
            } else if (EPI == 2) {
                const float b0 = bias[col], b1 = bias[col + 1];
                v0 += b0; v1 += b1; v2 += b0; v3 += b1;
                v0 = f2tff(v0 / (1.0f + __expf(-v0)));   // pre-round: feeds W2 GEMM
                v1 = f2tff(v1 / (1.0f + __expf(-v1)));
                v2 = f2tff(v2 / (1.0f + __expf(-v2)));
                v3 = f2tff(v3 / (1.0f + __expf(-v3)));
            }
            float2 o0; o0.x = v0; o0.y = v1;
            float2 o1; o1.x = v2; o1.y = v3;
            *(float2*)(C + (size_t)r0 * N + col) = o0;
            *(float2*)(C + (size_t)r1 * N + col) = o1;
        }
    }
}

// ---------------- tensor-core flash attention (tf32, causal) ----------------
#define KS_STR 68
#define VS_STR 72
#define PS_STR 68
#define ATT_SMEM ((64*KS_STR + 64*VS_STR + 64*PS_STR) * 4)

__global__ __launch_bounds__(128)
void attn_tc(const float* __restrict__ q, const float* __restrict__ k,
             const float* __restrict__ v, float* __restrict__ o) {
    extern __shared__ uint32_t smu[];
    uint32_t* Ks = smu;
    uint32_t* Vs = Ks + 64 * KS_STR;
    uint32_t* Ps = Vs + 64 * VS_STR;

    const int tid  = threadIdx.x;
    const int lane = tid & 31;
    const int warp = tid >> 5;
    const int gid  = lane >> 2;
    const int tig  = lane & 3;
    const int qt = blockIdx.x, h = blockIdx.y, b = blockIdx.z;
    const size_t base = ((size_t)b * TT) * DD + (size_t)h * HDIM;

    for (int idx = tid; idx < 64 * 16; idx += 128) {
        int row = idx >> 4, c4 = (idx & 15) << 2;
        float4 qv = *(const float4*)(q + base + (size_t)(qt * 64 + row) * DD + c4);
        uint32_t* dst = Ps + row * PS_STR + c4;
        dst[0] = f2tf(qv.x * 0.125f); dst[1] = f2tf(qv.y * 0.125f);
        dst[2] = f2tf(qv.z * 0.125f); dst[3] = f2tf(qv.w * 0.125f);
    }
    __syncthreads();

    uint32_t qf[8][4];
    {
        const uint32_t* Qw = Ps + (warp * 16) * PS_STR;
        #pragma unroll
        for (int k8 = 0; k8 < 8; k8++) {
            int col = k8 * 8 + tig;
            qf[k8][0] = Qw[gid * PS_STR + col];
            qf[k8][1] = Qw[(gid + 8) * PS_STR + col];
            qf[k8][2] = Qw[gid * PS_STR + col + 4];
            qf[k8][3] = Qw[(gid + 8) * PS_STR + col + 4];
        }
    }
    __syncthreads();

    float oacc[8][4];
    #pragma unroll
    for (int nt = 0; nt < 8; nt++)
        #pragma unroll
        for (int u = 0; u < 4; u++) oacc[nt][u] = 0.f;

    float m0 = -INFINITY, m1 = -INFINITY, l0 = 0.f, l1 = 0.f;
    const int r0 = qt * 64 + warp * 16 + gid;
    const int r1 = r0 + 8;
    uint32_t* Pw = Ps + (warp * 16) * PS_STR;

    for (int kt = 0; kt <= qt; kt++) {
        for (int idx = tid; idx < 64 * 16; idx += 128) {
            int row = idx >> 4, c4 = (idx & 15) << 2;
            const float* kp = k + base + (size_t)(kt * 64 + row) * DD + c4;
            const float* vp = v + base + (size_t)(kt * 64 + row) * DD + c4;
            float4 kv = *(const float4*)kp;
            float4 vv = *(const float4*)vp;
            uint32_t* kd = Ks + row * KS_STR + c4;
            kd[0] = f2tf(kv.x); kd[1] = f2tf(kv.y); kd[2] = f2tf(kv.z); kd[3] = f2tf(kv.w);
            uint32_t* vd = Vs + row * VS_STR + c4;
            vd[0] = f2tf(vv.x); vd[1] = f2tf(vv.y); vd[2] = f2tf(vv.z); vd[3] = f2tf(vv.w);
        }
        __syncthreads();

        float s[8][4];
        #pragma unroll
        for (int nt = 0; nt < 8; nt++) {
            s[nt][0] = s[nt][1] = s[nt][2] = s[nt][3] = 0.f;
            #pragma unroll
            for (int k8 = 0; k8 < 8; k8++) {
                uint32_t bf[2];
                const uint32_t* kr = Ks + (nt * 8 + gid) * KS_STR + k8 * 8 + tig;
                bf[0] = kr[0];
                bf[1] = kr[4];
                mma_tf32(s[nt], qf[k8], bf);
            }
        }

        if (kt == qt) {
            #pragma unroll
            for (int nt = 0; nt < 8; nt++) {
                int cc = kt * 64 + nt * 8 + 2 * tig;
                if (cc     > r0) s[nt][0] = -INFINITY;
                if (cc + 1 > r0) s[nt][1] = -INFINITY;
                if (cc     > r1) s[nt][2] = -INFINITY;
                if (cc + 1 > r1) s[nt][3] = -INFINITY;
            }
        }

        float mt0 = -INFINITY, mt1 = -INFINITY;
        #pragma unroll
        for (int nt = 0; nt < 8; nt++) {
            mt0 = fmaxf(mt0, fmaxf(s[nt][0], s[nt][1]));
            mt1 = fmaxf(mt1, fmaxf(s[nt][2], s[nt][3]));
        }
        mt0 = fmaxf(mt0, __shfl_xor_sync(0xFFFFFFFFu, mt0, 1));
        mt0 = fmaxf(mt0, __shfl_xor_sync(0xFFFFFFFFu, mt0, 2));
        mt1 = fmaxf(mt1, __shfl_xor_sync(0xFFFFFFFFu, mt1, 1));
        mt1 = fmaxf(mt1, __shfl_xor_sync(0xFFFFFFFFu, mt1, 2));
        const float mn0 = fmaxf(m0, mt0), mn1 = fmaxf(m1, mt1);
        const float a0 = __expf(m0 - mn0), a1 = __expf(m1 - mn1);

        float ls0 = 0.f, ls1 = 0.f;
        #pragma unroll
        for (int nt = 0; nt < 8; nt++) {
            float p0 = __expf(s[nt][0] - mn0);
            float p1 = __expf(s[nt][1] - mn0);
            float p2 = __expf(s[nt][2] - mn1);
            float p3 = __expf(s[nt][3] - mn1);
            ls0 += p0 + p1; ls1 += p2 + p3;
            uint32_t* d0 = Pw + gid * PS_STR + nt * 8 + 2 * tig;
            d0[0] = f2tf(p0); d0[1] = f2tf(p1);
            uint32_t* d1 = Pw + (gid + 8) * PS_STR + nt * 8 + 2 * tig;
            d1[0] = f2tf(p2); d1[1] = f2tf(p3);
        }
        ls0 += __shfl_xor_sync(0xFFFFFFFFu, ls0, 1);
        ls0 += __shfl_xor_sync(0xFFFFFFFFu, ls0, 2);
        ls1 += __shfl_xor_sync(0xFFFFFFFFu, ls1, 1);
        ls1 += __shfl_xor_sync(0xFFFFFFFFu, ls1, 2);
        l0 = l0 * a0 + ls0;
        l1 = l1 * a1 + ls1;
        m0 = mn0; m1 = mn1;

        #pragma unroll
        for (int nt = 0; nt < 8; nt++) {
            oacc[nt][0] *= a0; oacc[nt][1] *= a0;
            oacc[nt][2] *= a1; oacc[nt][3] *= a1;
        }
        __syncwarp();

        #pragma unroll
        for (int k8 = 0; k8 < 8; k8++) {
            uint32_t af[4];
            af[0] = Pw[gid * PS_STR + k8 * 8 + tig];
            af[1] = Pw[(gid + 8) * PS_STR + k8 * 8 + tig];
            af[2] = Pw[gid * PS_STR + k8 * 8 + tig + 4];
            af[3] = Pw[(gid + 8) * PS_STR + k8 * 8 + tig + 4];
            #pragma unroll
            for (int nt = 0; nt < 8; nt++) {
                uint32_t bf[2];
                bf[0] = Vs[(k8 * 8 + tig) * VS_STR + nt * 8 + gid];
                bf[1] = Vs[(k8 * 8 + tig + 4) * VS_STR + nt * 8 + gid];
                mma_tf32(oacc[nt], af, bf);
            }
        }
        __syncthreads();
    }

    // write O (pre-rounded to tf32: feeds the Wo GEMM)
    const float li0 = 1.0f / l0, li1 = 1.0f / l1;
    #pragma unroll
    for (int nt = 0; nt < 8; nt++) {
        const int col = nt * 8 + 2 * tig;
        float2 w0; w0.x = f2tff(oacc[nt][0] * li0); w0.y = f2tff(oacc[nt][1] * li0);
        float2 w1; w1.x = f2tff(oacc[nt][2] * li1); w1.y = f2tff(oacc[nt][3] * li1);
        *(float2*)(o + base + (size_t)r0 * DD + col) = w0;
        *(float2*)(o + base + (size_t)r1 * DD + col) = w1;
    }
}

// ---------------- launch ----------------
extern "C" void kernel_launch(void* const* d_in, const int* in_sizes, int n_in,
                              void* d_out, int out_size) {
    const float* x     = (const float*)d_in[0];
    const float* Wq    = (const float*)d_in[2];
    const float* Wk    = (const float*)d_in[3];
    const float* Wv    = (const float*)d_in[4];
    const float* Wo    = (const float*)d_in[5];
    const float* bo    = (const float*)d_in[6];
    const float* W1    = (const float*)d_in[7];
    const float* b1    = (const float*)d_in[8];
    const float* W2    = (const float*)d_in[9];
    const float* b2    = (const float*)d_in[10];
    const float* gattn = (const float*)d_in[11];
    const float* gff   = (const float*)d_in[12];
    float* out = (float*)d_out;

    float *xa, *q, *k, *v, *at, *x1, *hb, *wr;
    cudaGetSymbolAddress((void**)&xa, g_xa);
    cudaGetSymbolAddress((void**)&q,  g_q);
    cudaGetSymbolAddress((void**)&k,  g_k);
    cudaGetSymbolAddress((void**)&v,  g_v);
    cudaGetSymbolAddress((void**)&at, g_at);
    cudaGetSymbolAddress((void**)&x1, g_x1);
    cudaGetSymbolAddress((void**)&hb, g_h);
    cudaGetSymbolAddress((void**)&wr, g_wr);

    float* Wq_r = wr;
    float* Wk_r = wr + (size_t)1*1024*1024;
    float* Wv_r = wr + (size_t)2*1024*1024;
    float* Wo_r = wr + (size_t)3*1024*1024;
    float* W1_r = wr + (size_t)4*1024*1024;
    float* W2_r = wr + (size_t)8*1024*1024;

    cudaFuncSetAttribute(attn_tc, cudaFuncAttributeMaxDynamicSharedMemorySize, ATT_SMEM);
    cudaFuncSetAttribute(gemm_tc<0>, cudaFuncAttributeMaxDynamicSharedMemorySize, GEMM_SMEM);
    cudaFuncSetAttribute(gemm_tc<1>, cudaFuncAttributeMaxDynamicSharedMemorySize, GEMM_SMEM);
    cudaFuncSetAttribute(gemm_tc<2>, cudaFuncAttributeMaxDynamicSharedMemorySize, GEMM_SMEM);

    // 0. pre-round weights to tf32 values
    const int nDD = DD * DD / 4, nDF = DD * FF / 4;
    round4_kernel<<<(nDD + 255)/256, 256>>>((const float4*)Wq, (float4*)Wq_r, nDD);
    round4_kernel<<<(nDD + 255)/256, 256>>>((const float4*)Wk, (float4*)Wk_r, nDD);
    round4_kernel<<<(nDD + 255)/256, 256>>>((const float4*)Wv, (float4*)Wv_r, nDD);
    round4_kernel<<<(nDD + 255)/256, 256>>>((const float4*)Wo, (float4*)Wo_r, nDD);
    round4_kernel<<<(nDF + 255)/256, 256>>>((const float4*)W1, (float4*)W1_r, nDF);
    round4_kernel<<<(nDF + 255)/256, 256>>>((const float4*)W2, (float4*)W2_r, nDF);

    // 1. rmsnorm(x, g_attn) -> xa (tf32-rounded)
    rmsnorm_kernel<<<ROWS, 256>>>(x, gattn, xa);

    // 2. fused QKV projections
    {
        dim3 grid(DD / 128, ROWS / 128, 3);
        gemm_tc<0><<<grid, 256, GEMM_SMEM>>>(xa, Wq_r, Wk_r, Wv_r, q, k, v,
                                             nullptr, nullptr, ROWS, DD, DD);
    }

    // 3. causal attention (tensor cores)
    {
        dim3 grid(TT / 64, HH, BB);
        attn_tc<<<grid, 128, ATT_SMEM>>>(q, k, v, at);
    }

    // 4. x1 = x + at @ Wo + bo
    {
        dim3 grid(DD / 128, ROWS / 128, 1);
        gemm_tc<1><<<grid, 256, GEMM_SMEM>>>(at, Wo_r, Wo_r, Wo_r, x1, x1, x1,
                                             bo, x, ROWS, DD, DD);
    }

    // 5. rmsnorm(x1, g_ff) -> xa (tf32-rounded)
    rmsnorm_kernel<<<ROWS, 256>>>(x1, gff, xa);

    // 6. h = silu(xa @ W1 + b1) (tf32-rounded on store)
    {
        dim3 grid(FF / 128, ROWS / 128, 1);
        gemm_tc<2><<<grid, 256, GEMM_SMEM>>>(xa, W1_r, W1_r, W1_r, hb, hb, hb,
                                             b1, nullptr, ROWS, FF, DD);
    }

    // 7. out = x1 + h @ W2 + b2
    {
        dim3 grid(DD / 128, ROWS / 128, 1);
        gemm_tc<1><<<grid, 256, GEMM_SMEM>>>(hb, W2_r, W2_r, W2_r, out, out, out,
                                             b2, x1, ROWS, DD, FF);
    }
}

// round 6
// speedup vs baseline: 8.3754x; 1.6774x over previous
#include <cuda_runtime.h>
#include <cuda_fp16.h>
#include <cstdint>

// ---------------- problem constants ----------------
#define BB   2
#define TT   2048
#define DD   1024
#define HH   16
#define HDIM 64
#define FF   4096
#define ROWS (BB*TT)          // 4096

// ---------------- scratch (device globals) ----------------
__device__ __half g_xa [ROWS*DD];            // rmsnorm out (fp16, GEMM A input)
__device__ float  g_q  [ROWS*DD];
__device__ float  g_k  [ROWS*DD];
__device__ float  g_v  [ROWS*DD];
__device__ __half g_at [ROWS*DD];            // attention out (fp16, GEMM A input)
__device__ float  g_x1 [ROWS*DD];
__device__ __half g_h  [(size_t)ROWS*FF];    // silu out (fp16, GEMM A input)
__device__ __half g_wh [(size_t)12*1024*1024]; // fp16 transposed weights [N,K]

// ---------------- helpers ----------------
__device__ __forceinline__ uint32_t f2tf(float f) {
    uint32_t u; asm("cvt.rna.tf32.f32 %0, %1;" : "=r"(u) : "f"(f)); return u;
}
__device__ __forceinline__ uint32_t smem_u32(const void* p) {
    return (uint32_t)__cvta_generic_to_shared(p);
}
__device__ __forceinline__ void mma_tf32(float* c, const uint32_t* a, const uint32_t* b) {
    asm volatile(
        "mma.sync.aligned.m16n8k8.row.col.f32.tf32.tf32.f32 "
        "{%0,%1,%2,%3},{%4,%5,%6,%7},{%8,%9},{%0,%1,%2,%3};\n"
        : "+f"(c[0]), "+f"(c[1]), "+f"(c[2]), "+f"(c[3])
        : "r"(a[0]), "r"(a[1]), "r"(a[2]), "r"(a[3]), "r"(b[0]), "r"(b[1]));
}
__device__ __forceinline__ void mma_f16(float* c, const uint32_t* a,
                                        uint32_t b0, uint32_t b1) {
    asm volatile(
        "mma.sync.aligned.m16n8k16.row.col.f32.f16.f16.f32 "
        "{%0,%1,%2,%3},{%4,%5,%6,%7},{%8,%9},{%0,%1,%2,%3};\n"
        : "+f"(c[0]), "+f"(c[1]), "+f"(c[2]), "+f"(c[3])
        : "r"(a[0]), "r"(a[1]), "r"(a[2]), "r"(a[3]), "r"(b0), "r"(b1));
}
__device__ __forceinline__ void ldsm_x4(uint32_t* r, uint32_t saddr) {
    asm volatile("ldmatrix.sync.aligned.m8n8.x4.shared.b16 {%0,%1,%2,%3}, [%4];"
                 : "=r"(r[0]), "=r"(r[1]), "=r"(r[2]), "=r"(r[3]) : "r"(saddr));
}
__device__ __forceinline__ void cp16(uint32_t saddr, const void* g) {
    asm volatile("cp.async.cg.shared.global [%0], [%1], 16;\n" :: "r"(saddr), "l"(g));
}

// ---------------- weight transpose + fp16 round: [K,N] -> [N,K] ----------------
__global__ __launch_bounds__(256)
void transpose_half(const float* __restrict__ in, __half* __restrict__ out,
                    int K, int N) {
    __shared__ float t[32][33];
    const int n0 = blockIdx.x * 32, k0 = blockIdx.y * 32;
    const int tx = threadIdx.x, ty = threadIdx.y;
    #pragma unroll
    for (int i = ty; i < 32; i += 8)
        t[i][tx] = in[(size_t)(k0 + i) * N + n0 + tx];
    __syncthreads();
    #pragma unroll
    for (int i = ty; i < 32; i += 8)
        out[(size_t)(n0 + i) * K + k0 + tx] = __float2half_rn(t[tx][i]);
}

// ---------------- rmsnorm (fp16 output) ----------------
__global__ __launch_bounds__(256)
void rmsnorm_kernel(const float* __restrict__ x, const float* __restrict__ g,
                    __half* __restrict__ out) {
    __shared__ float red[256];
    const int row = blockIdx.x;
    const int tid = threadIdx.x;
    const float4 v = ((const float4*)(x + (size_t)row * DD))[tid];
    float ss = v.x*v.x + v.y*v.y + v.z*v.z + v.w*v.w;
    red[tid] = ss;
    __syncthreads();
    #pragma unroll
    for (int s = 128; s > 0; s >>= 1) {
        if (tid < s) red[tid] += red[tid + s];
        __syncthreads();
    }
    const float norm = rsqrtf(red[0] * (1.0f / DD) + 1e-5f);
    const float4 gv = ((const float4*)g)[tid];
    __half2 h01 = __floats2half2_rn(v.x * norm * gv.x, v.y * norm * gv.y);
    __half2 h23 = __floats2half2_rn(v.z * norm * gv.z, v.w * norm * gv.w);
    uint2 pk; pk.x = *(uint32_t*)&h01; pk.y = *(uint32_t*)&h23;
    ((uint2*)(out + (size_t)row * DD))[tid] = pk;
}

// ---------------- fp16 tensor-core GEMM, 3-stage cp.async pipeline ----------
// C[M,N] = A[M,K] @ Bt[N,K]^T. BM=BN=128, BK=64 halves, 256 thr, 2x4 warps.
// Both A and B smem: [128 rows][64 halves] with 16B-chunk XOR-8 swizzle.
// EPI 0: float out; 1: float out = acc+bias+res; 2: half out = silu(acc+bias).
#define SGS3 3
#define STG_BYTES 32768                       // A 16KB + B 16KB
#define GEMM_SMEM (SGS3 * STG_BYTES)          // 98304

template <int EPI>
__global__ __launch_bounds__(256, 2)
void gemm_f16(const __half* __restrict__ A,
              const __half* __restrict__ B0, const __half* __restrict__ B1,
              const __half* __restrict__ B2,
              void* C0v, void* C1v, void* C2v,
              const float* __restrict__ bias, const float* __restrict__ res,
              int N, int K) {
    extern __shared__ __align__(16) char dynsm[];
    const uint32_t sb = smem_u32(dynsm);

    const __half* Bt = (blockIdx.z == 0) ? B0 : (blockIdx.z == 1 ? B1 : B2);
    void* Cv = (blockIdx.z == 0) ? C0v : (blockIdx.z == 1 ? C1v : C2v);

    const int tid   = threadIdx.x;
    const int lane  = tid & 31;
    const int warp  = tid >> 5;
    const int warpM = warp & 1;
    const int warpN = warp >> 1;
    const int g8    = lane >> 3;     // ldmatrix lane group 0..3
    const int i7    = lane & 7;

    const int bm = blockIdx.y, bn = blockIdx.x;
    const __half* Aq = A  + (size_t)bm * 128 * K;
    const __half* Bq = Bt + (size_t)bn * 128 * K;

    // ldmatrix per-lane row/chunk components (row&7 == i7 for both)
    const int aRow = warpM * 64 + (g8 & 1) * 8 + i7;   // + mi*16
    const int aHi  = g8 >> 1;
    const int bRow = warpN * 32 + (g8 >> 1) * 8 + i7;  // + nj*16
    const int bHi  = g8 & 1;

    // cp.async indices: 4 chunks each for A and B per stage
    int cprow[4], cpch[4], cpsw[4];
    #pragma unroll
    for (int p = 0; p < 4; p++) {
        int idx = tid + p * 256;
        cprow[p] = idx >> 3;
        cpch[p]  = idx & 7;
        cpsw[p]  = cpch[p] ^ (cprow[p] & 7);
    }

#define ISSUE_STAGE(st, kb)                                                    \
    {                                                                          \
        uint32_t Ab = sb + (st) * STG_BYTES;                                   \
        uint32_t Bb = Ab + 16384;                                              \
        _Pragma("unroll")                                                      \
        for (int p = 0; p < 4; p++) {                                          \
            cp16(Ab + cprow[p] * 128 + cpsw[p] * 16,                           \
                 Aq + (size_t)cprow[p] * K + (kb) + cpch[p] * 8);              \
            cp16(Bb + cprow[p] * 128 + cpsw[p] * 16,                           \
                 Bq + (size_t)cprow[p] * K + (kb) + cpch[p] * 8);              \
        }                                                                      \
        asm volatile("cp.async.commit_group;\n");                              \
    }

    float c[4][4][4];
    #pragma unroll
    for (int mi = 0; mi < 4; mi++)
        #pragma unroll
        for (int ni = 0; ni < 4; ni++)
            #pragma unroll
            for (int u = 0; u < 4; u++) c[mi][ni][u] = 0.f;

    const int ktiles = K >> 6;

    ISSUE_STAGE(0, 0);
    ISSUE_STAGE(1, 64);

    for (int u = 0; u < ktiles; u++) {
        asm volatile("cp.async.wait_group 1;\n");
        __syncthreads();

        if (u + 2 < ktiles) {
            const int stn = (u + 2) % SGS3;
            ISSUE_STAGE(stn, (u + 2) * 64);
        } else {
            asm volatile("cp.async.commit_group;\n");   // keep group count uniform
        }

        const int st = u % SGS3;
        const uint32_t Ab = sb + st * STG_BYTES;
        const uint32_t Bb = Ab + 16384;

        #pragma unroll
        for (int s = 0; s < 4; s++) {
            uint32_t af[4][4], bf[2][4];
            const int ac = ((2 * s + aHi) ^ i7) << 4;
            const int bc = ((2 * s + bHi) ^ i7) << 4;
            #pragma unroll
            for (int mi = 0; mi < 4; mi++)
                ldsm_x4(af[mi], Ab + (aRow + mi * 16) * 128 + ac);
            #pragma unroll
            for (int nj = 0; nj < 2; nj++)
                ldsm_x4(bf[nj], Bb + (bRow + nj * 16) * 128 + bc);
            #pragma unroll
            for (int mi = 0; mi < 4; mi++)
                #pragma unroll
                for (int ni = 0; ni < 4; ni++)
                    mma_f16(c[mi][ni], af[mi],
                            bf[ni >> 1][(ni & 1) * 2], bf[ni >> 1][(ni & 1) * 2 + 1]);
        }
    }
#undef ISSUE_STAGE

    // ---------------- epilogue (direct reg -> gmem) ----------------
    const int gid = lane >> 2, tig = lane & 3;
    #pragma unroll
    for (int mi = 0; mi < 4; mi++) {
        const int r0 = bm * 128 + warpM * 64 + mi * 16 + gid;
        const int r1 = r0 + 8;
        #pragma unroll
        for (int ni = 0; ni < 4; ni++) {
            const int col = bn * 128 + warpN * 32 + ni * 8 + 2 * tig;
            float v0 = c[mi][ni][0], v1 = c[mi][ni][1];
            float v2 = c[mi][ni][2], v3 = c[mi][ni][3];
            if (EPI == 0) {
                float* C = (float*)Cv;
                float2 o0; o0.x = v0; o0.y = v1;
                float2 o1; o1.x = v2; o1.y = v3;
                *(float2*)(C + (size_t)r0 * N + col) = o0;
                *(float2*)(C + (size_t)r1 * N + col) = o1;
            } else if (EPI == 1) {
                float* C = (float*)Cv;
                const float b0 = bias[col], b1 = bias[col + 1];
                const float2 rA = *(const float2*)(res + (size_t)r0 * N + col);
                const float2 rB = *(const float2*)(res + (size_t)r1 * N + col);
                float2 o0; o0.x = v0 + b0 + rA.x; o0.y = v1 + b1 + rA.y;
                float2 o1; o1.x = v2 + b0 + rB.x; o1.y = v3 + b1 + rB.y;
                *(float2*)(C + (size_t)r0 * N + col) = o0;
                *(float2*)(C + (size_t)r1 * N + col) = o1;
            } else {
                __half* C = (__half*)Cv;
                const float b0 = bias[col], b1 = bias[col + 1];
                v0 += b0; v1 += b1; v2 += b0; v3 += b1;
                v0 = v0 / (1.0f + __expf(-v0));
                v1 = v1 / (1.0f + __expf(-v1));
                v2 = v2 / (1.0f + __expf(-v2));
                v3 = v3 / (1.0f + __expf(-v3));
                *(__half2*)(C + (size_t)r0 * N + col) = __floats2half2_rn(v0, v1);
                *(__half2*)(C + (size_t)r1 * N + col) = __floats2half2_rn(v2, v3);
            }
        }
    }
}

// ---------------- tensor-core flash attention (tf32, causal) ----------------
#define KS_STR 68
#define VS_STR 72
#define PS_STR 68
#define ATT_SMEM ((64*KS_STR + 64*VS_STR + 64*PS_STR) * 4)

__global__ __launch_bounds__(128)
void attn_tc(const float* __restrict__ q, const float* __restrict__ k,
             const float* __restrict__ v, __half* __restrict__ o) {
    extern __shared__ uint32_t smu[];
    uint32_t* Ks = smu;
    uint32_t* Vs = Ks + 64 * KS_STR;
    uint32_t* Ps = Vs + 64 * VS_STR;

    const int tid  = threadIdx.x;
    const int lane = tid & 31;
    const int warp = tid >> 5;
    const int gid  = lane >> 2;
    const int tig  = lane & 3;
    const int qt = blockIdx.x, h = blockIdx.y, b = blockIdx.z;
    const size_t base = ((size_t)b * TT) * DD + (size_t)h * HDIM;

    for (int idx = tid; idx < 64 * 16; idx += 128) {
        int row = idx >> 4, c4 = (idx & 15) << 2;
        float4 qv = *(const float4*)(q + base + (size_t)(qt * 64 + row) * DD + c4);
        uint32_t* dst = Ps + row * PS_STR + c4;
        dst[0] = f2tf(qv.x * 0.125f); dst[1] = f2tf(qv.y * 0.125f);
        dst[2] = f2tf(qv.z * 0.125f); dst[3] = f2tf(qv.w * 0.125f);
    }
    __syncthreads();

    uint32_t qf[8][4];
    {
        const uint32_t* Qw = Ps + (warp * 16) * PS_STR;
        #pragma unroll
        for (int k8 = 0; k8 < 8; k8++) {
            int col = k8 * 8 + tig;
            qf[k8][0] = Qw[gid * PS_STR + col];
            qf[k8][1] = Qw[(gid + 8) * PS_STR + col];
            qf[k8][2] = Qw[gid * PS_STR + col + 4];
            qf[k8][3] = Qw[(gid + 8) * PS_STR + col + 4];
        }
    }
    __syncthreads();

    float oacc[8][4];
    #pragma unroll
    for (int nt = 0; nt < 8; nt++)
        #pragma unroll
        for (int u = 0; u < 4; u++) oacc[nt][u] = 0.f;

    float m0 = -INFINITY, m1 = -INFINITY, l0 = 0.f, l1 = 0.f;
    const int r0 = qt * 64 + warp * 16 + gid;
    const int r1 = r0 + 8;
    uint32_t* Pw = Ps + (warp * 16) * PS_STR;

    for (int kt = 0; kt <= qt; kt++) {
        for (int idx = tid; idx < 64 * 16; idx += 128) {
            int row = idx >> 4, c4 = (idx & 15) << 2;
            const float* kp = k + base + (size_t)(kt * 64 + row) * DD + c4;
            const float* vp = v + base + (size_t)(kt * 64 + row) * DD + c4;
            float4 kv = *(const float4*)kp;
            float4 vv = *(const float4*)vp;
            uint32_t* kd = Ks + row * KS_STR + c4;
            kd[0] = f2tf(kv.x); kd[1] = f2tf(kv.y); kd[2] = f2tf(kv.z); kd[3] = f2tf(kv.w);
            uint32_t* vd = Vs + row * VS_STR + c4;
            vd[0] = f2tf(vv.x); vd[1] = f2tf(vv.y); vd[2] = f2tf(vv.z); vd[3] = f2tf(vv.w);
        }
        __syncthreads();

        float s[8][4];
        #pragma unroll
        for (int nt = 0; nt < 8; nt++) {
            s[nt][0] = s[nt][1] = s[nt][2] = s[nt][3] = 0.f;
            #pragma unroll
            for (int k8 = 0; k8 < 8; k8++) {
                uint32_t bfm[2];
                const uint32_t* kr = Ks + (nt * 8 + gid) * KS_STR + k8 * 8 + tig;
                bfm[0] = kr[0];
                bfm[1] = kr[4];
                mma_tf32(s[nt], qf[k8], bfm);
            }
        }

        if (kt == qt) {
            #pragma unroll
            for (int nt = 0; nt < 8; nt++) {
                int cc = kt * 64 + nt * 8 + 2 * tig;
                if (cc     > r0) s[nt][0] = -INFINITY;
                if (cc + 1 > r0) s[nt][1] = -INFINITY;
                if (cc     > r1) s[nt][2] = -INFINITY;
                if (cc + 1 > r1) s[nt][3] = -INFINITY;
            }
        }

        float mt0 = -INFINITY, mt1 = -INFINITY;
        #pragma unroll
        for (int nt = 0; nt < 8; nt++) {
            mt0 = fmaxf(mt0, fmaxf(s[nt][0], s[nt][1]));
            mt1 = fmaxf(mt1, fmaxf(s[nt][2], s[nt][3]));
        }
        mt0 = fmaxf(mt0, __shfl_xor_sync(0xFFFFFFFFu, mt0, 1));
        mt0 = fmaxf(mt0, __shfl_xor_sync(0xFFFFFFFFu, mt0, 2));
        mt1 = fmaxf(mt1, __shfl_xor_sync(0xFFFFFFFFu, mt1, 1));
        mt1 = fmaxf(mt1, __shfl_xor_sync(0xFFFFFFFFu, mt1, 2));
        const float mn0 = fmaxf(m0, mt0), mn1 = fmaxf(m1, mt1);
        const float a0 = __expf(m0 - mn0), a1 = __expf(m1 - mn1);

        float ls0 = 0.f, ls1 = 0.f;
        #pragma unroll
        for (int nt = 0; nt < 8; nt++) {
            float p0 = __expf(s[nt][0] - mn0);
            float p1 = __expf(s[nt][1] - mn0);
            float p2 = __expf(s[nt][2] - mn1);
            float p3 = __expf(s[nt][3] - mn1);
            ls0 += p0 + p1; ls1 += p2 + p3;
            uint32_t* d0 = Pw + gid * PS_STR + nt * 8 + 2 * tig;
            d0[0] = f2tf(p0); d0[1] = f2tf(p1);
            uint32_t* d1 = Pw + (gid + 8) * PS_STR + nt * 8 + 2 * tig;
            d1[0] = f2tf(p2); d1[1] = f2tf(p3);
        }
        ls0 += __shfl_xor_sync(0xFFFFFFFFu, ls0, 1);
        ls0 += __shfl_xor_sync(0xFFFFFFFFu, ls0, 2);
        ls1 += __shfl_xor_sync(0xFFFFFFFFu, ls1, 1);
        ls1 += __shfl_xor_sync(0xFFFFFFFFu, ls1, 2);
        l0 = l0 * a0 + ls0;
        l1 = l1 * a1 + ls1;
        m0 = mn0; m1 = mn1;

        #pragma unroll
        for (int nt = 0; nt < 8; nt++) {
            oacc[nt][0] *= a0; oacc[nt][1] *= a0;
            oacc[nt][2] *= a1; oacc[nt][3] *= a1;
        }
        __syncwarp();

        #pragma unroll
        for (int k8 = 0; k8 < 8; k8++) {
            uint32_t af[4];
            af[0] = Pw[gid * PS_STR + k8 * 8 + tig];
            af[1] = Pw[(gid + 8) * PS_STR + k8 * 8 + tig];
            af[2] = Pw[gid * PS_STR + k8 * 8 + tig + 4];
            af[3] = Pw[(gid + 8) * PS_STR + k8 * 8 + tig + 4];
            #pragma unroll
            for (int nt = 0; nt < 8; nt++) {
                uint32_t bfm[2];
                bfm[0] = Vs[(k8 * 8 + tig) * VS_STR + nt * 8 + gid];
                bfm[1] = Vs[(k8 * 8 + tig + 4) * VS_STR + nt * 8 + gid];
                mma_tf32(oacc[nt], af, bfm);
            }
        }
        __syncthreads();
    }

    // write O as fp16 (feeds Wo GEMM)
    const float li0 = 1.0f / l0, li1 = 1.0f / l1;
    #pragma unroll
    for (int nt = 0; nt < 8; nt++) {
        const int col = nt * 8 + 2 * tig;
        *(__half2*)(o + base + (size_t)r0 * DD + col) =
            __floats2half2_rn(oacc[nt][0] * li0, oacc[nt][1] * li0);
        *(__half2*)(o + base + (size_t)r1 * DD + col) =
            __floats2half2_rn(oacc[nt][2] * li1, oacc[nt][3] * li1);
    }
}

// ---------------- launch ----------------
extern "C" void kernel_launch(void* const* d_in, const int* in_sizes, int n_in,
                              void* d_out, int out_size) {
    const float* x     = (const float*)d_in[0];
    const float* Wq    = (const float*)d_in[2];
    const float* Wk    = (const float*)d_in[3];
    const float* Wv    = (const float*)d_in[4];
    const float* Wo    = (const float*)d_in[5];
    const float* bo    = (const float*)d_in[6];
    const float* W1    = (const float*)d_in[7];
    const float* b1    = (const float*)d_in[8];
    const float* W2    = (const float*)d_in[9];
    const float* b2    = (const float*)d_in[10];
    const float* gattn = (const float*)d_in[11];
    const float* gff   = (const float*)d_in[12];
    float* out = (float*)d_out;

    __half *xa, *at, *hb, *wh;
    float *q, *k, *v, *x1;
    cudaGetSymbolAddress((void**)&xa, g_xa);
    cudaGetSymbolAddress((void**)&q,  g_q);
    cudaGetSymbolAddress((void**)&k,  g_k);
    cudaGetSymbolAddress((void**)&v,  g_v);
    cudaGetSymbolAddress((void**)&at, g_at);
    cudaGetSymbolAddress((void**)&x1, g_x1);
    cudaGetSymbolAddress((void**)&hb, g_h);
    cudaGetSymbolAddress((void**)&wh, g_wh);

    __half* Wq_t = wh;                               // [1024,1024]
    __half* Wk_t = wh + (size_t)1*1024*1024;
    __half* Wv_t = wh + (size_t)2*1024*1024;
    __half* Wo_t = wh + (size_t)3*1024*1024;
    __half* W1_t = wh + (size_t)4*1024*1024;         // [4096,1024]
    __half* W2_t = wh + (size_t)8*1024*1024;         // [1024,4096]

    cudaFuncSetAttribute(attn_tc, cudaFuncAttributeMaxDynamicSharedMemorySize, ATT_SMEM);
    cudaFuncSetAttribute(gemm_f16<0>, cudaFuncAttributeMaxDynamicSharedMemorySize, GEMM_SMEM);
    cudaFuncSetAttribute(gemm_f16<1>, cudaFuncAttributeMaxDynamicSharedMemorySize, GEMM_SMEM);
    cudaFuncSetAttribute(gemm_f16<2>, cudaFuncAttributeMaxDynamicSharedMemorySize, GEMM_SMEM);

    // 0. transpose + fp16-round weights: [K,N] -> [N,K]
    {
        dim3 blk(32, 8);
        transpose_half<<<dim3(DD/32, DD/32), blk>>>(Wq, Wq_t, DD, DD);
        transpose_half<<<dim3(DD/32, DD/32), blk>>>(Wk, Wk_t, DD, DD);
        transpose_half<<<dim3(DD/32, DD/32), blk>>>(Wv, Wv_t, DD, DD);
        transpose_half<<<dim3(DD/32, DD/32), blk>>>(Wo, Wo_t, DD, DD);
        transpose_half<<<dim3(FF/32, DD/32), blk>>>(W1, W1_t, DD, FF);
        transpose_half<<<dim3(DD/32, FF/32), blk>>>(W2, W2_t, FF, DD);
    }

    // 1. rmsnorm(x, g_attn) -> xa (fp16)
    rmsnorm_kernel<<<ROWS, 256>>>(x, gattn, xa);

    // 2. fused QKV projections (fp16 MMA)
    {
        dim3 grid(DD / 128, ROWS / 128, 3);
        gemm_f16<0><<<grid, 256, GEMM_SMEM>>>(xa, Wq_t, Wk_t, Wv_t,
                                              q, k, v, nullptr, nullptr, DD, DD);
    }

    // 3. causal attention (tf32 MMA) -> at (fp16)
    {
        dim3 grid(TT / 64, HH, BB);
        attn_tc<<<grid, 128, ATT_SMEM>>>(q, k, v, at);
    }

    // 4. x1 = x + at @ Wo + bo
    {
        dim3 grid(DD / 128, ROWS / 128, 1);
        gemm_f16<1><<<grid, 256, GEMM_SMEM>>>(at, Wo_t, Wo_t, Wo_t,
                                              x1, x1, x1, bo, x, DD, DD);
    }

    // 5. rmsnorm(x1, g_ff) -> xa (fp16)
    rmsnorm_kernel<<<ROWS, 256>>>(x1, gff, xa);

    // 6. h = silu(xa @ W1 + b1) -> hb (fp16)
    {
        dim3 grid(FF / 128, ROWS / 128, 1);
        gemm_f16<2><<<grid, 256, GEMM_SMEM>>>(xa, W1_t, W1_t, W1_t,
                                              hb, hb, hb, b1, nullptr, FF, DD);
    }

    // 7. out = x1 + hb @ W2 + b2
    {
        dim3 grid(DD / 128, ROWS / 128, 1);
        gemm_f16<1><<<grid, 256, GEMM_SMEM>>>(hb, W2_t, W2_t, W2_t,
                                              out, out, out, b2, x1, DD, FF);
    }
}

// round 9
// speedup vs baseline: 10.7206x; 1.2800x over previous
#include <cuda_runtime.h>
#include <cuda_fp16.h>
#include <cstdint>

// ---------------- problem constants ----------------
#define BB   2
#define TT   2048
#define DD   1024
#define HH   16
#define HDIM 64
#define FF   4096
#define ROWS (BB*TT)          // 4096

// ---------------- scratch (device globals) ----------------
__device__ __half g_xa [ROWS*DD];            // rmsnorm out (fp16)
__device__ __half g_q  [ROWS*DD];            // Q (pre-scaled by 0.125, fp16)
__device__ __half g_k  [ROWS*DD];
__device__ __half g_v  [ROWS*DD];
__device__ __half g_at [ROWS*DD];            // attention out (fp16)
__device__ float  g_x1 [ROWS*DD];
__device__ __half g_h  [(size_t)ROWS*FF];    // silu out (fp16)
__device__ __half g_wh [(size_t)12*1024*1024]; // fp16 transposed weights [N,K]

// ---------------- helpers ----------------
__device__ __forceinline__ uint32_t smem_u32(const void* p) {
    return (uint32_t)__cvta_generic_to_shared(p);
}
__device__ __forceinline__ void mma_f16(float* c, const uint32_t* a,
                                        uint32_t b0, uint32_t b1) {
    asm volatile(
        "mma.sync.aligned.m16n8k16.row.col.f32.f16.f16.f32 "
        "{%0,%1,%2,%3},{%4,%5,%6,%7},{%8,%9},{%0,%1,%2,%3};\n"
        : "+f"(c[0]), "+f"(c[1]), "+f"(c[2]), "+f"(c[3])
        : "r"(a[0]), "r"(a[1]), "r"(a[2]), "r"(a[3]), "r"(b0), "r"(b1));
}
__device__ __forceinline__ void ldsm_x4(uint32_t* r, uint32_t saddr) {
    asm volatile("ldmatrix.sync.aligned.m8n8.x4.shared.b16 {%0,%1,%2,%3}, [%4];"
                 : "=r"(r[0]), "=r"(r[1]), "=r"(r[2]), "=r"(r[3]) : "r"(saddr));
}
__device__ __forceinline__ void ldsm_x4_t(uint32_t* r, uint32_t saddr) {
    asm volatile("ldmatrix.sync.aligned.m8n8.x4.trans.shared.b16 {%0,%1,%2,%3}, [%4];"
                 : "=r"(r[0]), "=r"(r[1]), "=r"(r[2]), "=r"(r[3]) : "r"(saddr));
}
__device__ __forceinline__ void cp16(uint32_t saddr, const void* g) {
    asm volatile("cp.async.cg.shared.global [%0], [%1], 16;\n" :: "r"(saddr), "l"(g));
}

// ---------------- weight transpose + fp16 round: [K,N] -> [N,K] ----------------
__global__ __launch_bounds__(256)
void transpose_half(const float* __restrict__ in, __half* __restrict__ out,
                    int K, int N) {
    __shared__ float t[32][33];
    const int n0 = blockIdx.x * 32, k0 = blockIdx.y * 32;
    const int tx = threadIdx.x, ty = threadIdx.y;
    #pragma unroll
    for (int i = ty; i < 32; i += 8)
        t[i][tx] = in[(size_t)(k0 + i) * N + n0 + tx];
    __syncthreads();
    #pragma unroll
    for (int i = ty; i < 32; i += 8)
        out[(size_t)(n0 + i) * K + k0 + tx] = __float2half_rn(t[tx][i]);
}

// ---------------- rmsnorm (fp16 output) ----------------
__global__ __launch_bounds__(256)
void rmsnorm_kernel(const float* __restrict__ x, const float* __restrict__ g,
                    __half* __restrict__ out) {
    __shared__ float red[256];
    const int row = blockIdx.x;
    const int tid = threadIdx.x;
    const float4 v = ((const float4*)(x + (size_t)row * DD))[tid];
    float ss = v.x*v.x + v.y*v.y + v.z*v.z + v.w*v.w;
    red[tid] = ss;
    __syncthreads();
    #pragma unroll
    for (int s = 128; s > 0; s >>= 1) {
        if (tid < s) red[tid] += red[tid + s];
        __syncthreads();
    }
    const float norm = rsqrtf(red[0] * (1.0f / DD) + 1e-5f);
    const float4 gv = ((const float4*)g)[tid];
    __half2 h01 = __floats2half2_rn(v.x * norm * gv.x, v.y * norm * gv.y);
    __half2 h23 = __floats2half2_rn(v.z * norm * gv.z, v.w * norm * gv.w);
    uint2 pk; pk.x = *(uint32_t*)&h01; pk.y = *(uint32_t*)&h23;
    ((uint2*)(out + (size_t)row * DD))[tid] = pk;
}

// ---------------- fp16 tensor-core GEMM, 3-stage cp.async pipeline ----------
// EPI 0: float out; 1: float = acc+bias+res; 2: half = silu(acc+bias);
// EPI 3: half = acc * (z==0 ? 0.125 : 1)   [QKV path, Q pre-scaled]
#define SGS3 3
#define STG_BYTES 32768
#define GEMM_SMEM (SGS3 * STG_BYTES)

template <int EPI>
__global__ __launch_bounds__(256, 2)
void gemm_f16(const __half* __restrict__ A,
              const __half* __restrict__ B0, const __half* __restrict__ B1,
              const __half* __restrict__ B2,
              void* C0v, void* C1v, void* C2v,
              const float* __restrict__ bias, const float* __restrict__ res,
              int N, int K) {
    extern __shared__ __align__(16) char dynsm[];
    const uint32_t sb = smem_u32(dynsm);

    const __half* Bt = (blockIdx.z == 0) ? B0 : (blockIdx.z == 1 ? B1 : B2);
    void* Cv = (blockIdx.z == 0) ? C0v : (blockIdx.z == 1 ? C1v : C2v);

    const int tid   = threadIdx.x;
    const int lane  = tid & 31;
    const int warp  = tid >> 5;
    const int warpM = warp & 1;
    const int warpN = warp >> 1;
    const int g8    = lane >> 3;
    const int i7    = lane & 7;

    const int bm = blockIdx.y, bn = blockIdx.x;
    const __half* Aq = A  + (size_t)bm * 128 * K;
    const __half* Bq = Bt + (size_t)bn * 128 * K;

    const int aRow = warpM * 64 + (g8 & 1) * 8 + i7;
    const int aHi  = g8 >> 1;
    const int bRow = warpN * 32 + (g8 >> 1) * 8 + i7;
    const int bHi  = g8 & 1;

    int cprow[4], cpch[4], cpsw[4];
    #pragma unroll
    for (int p = 0; p < 4; p++) {
        int idx = tid + p * 256;
        cprow[p] = idx >> 3;
        cpch[p]  = idx & 7;
        cpsw[p]  = cpch[p] ^ (cprow[p] & 7);
    }

#define ISSUE_STAGE(st, kb)                                                    \
    {                                                                          \
        uint32_t Ab = sb + (st) * STG_BYTES;                                   \
        uint32_t Bb = Ab + 16384;                                              \
        _Pragma("unroll")                                                      \
        for (int p = 0; p < 4; p++) {                                          \
            cp16(Ab + cprow[p] * 128 + cpsw[p] * 16,                           \
                 Aq + (size_t)cprow[p] * K + (kb) + cpch[p] * 8);              \
            cp16(Bb + cprow[p] * 128 + cpsw[p] * 16,                           \
                 Bq + (size_t)cprow[p] * K + (kb) + cpch[p] * 8);              \
        }                                                                      \
        asm volatile("cp.async.commit_group;\n");                              \
    }

    float c[4][4][4];
    #pragma unroll
    for (int mi = 0; mi < 4; mi++)
        #pragma unroll
        for (int ni = 0; ni < 4; ni++)
            #pragma unroll
            for (int u = 0; u < 4; u++) c[mi][ni][u] = 0.f;

    const int ktiles = K >> 6;

    ISSUE_STAGE(0, 0);
    ISSUE_STAGE(1, 64);

    for (int u = 0; u < ktiles; u++) {
        asm volatile("cp.async.wait_group 1;\n");
        __syncthreads();

        if (u + 2 < ktiles) {
            const int stn = (u + 2) % SGS3;
            ISSUE_STAGE(stn, (u + 2) * 64);
        } else {
            asm volatile("cp.async.commit_group;\n");
        }

        const int st = u % SGS3;
        const uint32_t Ab = sb + st * STG_BYTES;
        const uint32_t Bb = Ab + 16384;

        #pragma unroll
        for (int s = 0; s < 4; s++) {
            uint32_t af[4][4], bf[2][4];
            const int ac = ((2 * s + aHi) ^ i7) << 4;
            const int bc = ((2 * s + bHi) ^ i7) << 4;
            #pragma unroll
            for (int mi = 0; mi < 4; mi++)
                ldsm_x4(af[mi], Ab + (aRow + mi * 16) * 128 + ac);
            #pragma unroll
            for (int nj = 0; nj < 2; nj++)
                ldsm_x4(bf[nj], Bb + (bRow + nj * 16) * 128 + bc);
            #pragma unroll
            for (int mi = 0; mi < 4; mi++)
                #pragma unroll
                for (int ni = 0; ni < 4; ni++)
                    mma_f16(c[mi][ni], af[mi],
                            bf[ni >> 1][(ni & 1) * 2], bf[ni >> 1][(ni & 1) * 2 + 1]);
        }
    }
#undef ISSUE_STAGE

    const int gid = lane >> 2, tig = lane & 3;
    #pragma unroll
    for (int mi = 0; mi < 4; mi++) {
        const int r0 = bm * 128 + warpM * 64 + mi * 16 + gid;
        const int r1 = r0 + 8;
        #pragma unroll
        for (int ni = 0; ni < 4; ni++) {
            const int col = bn * 128 + warpN * 32 + ni * 8 + 2 * tig;
            float v0 = c[mi][ni][0], v1 = c[mi][ni][1];
            float v2 = c[mi][ni][2], v3 = c[mi][ni][3];
            if (EPI == 0) {
                float* C = (float*)Cv;
                float2 o0; o0.x = v0; o0.y = v1;
                float2 o1; o1.x = v2; o1.y = v3;
                *(float2*)(C + (size_t)r0 * N + col) = o0;
                *(float2*)(C + (size_t)r1 * N + col) = o1;
            } else if (EPI == 1) {
                float* C = (float*)Cv;
                const float b0 = bias[col], b1 = bias[col + 1];
                const float2 rA = *(const float2*)(res + (size_t)r0 * N + col);
                const float2 rB = *(const float2*)(res + (size_t)r1 * N + col);
                float2 o0; o0.x = v0 + b0 + rA.x; o0.y = v1 + b1 + rA.y;
                float2 o1; o1.x = v2 + b0 + rB.x; o1.y = v3 + b1 + rB.y;
                *(float2*)(C + (size_t)r0 * N + col) = o0;
                *(float2*)(C + (size_t)r1 * N + col) = o1;
            } else if (EPI == 2) {
                __half* C = (__half*)Cv;
                const float b0 = bias[col], b1 = bias[col + 1];
                v0 += b0; v1 += b1; v2 += b0; v3 += b1;
                v0 = v0 / (1.0f + __expf(-v0));
                v1 = v1 / (1.0f + __expf(-v1));
                v2 = v2 / (1.0f + __expf(-v2));
                v3 = v3 / (1.0f + __expf(-v3));
                *(__half2*)(C + (size_t)r0 * N + col) = __floats2half2_rn(v0, v1);
                *(__half2*)(C + (size_t)r1 * N + col) = __floats2half2_rn(v2, v3);
            } else {
                __half* C = (__half*)Cv;
                const float sc = (blockIdx.z == 0) ? 0.125f : 1.0f;
                *(__half2*)(C + (size_t)r0 * N + col) = __floats2half2_rn(v0*sc, v1*sc);
                *(__half2*)(C + (size_t)r1 * N + col) = __floats2half2_rn(v2*sc, v3*sc);
            }
        }
    }
}

// ---------------- fp16 tensor-core flash attention (causal) ----------------
// Block: 64 q-rows x (head, batch). 4 warps x 16 rows. 32KB static smem.
// BYTE layout: Q [0,8192), K [8192,16384), V [16384,24576), P [24576,32768)
__global__ __launch_bounds__(128)
void attn_f16(const __half* __restrict__ q, const __half* __restrict__ k,
              const __half* __restrict__ v, __half* __restrict__ o) {
    __shared__ __align__(16) __half sm[16384];
    const uint32_t sb = smem_u32(sm);
    const uint32_t Kb = sb + 8192;
    const uint32_t Vb = sb + 16384;

    const int tid  = threadIdx.x;
    const int lane = tid & 31;
    const int warp = tid >> 5;
    const int g8   = lane >> 3;
    const int i7   = lane & 7;
    const int gid  = lane >> 2;
    const int tig  = lane & 3;
    const int qt = blockIdx.x, h = blockIdx.y, b = blockIdx.z;
    const size_t base = ((size_t)b * TT) * DD + (size_t)h * HDIM;

    const __half* qg = q + base + (size_t)qt * 64 * DD;
    const __half* kg = k + base;
    const __half* vg = v + base;

    // prologue: load Q tile + K/V tile 0 (swizzled rows of 64 halves)
    #pragma unroll
    for (int p = 0; p < 4; p++) {
        int idx = tid + p * 128;
        int row = idx >> 3, ch = idx & 7;
        uint32_t dst = (row * 64 + ((ch ^ (row & 7)) << 3)) * 2;   // bytes
        cp16(sb + dst, qg + (size_t)row * DD + ch * 8);
        cp16(Kb + dst, kg + (size_t)row * DD + ch * 8);
        cp16(Vb + dst, vg + (size_t)row * DD + ch * 8);
    }
    asm volatile("cp.async.commit_group;\n");
    asm volatile("cp.async.wait_group 0;\n");
    __syncthreads();

    // Q fragments (register-resident for whole kernel)
    uint32_t qf[4][4];
    {
        const int rowQ = warp * 16 + (g8 & 1) * 8 + i7;
        #pragma unroll
        for (int s4 = 0; s4 < 4; s4++) {
            uint32_t addr = sb + (rowQ * 64 + (((2 * s4 + (g8 >> 1)) ^ (rowQ & 7)) << 3)) * 2;
            ldsm_x4(qf[s4], addr);
        }
    }

    float oacc[8][4];
    #pragma unroll
    for (int nt = 0; nt < 8; nt++)
        #pragma unroll
        for (int u = 0; u < 4; u++) oacc[nt][u] = 0.f;

    float m0 = -INFINITY, m1 = -INFINITY, l0 = 0.f, l1 = 0.f;
    const int r0 = qt * 64 + warp * 16 + gid;
    const int r1 = r0 + 8;
    // P tile: u32 shared addr for ldmatrix reads, GENERIC pointer for stores
    const uint32_t Pw = sb + 24576 + warp * 2048;           // bytes (asm reads)
    char* Pg = (char*)sm + 24576 + warp * 2048;             // generic (C++ stores)

    for (int kt = 0; kt <= qt; kt++) {
        if (kt > 0) {
            __syncthreads();   // prior K/V reads complete
            #pragma unroll
            for (int p = 0; p < 4; p++) {
                int idx = tid + p * 128;
                int row = idx >> 3, ch = idx & 7;
                uint32_t dst = (row * 64 + ((ch ^ (row & 7)) << 3)) * 2;
                const size_t gro = (size_t)(kt * 64 + row) * DD + ch * 8;
                cp16(Kb + dst, kg + gro);
                cp16(Vb + dst, vg + gro);
            }
            asm volatile("cp.async.commit_group;\n");
            asm volatile("cp.async.wait_group 0;\n");
            __syncthreads();
        }

        // ---- S = Q @ K^T ----
        float s[8][4];
        #pragma unroll
        for (int nt = 0; nt < 8; nt++)
            s[nt][0] = s[nt][1] = s[nt][2] = s[nt][3] = 0.f;
        #pragma unroll
        for (int s4 = 0; s4 < 4; s4++) {
            #pragma unroll
            for (int ntb = 0; ntb < 4; ntb++) {
                const int rowK = ntb * 16 + (g8 >> 1) * 8 + i7;
                uint32_t addr = Kb + (rowK * 64 +
                                (((2 * s4 + (g8 & 1)) ^ (rowK & 7)) << 3)) * 2;
                uint32_t bf[4];
                ldsm_x4(bf, addr);
                mma_f16(s[2 * ntb],     qf[s4], bf[0], bf[1]);
                mma_f16(s[2 * ntb + 1], qf[s4], bf[2], bf[3]);
            }
        }

        // causal mask on diagonal tile
        if (kt == qt) {
            #pragma unroll
            for (int nt = 0; nt < 8; nt++) {
                int cc = kt * 64 + nt * 8 + 2 * tig;
                if (cc     > r0) s[nt][0] = -INFINITY;
                if (cc + 1 > r0) s[nt][1] = -INFINITY;
                if (cc     > r1) s[nt][2] = -INFINITY;
                if (cc + 1 > r1) s[nt][3] = -INFINITY;
            }
        }

        // ---- online softmax ----
        float mt0 = -INFINITY, mt1 = -INFINITY;
        #pragma unroll
        for (int nt = 0; nt < 8; nt++) {
            mt0 = fmaxf(mt0, fmaxf(s[nt][0], s[nt][1]));
            mt1 = fmaxf(mt1, fmaxf(s[nt][2], s[nt][3]));
        }
        mt0 = fmaxf(mt0, __shfl_xor_sync(0xFFFFFFFFu, mt0, 1));
        mt0 = fmaxf(mt0, __shfl_xor_sync(0xFFFFFFFFu, mt0, 2));
        mt1 = fmaxf(mt1, __shfl_xor_sync(0xFFFFFFFFu, mt1, 1));
        mt1 = fmaxf(mt1, __shfl_xor_sync(0xFFFFFFFFu, mt1, 2));
        const float mn0 = fmaxf(m0, mt0), mn1 = fmaxf(m1, mt1);
        const float a0 = __expf(m0 - mn0), a1 = __expf(m1 - mn1);

        float ls0 = 0.f, ls1 = 0.f;
        #pragma unroll
        for (int nt = 0; nt < 8; nt++) {
            float p0 = __expf(s[nt][0] - mn0);
            float p1 = __expf(s[nt][1] - mn0);
            float p2 = __expf(s[nt][2] - mn1);
            float p3 = __expf(s[nt][3] - mn1);
            ls0 += p0 + p1; ls1 += p2 + p3;
            const int rA = gid, rB = gid + 8;
            *(__half2*)(Pg + (rA * 64 + ((nt ^ (rA & 7)) << 3) + 2 * tig) * 2) =
                __floats2half2_rn(p0, p1);
            *(__half2*)(Pg + (rB * 64 + ((nt ^ (rB & 7)) << 3) + 2 * tig) * 2) =
                __floats2half2_rn(p2, p3);
        }
        ls0 += __shfl_xor_sync(0xFFFFFFFFu, ls0, 1);
        ls0 += __shfl_xor_sync(0xFFFFFFFFu, ls0, 2);
        ls1 += __shfl_xor_sync(0xFFFFFFFFu, ls1, 1);
        ls1 += __shfl_xor_sync(0xFFFFFFFFu, ls1, 2);
        l0 = l0 * a0 + ls0;
        l1 = l1 * a1 + ls1;
        m0 = mn0; m1 = mn1;

        #pragma unroll
        for (int nt = 0; nt < 8; nt++) {
            oacc[nt][0] *= a0; oacc[nt][1] *= a0;
            oacc[nt][2] *= a1; oacc[nt][3] *= a1;
        }
        __syncwarp();

        // ---- O += P @ V ----
        #pragma unroll
        for (int s4 = 0; s4 < 4; s4++) {
            uint32_t pf[4];
            const int rowP = (g8 & 1) * 8 + i7;
            ldsm_x4(pf, Pw + (rowP * 64 + (((2 * s4 + (g8 >> 1)) ^ (rowP & 7)) << 3)) * 2);
            const int rowV = s4 * 16 + (g8 & 1) * 8 + i7;
            #pragma unroll
            for (int db = 0; db < 4; db++) {
                uint32_t bf[4];
                uint32_t addr = Vb + (rowV * 64 +
                                (((2 * db + (g8 >> 1)) ^ (rowV & 7)) << 3)) * 2;
                ldsm_x4_t(bf, addr);
                mma_f16(oacc[2 * db],     pf, bf[0], bf[1]);
                mma_f16(oacc[2 * db + 1], pf, bf[2], bf[3]);
            }
        }
    }

    // write O as fp16
    const float li0 = 1.0f / l0, li1 = 1.0f / l1;
    __half* og = o + base;
    #pragma unroll
    for (int nt = 0; nt < 8; nt++) {
        const int col = nt * 8 + 2 * tig;
        *(__half2*)(og + (size_t)r0 * DD + col) =
            __floats2half2_rn(oacc[nt][0] * li0, oacc[nt][1] * li0);
        *(__half2*)(og + (size_t)r1 * DD + col) =
            __floats2half2_rn(oacc[nt][2] * li1, oacc[nt][3] * li1);
    }
}

// ---------------- launch ----------------
extern "C" void kernel_launch(void* const* d_in, const int* in_sizes, int n_in,
                              void* d_out, int out_size) {
    const float* x     = (const float*)d_in[0];
    const float* Wq    = (const float*)d_in[2];
    const float* Wk    = (const float*)d_in[3];
    const float* Wv    = (const float*)d_in[4];
    const float* Wo    = (const float*)d_in[5];
    const float* bo    = (const float*)d_in[6];
    const float* W1    = (const float*)d_in[7];
    const float* b1    = (const float*)d_in[8];
    const float* W2    = (const float*)d_in[9];
    const float* b2    = (const float*)d_in[10];
    const float* gattn = (const float*)d_in[11];
    const float* gff   = (const float*)d_in[12];
    float* out = (float*)d_out;

    __half *xa, *q, *k, *v, *at, *hb, *wh;
    float *x1;
    cudaGetSymbolAddress((void**)&xa, g_xa);
    cudaGetSymbolAddress((void**)&q,  g_q);
    cudaGetSymbolAddress((void**)&k,  g_k);
    cudaGetSymbolAddress((void**)&v,  g_v);
    cudaGetSymbolAddress((void**)&at, g_at);
    cudaGetSymbolAddress((void**)&x1, g_x1);
    cudaGetSymbolAddress((void**)&hb, g_h);
    cudaGetSymbolAddress((void**)&wh, g_wh);

    __half* Wq_t = wh;
    __half* Wk_t = wh + (size_t)1*1024*1024;
    __half* Wv_t = wh + (size_t)2*1024*1024;
    __half* Wo_t = wh + (size_t)3*1024*1024;
    __half* W1_t = wh + (size_t)4*1024*1024;
    __half* W2_t = wh + (size_t)8*1024*1024;

    cudaFuncSetAttribute(gemm_f16<1>, cudaFuncAttributeMaxDynamicSharedMemorySize, GEMM_SMEM);
    cudaFuncSetAttribute(gemm_f16<2>, cudaFuncAttributeMaxDynamicSharedMemorySize, GEMM_SMEM);
    cudaFuncSetAttribute(gemm_f16<3>, cudaFuncAttributeMaxDynamicSharedMemorySize, GEMM_SMEM);

    // 0. transpose + fp16-round weights
    {
        dim3 blk(32, 8);
        transpose_half<<<dim3(DD/32, DD/32), blk>>>(Wq, Wq_t, DD, DD);
        transpose_half<<<dim3(DD/32, DD/32), blk>>>(Wk, Wk_t, DD, DD);
        transpose_half<<<dim3(DD/32, DD/32), blk>>>(Wv, Wv_t, DD, DD);
        transpose_half<<<dim3(DD/32, DD/32), blk>>>(Wo, Wo_t, DD, DD);
        transpose_half<<<dim3(FF/32, DD/32), blk>>>(W1, W1_t, DD, FF);
        transpose_half<<<dim3(DD/32, FF/32), blk>>>(W2, W2_t, FF, DD);
    }

    // 1. rmsnorm(x, g_attn) -> xa (fp16)
    rmsnorm_kernel<<<ROWS, 256>>>(x, gattn, xa);

    // 2. QKV projections (fp16 out; Q pre-scaled by 0.125)
    {
        dim3 grid(DD / 128, ROWS / 128, 3);
        gemm_f16<3><<<grid, 256, GEMM_SMEM>>>(xa, Wq_t, Wk_t, Wv_t,
                                              q, k, v, nullptr, nullptr, DD, DD);
    }

    // 3. causal attention (fp16 MMA) -> at (fp16)
    {
        dim3 grid(TT / 64, HH, BB);
        attn_f16<<<grid, 128>>>(q, k, v, at);
    }

    // 4. x1 = x + at @ Wo + bo
    {
        dim3 grid(DD / 128, ROWS / 128, 1);
        gemm_f16<1><<<grid, 256, GEMM_SMEM>>>(at, Wo_t, Wo_t, Wo_t,
                                              x1, x1, x1, bo, x, DD, DD);
    }

    // 5. rmsnorm(x1, g_ff) -> xa (fp16)
    rmsnorm_kernel<<<ROWS, 256>>>(x1, gff, xa);

    // 6. h = silu(xa @ W1 + b1) -> hb (fp16)
    {
        dim3 grid(FF / 128, ROWS / 128, 1);
        gemm_f16<2><<<grid, 256, GEMM_SMEM>>>(xa, W1_t, W1_t, W1_t,
                                              hb, hb, hb, b1, nullptr, FF, DD);
    }

    // 7. out = x1 + hb @ W2 + b2
    {
        dim3 grid(DD / 128, ROWS / 128, 1);
        gemm_f16<1><<<grid, 256, GEMM_SMEM>>>(hb, W2_t, W2_t, W2_t,
                                              out, out, out, b2, x1, DD, FF);
    }
}

// round 10
// speedup vs baseline: 11.0095x; 1.0269x over previous
#include <cuda_runtime.h>
#include <cuda_fp16.h>
#include <cstdint>

// ---------------- problem constants ----------------
#define BB   2
#define TT   2048
#define DD   1024
#define HH   16
#define HDIM 64
#define FF   4096
#define ROWS (BB*TT)          // 4096

// ---------------- scratch (device globals) ----------------
__device__ __half g_xa [ROWS*DD];            // rmsnorm out (fp16)
__device__ __half g_q  [ROWS*DD];            // Q (pre-scaled by 0.125, fp16)
__device__ __half g_k  [ROWS*DD];
__device__ __half g_v  [ROWS*DD];
__device__ __half g_at [ROWS*DD];            // attention out (fp16)
__device__ float  g_x1 [ROWS*DD];
__device__ __half g_h  [(size_t)ROWS*FF];    // silu out (fp16)
__device__ __half g_wh [(size_t)12*1024*1024]; // fp16 weights, ORIGINAL [K,N] layout

// ---------------- helpers ----------------
__device__ __forceinline__ uint32_t smem_u32(const void* p) {
    return (uint32_t)__cvta_generic_to_shared(p);
}
__device__ __forceinline__ void mma_f16(float* c, const uint32_t* a,
                                        uint32_t b0, uint32_t b1) {
    asm volatile(
        "mma.sync.aligned.m16n8k16.row.col.f32.f16.f16.f32 "
        "{%0,%1,%2,%3},{%4,%5,%6,%7},{%8,%9},{%0,%1,%2,%3};\n"
        : "+f"(c[0]), "+f"(c[1]), "+f"(c[2]), "+f"(c[3])
        : "r"(a[0]), "r"(a[1]), "r"(a[2]), "r"(a[3]), "r"(b0), "r"(b1));
}
__device__ __forceinline__ void ldsm_x4(uint32_t* r, uint32_t saddr) {
    asm volatile("ldmatrix.sync.aligned.m8n8.x4.shared.b16 {%0,%1,%2,%3}, [%4];"
                 : "=r"(r[0]), "=r"(r[1]), "=r"(r[2]), "=r"(r[3]) : "r"(saddr));
}
__device__ __forceinline__ void ldsm_x4_t(uint32_t* r, uint32_t saddr) {
    asm volatile("ldmatrix.sync.aligned.m8n8.x4.trans.shared.b16 {%0,%1,%2,%3}, [%4];"
                 : "=r"(r[0]), "=r"(r[1]), "=r"(r[2]), "=r"(r[3]) : "r"(saddr));
}
__device__ __forceinline__ void cp16(uint32_t saddr, const void* g) {
    asm volatile("cp.async.cg.shared.global [%0], [%1], 16;\n" :: "r"(saddr), "l"(g));
}

// ---------------- weight convert fp32 -> fp16 (streaming, layout kept) --------
__global__ __launch_bounds__(256)
void convert_half(const float4* __restrict__ in, uint4* __restrict__ out, int n8) {
    int i = blockIdx.x * 256 + threadIdx.x;
    if (i < n8) {
        float4 a = in[2 * i], b = in[2 * i + 1];
        __half2 h0 = __floats2half2_rn(a.x, a.y);
        __half2 h1 = __floats2half2_rn(a.z, a.w);
        __half2 h2 = __floats2half2_rn(b.x, b.y);
        __half2 h3 = __floats2half2_rn(b.z, b.w);
        uint4 o;
        o.x = *(uint32_t*)&h0; o.y = *(uint32_t*)&h1;
        o.z = *(uint32_t*)&h2; o.w = *(uint32_t*)&h3;
        out[i] = o;
    }
}

// ---------------- rmsnorm (fp16 output) ----------------
__global__ __launch_bounds__(256)
void rmsnorm_kernel(const float* __restrict__ x, const float* __restrict__ g,
                    __half* __restrict__ out) {
    __shared__ float red[256];
    const int row = blockIdx.x;
    const int tid = threadIdx.x;
    const float4 v = ((const float4*)(x + (size_t)row * DD))[tid];
    float ss = v.x*v.x + v.y*v.y + v.z*v.z + v.w*v.w;
    red[tid] = ss;
    __syncthreads();
    #pragma unroll
    for (int s = 128; s > 0; s >>= 1) {
        if (tid < s) red[tid] += red[tid + s];
        __syncthreads();
    }
    const float norm = rsqrtf(red[0] * (1.0f / DD) + 1e-5f);
    const float4 gv = ((const float4*)g)[tid];
    __half2 h01 = __floats2half2_rn(v.x * norm * gv.x, v.y * norm * gv.y);
    __half2 h23 = __floats2half2_rn(v.z * norm * gv.z, v.w * norm * gv.w);
    uint2 pk; pk.x = *(uint32_t*)&h01; pk.y = *(uint32_t*)&h23;
    ((uint2*)(out + (size_t)row * DD))[tid] = pk;
}

// ---------------- fp16 tensor-core GEMM, 3-stage cp.async pipeline ----------
// C[M,N] = A[M,K] @ W[K,N].  A smem [128 m][64 k] (128B rows, XOR-8 swizzle).
// B smem [64 k][128 n] (256B rows, (c&8)|((c^r)&7) swizzle), frags via ldsm.trans.
// EPI 0: float out; 1: float = acc+bias+res; 2: half = silu(acc+bias);
// EPI 3: half = acc * (z==0 ? 0.125 : 1)   [QKV path, Q pre-scaled]
#define SGS3 3
#define STG_BYTES 32768
#define GEMM_SMEM (SGS3 * STG_BYTES)

template <int EPI>
__global__ __launch_bounds__(256, 2)
void gemm_f16(const __half* __restrict__ A,
              const __half* __restrict__ B0, const __half* __restrict__ B1,
              const __half* __restrict__ B2,
              void* C0v, void* C1v, void* C2v,
              const float* __restrict__ bias, const float* __restrict__ res,
              int N, int K) {
    extern __shared__ __align__(16) char dynsm[];
    const uint32_t sb = smem_u32(dynsm);

    const __half* Bw = (blockIdx.z == 0) ? B0 : (blockIdx.z == 1 ? B1 : B2);
    void* Cv = (blockIdx.z == 0) ? C0v : (blockIdx.z == 1 ? C1v : C2v);

    const int tid   = threadIdx.x;
    const int lane  = tid & 31;
    const int warp  = tid >> 5;
    const int warpM = warp & 1;
    const int warpN = warp >> 1;
    const int g8    = lane >> 3;
    const int i7    = lane & 7;

    const int bm = blockIdx.y, bn = blockIdx.x;
    const __half* Aq = A  + (size_t)bm * 128 * K;
    const __half* Bq = Bw + bn * 128;                 // column offset into [K,N]

    const int aRow = warpM * 64 + (g8 & 1) * 8 + i7;
    const int aHi  = g8 >> 1;

    // cp.async indices: A 4 chunks (128 rows x 8 chunks), B 4 chunks (64 rows x 16 chunks)
    int arow[4], ach[4], asw[4], brow[4], bch[4], bsw[4];
    #pragma unroll
    for (int p = 0; p < 4; p++) {
        int idx = tid + p * 256;
        arow[p] = idx >> 3;  ach[p] = idx & 7;
        asw[p]  = ach[p] ^ (arow[p] & 7);
        brow[p] = idx >> 4;  bch[p] = idx & 15;
        bsw[p]  = (bch[p] & 8) | ((bch[p] ^ brow[p]) & 7);
    }

#define ISSUE_STAGE(st, kb)                                                    \
    {                                                                          \
        uint32_t Ab = sb + (st) * STG_BYTES;                                   \
        uint32_t Bb = Ab + 16384;                                              \
        _Pragma("unroll")                                                      \
        for (int p = 0; p < 4; p++) {                                          \
            cp16(Ab + arow[p] * 128 + asw[p] * 16,                             \
                 Aq + (size_t)arow[p] * K + (kb) + ach[p] * 8);                \
            cp16(Bb + brow[p] * 256 + bsw[p] * 16,                             \
                 Bq + (size_t)((kb) + brow[p]) * N + bch[p] * 8);              \
        }                                                                      \
        asm volatile("cp.async.commit_group;\n");                              \
    }

    float c[4][4][4];
    #pragma unroll
    for (int mi = 0; mi < 4; mi++)
        #pragma unroll
        for (int ni = 0; ni < 4; ni++)
            #pragma unroll
            for (int u = 0; u < 4; u++) c[mi][ni][u] = 0.f;

    const int ktiles = K >> 6;

    ISSUE_STAGE(0, 0);
    ISSUE_STAGE(1, 64);

    for (int u = 0; u < ktiles; u++) {
        asm volatile("cp.async.wait_group 1;\n");
        __syncthreads();

        if (u + 2 < ktiles) {
            const int stn = (u + 2) % SGS3;
            ISSUE_STAGE(stn, (u + 2) * 64);
        } else {
            asm volatile("cp.async.commit_group;\n");
        }

        const int st = u % SGS3;
        const uint32_t Ab = sb + st * STG_BYTES;
        const uint32_t Bb = Ab + 16384;

        #pragma unroll
        for (int s = 0; s < 4; s++) {
            uint32_t af[4][4], bf[2][4];
            const int ac = ((2 * s + aHi) ^ i7) << 4;
            #pragma unroll
            for (int mi = 0; mi < 4; mi++)
                ldsm_x4(af[mi], Ab + (aRow + mi * 16) * 128 + ac);
            const int rowB = s * 16 + (g8 & 1) * 8 + i7;
            #pragma unroll
            for (int db = 0; db < 2; db++) {
                const int nc = warpN * 4 + 2 * db + (g8 >> 1);
                uint32_t addr = Bb + rowB * 256 +
                                (((nc & 8) | ((nc ^ rowB) & 7)) << 4);
                ldsm_x4_t(bf[db], addr);
            }
            #pragma unroll
            for (int mi = 0; mi < 4; mi++)
                #pragma unroll
                for (int ni = 0; ni < 4; ni++)
                    mma_f16(c[mi][ni], af[mi],
                            bf[ni >> 1][(ni & 1) * 2], bf[ni >> 1][(ni & 1) * 2 + 1]);
        }
    }
#undef ISSUE_STAGE

    const int gid = lane >> 2, tig = lane & 3;
    #pragma unroll
    for (int mi = 0; mi < 4; mi++) {
        const int r0 = bm * 128 + warpM * 64 + mi * 16 + gid;
        const int r1 = r0 + 8;
        #pragma unroll
        for (int ni = 0; ni < 4; ni++) {
            const int col = bn * 128 + warpN * 32 + ni * 8 + 2 * tig;
            float v0 = c[mi][ni][0], v1 = c[mi][ni][1];
            float v2 = c[mi][ni][2], v3 = c[mi][ni][3];
            if (EPI == 0) {
                float* C = (float*)Cv;
                float2 o0; o0.x = v0; o0.y = v1;
                float2 o1; o1.x = v2; o1.y = v3;
                *(float2*)(C + (size_t)r0 * N + col) = o0;
                *(float2*)(C + (size_t)r1 * N + col) = o1;
            } else if (EPI == 1) {
                float* C = (float*)Cv;
                const float b0 = bias[col], b1 = bias[col + 1];
                const float2 rA = *(const float2*)(res + (size_t)r0 * N + col);
                const float2 rB = *(const float2*)(res + (size_t)r1 * N + col);
                float2 o0; o0.x = v0 + b0 + rA.x; o0.y = v1 + b1 + rA.y;
                float2 o1; o1.x = v2 + b0 + rB.x; o1.y = v3 + b1 + rB.y;
                *(float2*)(C + (size_t)r0 * N + col) = o0;
                *(float2*)(C + (size_t)r1 * N + col) = o1;
            } else if (EPI == 2) {
                __half* C = (__half*)Cv;
                const float b0 = bias[col], b1 = bias[col + 1];
                v0 += b0; v1 += b1; v2 += b0; v3 += b1;
                v0 = v0 / (1.0f + __expf(-v0));
                v1 = v1 / (1.0f + __expf(-v1));
                v2 = v2 / (1.0f + __expf(-v2));
                v3 = v3 / (1.0f + __expf(-v3));
                *(__half2*)(C + (size_t)r0 * N + col) = __floats2half2_rn(v0, v1);
                *(__half2*)(C + (size_t)r1 * N + col) = __floats2half2_rn(v2, v3);
            } else {
                __half* C = (__half*)Cv;
                const float sc = (blockIdx.z == 0) ? 0.125f : 1.0f;
                *(__half2*)(C + (size_t)r0 * N + col) = __floats2half2_rn(v0*sc, v1*sc);
                *(__half2*)(C + (size_t)r1 * N + col) = __floats2half2_rn(v2*sc, v3*sc);
            }
        }
    }
}

// ---------------- fp16 tensor-core flash attention (causal, dbl-buffered KV) ---
// BYTE layout: Q [0,8K), K0 [8K,16K), K1 [16K,24K), V0 [24K,32K), V1 [32K,40K),
//              P [40K,48K)
__global__ __launch_bounds__(128)
void attn_f16(const __half* __restrict__ q, const __half* __restrict__ k,
              const __half* __restrict__ v, __half* __restrict__ o) {
    __shared__ __align__(16) __half sm[24576];
    const uint32_t sb = smem_u32(sm);
    const uint32_t Kb[2] = { sb + 8192,  sb + 16384 };
    const uint32_t Vb[2] = { sb + 24576, sb + 32768 };

    const int tid  = threadIdx.x;
    const int lane = tid & 31;
    const int warp = tid >> 5;
    const int g8   = lane >> 3;
    const int i7   = lane & 7;
    const int gid  = lane >> 2;
    const int tig  = lane & 3;
    const int qt = blockIdx.x, h = blockIdx.y, b = blockIdx.z;
    const size_t base = ((size_t)b * TT) * DD + (size_t)h * HDIM;

    const __half* qg = q + base + (size_t)qt * 64 * DD;
    const __half* kg = k + base;
    const __half* vg = v + base;

    // prologue: Q + K/V tile 0 in one group
    #pragma unroll
    for (int p = 0; p < 4; p++) {
        int idx = tid + p * 128;
        int row = idx >> 3, ch = idx & 7;
        uint32_t dst = (row * 64 + ((ch ^ (row & 7)) << 3)) * 2;   // bytes
        cp16(sb + dst,    qg + (size_t)row * DD + ch * 8);
        cp16(Kb[0] + dst, kg + (size_t)row * DD + ch * 8);
        cp16(Vb[0] + dst, vg + (size_t)row * DD + ch * 8);
    }
    asm volatile("cp.async.commit_group;\n");

    uint32_t qf[4][4];
    float oacc[8][4];
    #pragma unroll
    for (int nt = 0; nt < 8; nt++)
        #pragma unroll
        for (int u = 0; u < 4; u++) oacc[nt][u] = 0.f;

    float m0 = -INFINITY, m1 = -INFINITY, l0 = 0.f, l1 = 0.f;
    const int r0 = qt * 64 + warp * 16 + gid;
    const int r1 = r0 + 8;
    const uint32_t Pw = sb + 40960 + warp * 2048;           // asm reads
    char* Pg = (char*)sm + 40960 + warp * 2048;             // C++ stores

    for (int kt = 0; kt <= qt; kt++) {
        const int cur = kt & 1;
        if (kt < qt) {
            const int nxt = (kt + 1) & 1;
            #pragma unroll
            for (int p = 0; p < 4; p++) {
                int idx = tid + p * 128;
                int row = idx >> 3, ch = idx & 7;
                uint32_t dst = (row * 64 + ((ch ^ (row & 7)) << 3)) * 2;
                const size_t gro = (size_t)((kt + 1) * 64 + row) * DD + ch * 8;
                cp16(Kb[nxt] + dst, kg + gro);
                cp16(Vb[nxt] + dst, vg + gro);
            }
            asm volatile("cp.async.commit_group;\n");
            asm volatile("cp.async.wait_group 1;\n");
        } else {
            asm volatile("cp.async.wait_group 0;\n");
        }
        __syncthreads();

        if (kt == 0) {
            const int rowQ = warp * 16 + (g8 & 1) * 8 + i7;
            #pragma unroll
            for (int s4 = 0; s4 < 4; s4++) {
                uint32_t addr = sb +
                    (rowQ * 64 + (((2 * s4 + (g8 >> 1)) ^ (rowQ & 7)) << 3)) * 2;
                ldsm_x4(qf[s4], addr);
            }
        }

        // ---- S = Q @ K^T ----
        float s[8][4];
        #pragma unroll
        for (int nt = 0; nt < 8; nt++)
            s[nt][0] = s[nt][1] = s[nt][2] = s[nt][3] = 0.f;
        #pragma unroll
        for (int s4 = 0; s4 < 4; s4++) {
            #pragma unroll
            for (int ntb = 0; ntb < 4; ntb++) {
                const int rowK = ntb * 16 + (g8 >> 1) * 8 + i7;
                uint32_t addr = Kb[cur] + (rowK * 64 +
                                (((2 * s4 + (g8 & 1)) ^ (rowK & 7)) << 3)) * 2;
                uint32_t bf[4];
                ldsm_x4(bf, addr);
                mma_f16(s[2 * ntb],     qf[s4], bf[0], bf[1]);
                mma_f16(s[2 * ntb + 1], qf[s4], bf[2], bf[3]);
            }
        }

        if (kt == qt) {
            #pragma unroll
            for (int nt = 0; nt < 8; nt++) {
                int cc = kt * 64 + nt * 8 + 2 * tig;
                if (cc     > r0) s[nt][0] = -INFINITY;
                if (cc + 1 > r0) s[nt][1] = -INFINITY;
                if (cc     > r1) s[nt][2] = -INFINITY;
                if (cc + 1 > r1) s[nt][3] = -INFINITY;
            }
        }

        // ---- online softmax ----
        float mt0 = -INFINITY, mt1 = -INFINITY;
        #pragma unroll
        for (int nt = 0; nt < 8; nt++) {
            mt0 = fmaxf(mt0, fmaxf(s[nt][0], s[nt][1]));
            mt1 = fmaxf(mt1, fmaxf(s[nt][2], s[nt][3]));
        }
        mt0 = fmaxf(mt0, __shfl_xor_sync(0xFFFFFFFFu, mt0, 1));
        mt0 = fmaxf(mt0, __shfl_xor_sync(0xFFFFFFFFu, mt0, 2));
        mt1 = fmaxf(mt1, __shfl_xor_sync(0xFFFFFFFFu, mt1, 1));
        mt1 = fmaxf(mt1, __shfl_xor_sync(0xFFFFFFFFu, mt1, 2));
        const float mn0 = fmaxf(m0, mt0), mn1 = fmaxf(m1, mt1);
        const float a0 = __expf(m0 - mn0), a1 = __expf(m1 - mn1);

        float ls0 = 0.f, ls1 = 0.f;
        #pragma unroll
        for (int nt = 0; nt < 8; nt++) {
            float p0 = __expf(s[nt][0] - mn0);
            float p1 = __expf(s[nt][1] - mn0);
            float p2 = __expf(s[nt][2] - mn1);
            float p3 = __expf(s[nt][3] - mn1);
            ls0 += p0 + p1; ls1 += p2 + p3;
            const int rA = gid, rB = gid + 8;
            *(__half2*)(Pg + (rA * 64 + ((nt ^ (rA & 7)) << 3) + 2 * tig) * 2) =
                __floats2half2_rn(p0, p1);
            *(__half2*)(Pg + (rB * 64 + ((nt ^ (rB & 7)) << 3) + 2 * tig) * 2) =
                __floats2half2_rn(p2, p3);
        }
        ls0 += __shfl_xor_sync(0xFFFFFFFFu, ls0, 1);
        ls0 += __shfl_xor_sync(0xFFFFFFFFu, ls0, 2);
        ls1 += __shfl_xor_sync(0xFFFFFFFFu, ls1, 1);
        ls1 += __shfl_xor_sync(0xFFFFFFFFu, ls1, 2);
        l0 = l0 * a0 + ls0;
        l1 = l1 * a1 + ls1;
        m0 = mn0; m1 = mn1;

        #pragma unroll
        for (int nt = 0; nt < 8; nt++) {
            oacc[nt][0] *= a0; oacc[nt][1] *= a0;
            oacc[nt][2] *= a1; oacc[nt][3] *= a1;
        }
        __syncwarp();

        // ---- O += P @ V ----
        #pragma unroll
        for (int s4 = 0; s4 < 4; s4++) {
            uint32_t pf[4];
            const int rowP = (g8 & 1) * 8 + i7;
            ldsm_x4(pf, Pw + (rowP * 64 + (((2 * s4 + (g8 >> 1)) ^ (rowP & 7)) << 3)) * 2);
            const int rowV = s4 * 16 + (g8 & 1) * 8 + i7;
            #pragma unroll
            for (int db = 0; db < 4; db++) {
                uint32_t bf[4];
                uint32_t addr = Vb[cur] + (rowV * 64 +
                                (((2 * db + (g8 >> 1)) ^ (rowV & 7)) << 3)) * 2;
                ldsm_x4_t(bf, addr);
                mma_f16(oacc[2 * db],     pf, bf[0], bf[1]);
                mma_f16(oacc[2 * db + 1], pf, bf[2], bf[3]);
            }
        }
        __syncthreads();   // protect buffer reuse by next prefetch
    }

    // write O as fp16
    const float li0 = 1.0f / l0, li1 = 1.0f / l1;
    __half* og = o + base;
    #pragma unroll
    for (int nt = 0; nt < 8; nt++) {
        const int col = nt * 8 + 2 * tig;
        *(__half2*)(og + (size_t)r0 * DD + col) =
            __floats2half2_rn(oacc[nt][0] * li0, oacc[nt][1] * li0);
        *(__half2*)(og + (size_t)r1 * DD + col) =
            __floats2half2_rn(oacc[nt][2] * li1, oacc[nt][3] * li1);
    }
}

// ---------------- launch ----------------
extern "C" void kernel_launch(void* const* d_in, const int* in_sizes, int n_in,
                              void* d_out, int out_size) {
    const float* x     = (const float*)d_in[0];
    const float* Wq    = (const float*)d_in[2];
    const float* Wk    = (const float*)d_in[3];
    const float* Wv    = (const float*)d_in[4];
    const float* Wo    = (const float*)d_in[5];
    const float* bo    = (const float*)d_in[6];
    const float* W1    = (const float*)d_in[7];
    const float* b1    = (const float*)d_in[8];
    const float* W2    = (const float*)d_in[9];
    const float* b2    = (const float*)d_in[10];
    const float* gattn = (const float*)d_in[11];
    const float* gff   = (const float*)d_in[12];
    float* out = (float*)d_out;

    __half *xa, *q, *k, *v, *at, *hb, *wh;
    float *x1;
    cudaGetSymbolAddress((void**)&xa, g_xa);
    cudaGetSymbolAddress((void**)&q,  g_q);
    cudaGetSymbolAddress((void**)&k,  g_k);
    cudaGetSymbolAddress((void**)&v,  g_v);
    cudaGetSymbolAddress((void**)&at, g_at);
    cudaGetSymbolAddress((void**)&x1, g_x1);
    cudaGetSymbolAddress((void**)&hb, g_h);
    cudaGetSymbolAddress((void**)&wh, g_wh);

    __half* Wq_h = wh;                               // [K,N] fp16 copies
    __half* Wk_h = wh + (size_t)1*1024*1024;
    __half* Wv_h = wh + (size_t)2*1024*1024;
    __half* Wo_h = wh + (size_t)3*1024*1024;
    __half* W1_h = wh + (size_t)4*1024*1024;
    __half* W2_h = wh + (size_t)8*1024*1024;

    cudaFuncSetAttribute(gemm_f16<1>, cudaFuncAttributeMaxDynamicSharedMemorySize, GEMM_SMEM);
    cudaFuncSetAttribute(gemm_f16<2>, cudaFuncAttributeMaxDynamicSharedMemorySize, GEMM_SMEM);
    cudaFuncSetAttribute(gemm_f16<3>, cudaFuncAttributeMaxDynamicSharedMemorySize, GEMM_SMEM);

    // 0. fp32 -> fp16 weight convert (layout preserved, pure streaming)
    {
        const int nDD8 = DD * DD / 8, nDF8 = DD * FF / 8;
        convert_half<<<(nDD8 + 255)/256, 256>>>((const float4*)Wq, (uint4*)Wq_h, nDD8);
        convert_half<<<(nDD8 + 255)/256, 256>>>((const float4*)Wk, (uint4*)Wk_h, nDD8);
        convert_half<<<(nDD8 + 255)/256, 256>>>((const float4*)Wv, (uint4*)Wv_h, nDD8);
        convert_half<<<(nDD8 + 255)/256, 256>>>((const float4*)Wo, (uint4*)Wo_h, nDD8);
        convert_half<<<(nDF8 + 255)/256, 256>>>((const float4*)W1, (uint4*)W1_h, nDF8);
        convert_half<<<(nDF8 + 255)/256, 256>>>((const float4*)W2, (uint4*)W2_h, nDF8);
    }

    // 1. rmsnorm(x, g_attn) -> xa (fp16)
    rmsnorm_kernel<<<ROWS, 256>>>(x, gattn, xa);

    // 2. QKV projections (fp16 out; Q pre-scaled by 0.125)
    {
        dim3 grid(DD / 128, ROWS / 128, 3);
        gemm_f16<3><<<grid, 256, GEMM_SMEM>>>(xa, Wq_h, Wk_h, Wv_h,
                                              q, k, v, nullptr, nullptr, DD, DD);
    }

    // 3. causal attention (fp16 MMA) -> at (fp16)
    {
        dim3 grid(TT / 64, HH, BB);
        attn_f16<<<grid, 128>>>(q, k, v, at);
    }

    // 4. x1 = x + at @ Wo + bo
    {
        dim3 grid(DD / 128, ROWS / 128, 1);
        gemm_f16<1><<<grid, 256, GEMM_SMEM>>>(at, Wo_h, Wo_h, Wo_h,
                                              x1, x1, x1, bo, x, DD, DD);
    }

    // 5. rmsnorm(x1, g_ff) -> xa (fp16)
    rmsnorm_kernel<<<ROWS, 256>>>(x1, gff, xa);

    // 6. h = silu(xa @ W1 + b1) -> hb (fp16)
    {
        dim3 grid(FF / 128, ROWS / 128, 1);
        gemm_f16<2><<<grid, 256, GEMM_SMEM>>>(xa, W1_h, W1_h, W1_h,
                                              hb, hb, hb, b1, nullptr, FF, DD);
    }

    // 7. out = x1 + hb @ W2 + b2
    {
        dim3 grid(DD / 128, ROWS / 128, 1);
        gemm_f16<1><<<grid, 256, GEMM_SMEM>>>(hb, W2_h, W2_h, W2_h,
                                              out, out, out, b2, x1, DD, FF);
    }
}

// round 11
// speedup vs baseline: 11.3611x; 1.0319x over previous
#include <cuda_runtime.h>
#include <cuda_fp16.h>
#include <cstdint>

// ---------------- problem constants ----------------
#define BB   2
#define TT   2048
#define DD   1024
#define HH   16
#define HDIM 64
#define FF   4096
#define ROWS (BB*TT)          // 4096

// ---------------- scratch (device globals) ----------------
__device__ __half g_xa [ROWS*DD];            // rmsnorm out (fp16)
__device__ __half g_q  [ROWS*DD];            // Q (pre-scaled by 0.125, fp16)
__device__ __half g_k  [ROWS*DD];
__device__ __half g_v  [ROWS*DD];
__device__ __half g_at [ROWS*DD];            // attention out (fp16)
__device__ float  g_x1 [ROWS*DD];
__device__ __half g_h  [(size_t)ROWS*FF];    // silu out (fp16)
__device__ __half g_wh [(size_t)12*1024*1024]; // fp16 weights, [K,N] layout, packed

// ---------------- helpers ----------------
__device__ __forceinline__ uint32_t smem_u32(const void* p) {
    return (uint32_t)__cvta_generic_to_shared(p);
}
__device__ __forceinline__ void mma_f16(float* c, const uint32_t* a,
                                        uint32_t b0, uint32_t b1) {
    asm volatile(
        "mma.sync.aligned.m16n8k16.row.col.f32.f16.f16.f32 "
        "{%0,%1,%2,%3},{%4,%5,%6,%7},{%8,%9},{%0,%1,%2,%3};\n"
        : "+f"(c[0]), "+f"(c[1]), "+f"(c[2]), "+f"(c[3])
        : "r"(a[0]), "r"(a[1]), "r"(a[2]), "r"(a[3]), "r"(b0), "r"(b1));
}
__device__ __forceinline__ void ldsm_x4(uint32_t* r, uint32_t saddr) {
    asm volatile("ldmatrix.sync.aligned.m8n8.x4.shared.b16 {%0,%1,%2,%3}, [%4];"
                 : "=r"(r[0]), "=r"(r[1]), "=r"(r[2]), "=r"(r[3]) : "r"(saddr));
}
__device__ __forceinline__ void ldsm_x4_t(uint32_t* r, uint32_t saddr) {
    asm volatile("ldmatrix.sync.aligned.m8n8.x4.trans.shared.b16 {%0,%1,%2,%3}, [%4];"
                 : "=r"(r[0]), "=r"(r[1]), "=r"(r[2]), "=r"(r[3]) : "r"(saddr));
}
__device__ __forceinline__ void cp16(uint32_t saddr, const void* g) {
    asm volatile("cp.async.cg.shared.global [%0], [%1], 16;\n" :: "r"(saddr), "l"(g));
}

// ---------------- fused weight convert fp32 -> fp16 (all 6 weights, 1 launch) --
// uint4-output index space (8 halves each):
//   [0, 4*131072)            : Wq/Wk/Wv/Wo  (131072 each)
//   [524288, 1048576)        : W1
//   [1048576, 1572864)       : W2
#define CVT_TOTAL 1572864
__global__ __launch_bounds__(256)
void convert_all(const float4* __restrict__ wq, const float4* __restrict__ wk,
                 const float4* __restrict__ wv, const float4* __restrict__ wo,
                 const float4* __restrict__ w1, const float4* __restrict__ w2,
                 uint4* __restrict__ dst) {
    const int nth = gridDim.x * 256;
    for (int i = blockIdx.x * 256 + threadIdx.x; i < CVT_TOTAL; i += nth) {
        const float4* src;
        int off;
        if (i < 524288) {
            int r = i >> 17;
            src = (r == 0) ? wq : (r == 1) ? wk : (r == 2) ? wv : wo;
            off = i & 131071;
        } else if (i < 1048576) {
            src = w1; off = i - 524288;
        } else {
            src = w2; off = i - 1048576;
        }
        float4 a = src[2 * off], b = src[2 * off + 1];
        __half2 h0 = __floats2half2_rn(a.x, a.y);
        __half2 h1 = __floats2half2_rn(a.z, a.w);
        __half2 h2 = __floats2half2_rn(b.x, b.y);
        __half2 h3 = __floats2half2_rn(b.z, b.w);
        uint4 o;
        o.x = *(uint32_t*)&h0; o.y = *(uint32_t*)&h1;
        o.z = *(uint32_t*)&h2; o.w = *(uint32_t*)&h3;
        dst[i] = o;
    }
}

// ---------------- rmsnorm (fp16 output) ----------------
__global__ __launch_bounds__(256)
void rmsnorm_kernel(const float* __restrict__ x, const float* __restrict__ g,
                    __half* __restrict__ out) {
    __shared__ float red[256];
    const int row = blockIdx.x;
    const int tid = threadIdx.x;
    const float4 v = ((const float4*)(x + (size_t)row * DD))[tid];
    float ss = v.x*v.x + v.y*v.y + v.z*v.z + v.w*v.w;
    red[tid] = ss;
    __syncthreads();
    #pragma unroll
    for (int s = 128; s > 0; s >>= 1) {
        if (tid < s) red[tid] += red[tid + s];
        __syncthreads();
    }
    const float norm = rsqrtf(red[0] * (1.0f / DD) + 1e-5f);
    const float4 gv = ((const float4*)g)[tid];
    __half2 h01 = __floats2half2_rn(v.x * norm * gv.x, v.y * norm * gv.y);
    __half2 h23 = __floats2half2_rn(v.z * norm * gv.z, v.w * norm * gv.w);
    uint2 pk; pk.x = *(uint32_t*)&h01; pk.y = *(uint32_t*)&h23;
    ((uint2*)(out + (size_t)row * DD))[tid] = pk;
}

// ---------------- fp16 tensor-core GEMM, 3-stage cp.async pipeline ----------
// C[M,N] = A[M,K] @ W[K,N]. 128 threads, 2x2 warps, 64x64 warp tile.
// A smem [128 m][64 k] (128B rows, XOR-8). B smem [64 k][128 n] (256B rows,
// (c&8)|((c^r)&7)), frags via ldsm.trans.
// EPI 0: float; 1: float = acc+bias+res; 2: half = silu(acc+bias);
// EPI 3: half = acc * (z==0 ? 0.125 : 1)
#define SGS3 3
#define STG_BYTES 32768
#define GEMM_SMEM (SGS3 * STG_BYTES)

template <int EPI>
__global__ __launch_bounds__(128, 2)
void gemm_f16(const __half* __restrict__ A,
              const __half* __restrict__ B0, const __half* __restrict__ B1,
              const __half* __restrict__ B2,
              void* C0v, void* C1v, void* C2v,
              const float* __restrict__ bias, const float* __restrict__ res,
              int N, int K) {
    extern __shared__ __align__(16) char dynsm[];
    const uint32_t sb = smem_u32(dynsm);

    const __half* Bw = (blockIdx.z == 0) ? B0 : (blockIdx.z == 1 ? B1 : B2);
    void* Cv = (blockIdx.z == 0) ? C0v : (blockIdx.z == 1 ? C1v : C2v);

    const int tid   = threadIdx.x;
    const int lane  = tid & 31;
    const int warp  = tid >> 5;
    const int warpM = warp & 1;
    const int warpN = warp >> 1;
    const int g8    = lane >> 3;
    const int i7    = lane & 7;

    const int bm = blockIdx.y, bn = blockIdx.x;
    const __half* Aq = A  + (size_t)bm * 128 * K;
    const __half* Bq = Bw + bn * 128;                 // column offset into [K,N]

    const int aRow = warpM * 64 + (g8 & 1) * 8 + i7;
    const int aHi  = g8 >> 1;

    // affine cp.async bases (swizzle terms are p-invariant)
    const int arow0 = tid >> 3, ach = tid & 7;
    const int brow0 = tid >> 4, bch = tid & 15;
    const uint32_t AdOff = arow0 * 128 + ((ach ^ (arow0 & 7)) << 4);
    const uint32_t BdOff = brow0 * 256 + ((((bch & 8) | ((bch ^ brow0) & 7))) << 4);

#define ISSUE_STAGE(st, kb)                                                    \
    {                                                                          \
        uint32_t Ad = sb + (st) * STG_BYTES + AdOff;                           \
        uint32_t Bd = sb + (st) * STG_BYTES + 16384 + BdOff;                   \
        const __half* As = Aq + (size_t)arow0 * K + (kb) + ach * 8;            \
        const __half* Bs = Bq + (size_t)((kb) + brow0) * N + bch * 8;          \
        _Pragma("unroll")                                                      \
        for (int p = 0; p < 8; p++) {                                          \
            cp16(Ad + p * 2048, As + (size_t)p * 16 * K);                      \
            cp16(Bd + p * 2048, Bs + (size_t)p * 8 * N);                       \
        }                                                                      \
        asm volatile("cp.async.commit_group;\n");                              \
    }

    float c[4][8][4];
    #pragma unroll
    for (int mi = 0; mi < 4; mi++)
        #pragma unroll
        for (int ni = 0; ni < 8; ni++)
            #pragma unroll
            for (int u = 0; u < 4; u++) c[mi][ni][u] = 0.f;

    const int ktiles = K >> 6;

    ISSUE_STAGE(0, 0);
    ISSUE_STAGE(1, 64);

    for (int u = 0; u < ktiles; u++) {
        asm volatile("cp.async.wait_group 1;\n");
        __syncthreads();

        if (u + 2 < ktiles) {
            const int stn = (u + 2) % SGS3;
            ISSUE_STAGE(stn, (u + 2) * 64);
        } else {
            asm volatile("cp.async.commit_group;\n");
        }

        const int st = u % SGS3;
        const uint32_t Ab = sb + st * STG_BYTES;
        const uint32_t Bb = Ab + 16384;

        #pragma unroll
        for (int s = 0; s < 4; s++) {
            uint32_t af[4][4], bf[4][4];
            const int ac = ((2 * s + aHi) ^ i7) << 4;
            #pragma unroll
            for (int mi = 0; mi < 4; mi++)
                ldsm_x4(af[mi], Ab + (aRow + mi * 16) * 128 + ac);
            const int rowB = s * 16 + (g8 & 1) * 8 + i7;
            #pragma unroll
            for (int db = 0; db < 4; db++) {
                const int nc = warpN * 8 + 2 * db + (g8 >> 1);
                uint32_t addr = Bb + rowB * 256 +
                                (((nc & 8) | ((nc ^ rowB) & 7)) << 4);
                ldsm_x4_t(bf[db], addr);
            }
            #pragma unroll
            for (int mi = 0; mi < 4; mi++)
                #pragma unroll
                for (int ni = 0; ni < 8; ni++)
                    mma_f16(c[mi][ni], af[mi],
                            bf[ni >> 1][(ni & 1) * 2], bf[ni >> 1][(ni & 1) * 2 + 1]);
        }
    }
#undef ISSUE_STAGE

    const int gid = lane >> 2, tig = lane & 3;
    #pragma unroll
    for (int mi = 0; mi < 4; mi++) {
        const int r0 = bm * 128 + warpM * 64 + mi * 16 + gid;
        const int r1 = r0 + 8;
        #pragma unroll
        for (int ni = 0; ni < 8; ni++) {
            const int col = bn * 128 + warpN * 64 + ni * 8 + 2 * tig;
            float v0 = c[mi][ni][0], v1 = c[mi][ni][1];
            float v2 = c[mi][ni][2], v3 = c[mi][ni][3];
            if (EPI == 0) {
                float* C = (float*)Cv;
                float2 o0; o0.x = v0; o0.y = v1;
                float2 o1; o1.x = v2; o1.y = v3;
                *(float2*)(C + (size_t)r0 * N + col) = o0;
                *(float2*)(C + (size_t)r1 * N + col) = o1;
            } else if (EPI == 1) {
                float* C = (float*)Cv;
                const float b0 = bias[col], b1 = bias[col + 1];
                const float2 rA = *(const float2*)(res + (size_t)r0 * N + col);
                const float2 rB = *(const float2*)(res + (size_t)r1 * N + col);
                float2 o0; o0.x = v0 + b0 + rA.x; o0.y = v1 + b1 + rA.y;
                float2 o1; o1.x = v2 + b0 + rB.x; o1.y = v3 + b1 + rB.y;
                *(float2*)(C + (size_t)r0 * N + col) = o0;
                *(float2*)(C + (size_t)r1 * N + col) = o1;
            } else if (EPI == 2) {
                __half* C = (__half*)Cv;
                const float b0 = bias[col], b1 = bias[col + 1];
                v0 += b0; v1 += b1; v2 += b0; v3 += b1;
                v0 = v0 / (1.0f + __expf(-v0));
                v1 = v1 / (1.0f + __expf(-v1));
                v2 = v2 / (1.0f + __expf(-v2));
                v3 = v3 / (1.0f + __expf(-v3));
                *(__half2*)(C + (size_t)r0 * N + col) = __floats2half2_rn(v0, v1);
                *(__half2*)(C + (size_t)r1 * N + col) = __floats2half2_rn(v2, v3);
            } else {
                __half* C = (__half*)Cv;
                const float sc = (blockIdx.z == 0) ? 0.125f : 1.0f;
                *(__half2*)(C + (size_t)r0 * N + col) = __floats2half2_rn(v0*sc, v1*sc);
                *(__half2*)(C + (size_t)r1 * N + col) = __floats2half2_rn(v2*sc, v3*sc);
            }
        }
    }
}

// ---------------- fp16 tensor-core flash attention (causal, dbl-buffered KV) ---
// BYTE layout: Q [0,8K), K0 [8K,16K), K1 [16K,24K), V0 [24K,32K), V1 [32K,40K),
//              P [40K,48K)
__global__ __launch_bounds__(128)
void attn_f16(const __half* __restrict__ q, const __half* __restrict__ k,
              const __half* __restrict__ v, __half* __restrict__ o) {
    __shared__ __align__(16) __half sm[24576];
    const uint32_t sb = smem_u32(sm);
    const uint32_t Kb[2] = { sb + 8192,  sb + 16384 };
    const uint32_t Vb[2] = { sb + 24576, sb + 32768 };

    const int tid  = threadIdx.x;
    const int lane = tid & 31;
    const int warp = tid >> 5;
    const int g8   = lane >> 3;
    const int i7   = lane & 7;
    const int gid  = lane >> 2;
    const int tig  = lane & 3;
    const int qt = blockIdx.x, h = blockIdx.y, b = blockIdx.z;
    const size_t base = ((size_t)b * TT) * DD + (size_t)h * HDIM;

    const __half* qg = q + base + (size_t)qt * 64 * DD;
    const __half* kg = k + base;
    const __half* vg = v + base;

    #pragma unroll
    for (int p = 0; p < 4; p++) {
        int idx = tid + p * 128;
        int row = idx >> 3, ch = idx & 7;
        uint32_t dst = (row * 64 + ((ch ^ (row & 7)) << 3)) * 2;   // bytes
        cp16(sb + dst,    qg + (size_t)row * DD + ch * 8);
        cp16(Kb[0] + dst, kg + (size_t)row * DD + ch * 8);
        cp16(Vb[0] + dst, vg + (size_t)row * DD + ch * 8);
    }
    asm volatile("cp.async.commit_group;\n");

    uint32_t qf[4][4];
    float oacc[8][4];
    #pragma unroll
    for (int nt = 0; nt < 8; nt++)
        #pragma unroll
        for (int u = 0; u < 4; u++) oacc[nt][u] = 0.f;

    float m0 = -INFINITY, m1 = -INFINITY, l0 = 0.f, l1 = 0.f;
    const int r0 = qt * 64 + warp * 16 + gid;
    const int r1 = r0 + 8;
    const uint32_t Pw = sb + 40960 + warp * 2048;           // asm reads
    char* Pg = (char*)sm + 40960 + warp * 2048;             // C++ stores

    for (int kt = 0; kt <= qt; kt++) {
        const int cur = kt & 1;
        if (kt < qt) {
            const int nxt = (kt + 1) & 1;
            #pragma unroll
            for (int p = 0; p < 4; p++) {
                int idx = tid + p * 128;
                int row = idx >> 3, ch = idx & 7;
                uint32_t dst = (row * 64 + ((ch ^ (row & 7)) << 3)) * 2;
                const size_t gro = (size_t)((kt + 1) * 64 + row) * DD + ch * 8;
                cp16(Kb[nxt] + dst, kg + gro);
                cp16(Vb[nxt] + dst, vg + gro);
            }
            asm volatile("cp.async.commit_group;\n");
            asm volatile("cp.async.wait_group 1;\n");
        } else {
            asm volatile("cp.async.wait_group 0;\n");
        }
        __syncthreads();

        if (kt == 0) {
            const int rowQ = warp * 16 + (g8 & 1) * 8 + i7;
            #pragma unroll
            for (int s4 = 0; s4 < 4; s4++) {
                uint32_t addr = sb +
                    (rowQ * 64 + (((2 * s4 + (g8 >> 1)) ^ (rowQ & 7)) << 3)) * 2;
                ldsm_x4(qf[s4], addr);
            }
        }

        // ---- S = Q @ K^T ----
        float s[8][4];
        #pragma unroll
        for (int nt = 0; nt < 8; nt++)
            s[nt][0] = s[nt][1] = s[nt][2] = s[nt][3] = 0.f;
        #pragma unroll
        for (int s4 = 0; s4 < 4; s4++) {
            #pragma unroll
            for (int ntb = 0; ntb < 4; ntb++) {
                const int rowK = ntb * 16 + (g8 >> 1) * 8 + i7;
                uint32_t addr = Kb[cur] + (rowK * 64 +
                                (((2 * s4 + (g8 & 1)) ^ (rowK & 7)) << 3)) * 2;
                uint32_t bf[4];
                ldsm_x4(bf, addr);
                mma_f16(s[2 * ntb],     qf[s4], bf[0], bf[1]);
                mma_f16(s[2 * ntb + 1], qf[s4], bf[2], bf[3]);
            }
        }

        if (kt == qt) {
            #pragma unroll
            for (int nt = 0; nt < 8; nt++) {
                int cc = kt * 64 + nt * 8 + 2 * tig;
                if (cc     > r0) s[nt][0] = -INFINITY;
                if (cc + 1 > r0) s[nt][1] = -INFINITY;
                if (cc     > r1) s[nt][2] = -INFINITY;
                if (cc + 1 > r1) s[nt][3] = -INFINITY;
            }
        }

        // ---- online softmax ----
        float mt0 = -INFINITY, mt1 = -INFINITY;
        #pragma unroll
        for (int nt = 0; nt < 8; nt++) {
            mt0 = fmaxf(mt0, fmaxf(s[nt][0], s[nt][1]));
            mt1 = fmaxf(mt1, fmaxf(s[nt][2], s[nt][3]));
        }
        mt0 = fmaxf(mt0, __shfl_xor_sync(0xFFFFFFFFu, mt0, 1));
        mt0 = fmaxf(mt0, __shfl_xor_sync(0xFFFFFFFFu, mt0, 2));
        mt1 = fmaxf(mt1, __shfl_xor_sync(0xFFFFFFFFu, mt1, 1));
        mt1 = fmaxf(mt1, __shfl_xor_sync(0xFFFFFFFFu, mt1, 2));
        const float mn0 = fmaxf(m0, mt0), mn1 = fmaxf(m1, mt1);
        const float a0 = __expf(m0 - mn0), a1 = __expf(m1 - mn1);

        float ls0 = 0.f, ls1 = 0.f;
        #pragma unroll
        for (int nt = 0; nt < 8; nt++) {
            float p0 = __expf(s[nt][0] - mn0);
            float p1 = __expf(s[nt][1] - mn0);
            float p2 = __expf(s[nt][2] - mn1);
            float p3 = __expf(s[nt][3] - mn1);
            ls0 += p0 + p1; ls1 += p2 + p3;
            const int rA = gid, rB = gid + 8;
            *(__half2*)(Pg + (rA * 64 + ((nt ^ (rA & 7)) << 3) + 2 * tig) * 2) =
                __floats2half2_rn(p0, p1);
            *(__half2*)(Pg + (rB * 64 + ((nt ^ (rB & 7)) << 3) + 2 * tig) * 2) =
                __floats2half2_rn(p2, p3);
        }
        ls0 += __shfl_xor_sync(0xFFFFFFFFu, ls0, 1);
        ls0 += __shfl_xor_sync(0xFFFFFFFFu, ls0, 2);
        ls1 += __shfl_xor_sync(0xFFFFFFFFu, ls1, 1);
        ls1 += __shfl_xor_sync(0xFFFFFFFFu, ls1, 2);
        l0 = l0 * a0 + ls0;
        l1 = l1 * a1 + ls1;
        m0 = mn0; m1 = mn1;

        #pragma unroll
        for (int nt = 0; nt < 8; nt++) {
            oacc[nt][0] *= a0; oacc[nt][1] *= a0;
            oacc[nt][2] *= a1; oacc[nt][3] *= a1;
        }
        __syncwarp();

        // ---- O += P @ V ----
        #pragma unroll
        for (int s4 = 0; s4 < 4; s4++) {
            uint32_t pf[4];
            const int rowP = (g8 & 1) * 8 + i7;
            ldsm_x4(pf, Pw + (rowP * 64 + (((2 * s4 + (g8 >> 1)) ^ (rowP & 7)) << 3)) * 2);
            const int rowV = s4 * 16 + (g8 & 1) * 8 + i7;
            #pragma unroll
            for (int db = 0; db < 4; db++) {
                uint32_t bf[4];
                uint32_t addr = Vb[cur] + (rowV * 64 +
                                (((2 * db + (g8 >> 1)) ^ (rowV & 7)) << 3)) * 2;
                ldsm_x4_t(bf, addr);
                mma_f16(oacc[2 * db],     pf, bf[0], bf[1]);
                mma_f16(oacc[2 * db + 1], pf, bf[2], bf[3]);
            }
        }
        __syncthreads();   // protect buffer reuse by next prefetch
    }

    const float li0 = 1.0f / l0, li1 = 1.0f / l1;
    __half* og = o + base;
    #pragma unroll
    for (int nt = 0; nt < 8; nt++) {
        const int col = nt * 8 + 2 * tig;
        *(__half2*)(og + (size_t)r0 * DD + col) =
            __floats2half2_rn(oacc[nt][0] * li0, oacc[nt][1] * li0);
        *(__half2*)(og + (size_t)r1 * DD + col) =
            __floats2half2_rn(oacc[nt][2] * li1, oacc[nt][3] * li1);
    }
}

// ---------------- launch ----------------
extern "C" void kernel_launch(void* const* d_in, const int* in_sizes, int n_in,
                              void* d_out, int out_size) {
    const float* x     = (const float*)d_in[0];
    const float* Wq    = (const float*)d_in[2];
    const float* Wk    = (const float*)d_in[3];
    const float* Wv    = (const float*)d_in[4];
    const float* Wo    = (const float*)d_in[5];
    const float* bo    = (const float*)d_in[6];
    const float* W1    = (const float*)d_in[7];
    const float* b1    = (const float*)d_in[8];
    const float* W2    = (const float*)d_in[9];
    const float* b2    = (const float*)d_in[10];
    const float* gattn = (const float*)d_in[11];
    const float* gff   = (const float*)d_in[12];
    float* out = (float*)d_out;

    __half *xa, *q, *k, *v, *at, *hb, *wh;
    float *x1;
    cudaGetSymbolAddress((void**)&xa, g_xa);
    cudaGetSymbolAddress((void**)&q,  g_q);
    cudaGetSymbolAddress((void**)&k,  g_k);
    cudaGetSymbolAddress((void**)&v,  g_v);
    cudaGetSymbolAddress((void**)&at, g_at);
    cudaGetSymbolAddress((void**)&x1, g_x1);
    cudaGetSymbolAddress((void**)&hb, g_h);
    cudaGetSymbolAddress((void**)&wh, g_wh);

    __half* Wq_h = wh;                               // [K,N] fp16, packed arena
    __half* Wk_h = wh + (size_t)1*1024*1024;
    __half* Wv_h = wh + (size_t)2*1024*1024;
    __half* Wo_h = wh + (size_t)3*1024*1024;
    __half* W1_h = wh + (size_t)4*1024*1024;
    __half* W2_h = wh + (size_t)8*1024*1024;

    cudaFuncSetAttribute(gemm_f16<1>, cudaFuncAttributeMaxDynamicSharedMemorySize, GEMM_SMEM);
    cudaFuncSetAttribute(gemm_f16<2>, cudaFuncAttributeMaxDynamicSharedMemorySize, GEMM_SMEM);
    cudaFuncSetAttribute(gemm_f16<3>, cudaFuncAttributeMaxDynamicSharedMemorySize, GEMM_SMEM);

    // 0. fused fp32 -> fp16 weight convert (one launch)
    convert_all<<<2048, 256>>>((const float4*)Wq, (const float4*)Wk,
                               (const float4*)Wv, (const float4*)Wo,
                               (const float4*)W1, (const float4*)W2,
                               (uint4*)wh);

    // 1. rmsnorm(x, g_attn) -> xa (fp16)
    rmsnorm_kernel<<<ROWS, 256>>>(x, gattn, xa);

    // 2. QKV projections (fp16 out; Q pre-scaled by 0.125)
    {
        dim3 grid(DD / 128, ROWS / 128, 3);
        gemm_f16<3><<<grid, 128, GEMM_SMEM>>>(xa, Wq_h, Wk_h, Wv_h,
                                              q, k, v, nullptr, nullptr, DD, DD);
    }

    // 3. causal attention (fp16 MMA) -> at (fp16)
    {
        dim3 grid(TT / 64, HH, BB);
        attn_f16<<<grid, 128>>>(q, k, v, at);
    }

    // 4. x1 = x + at @ Wo + bo
    {
        dim3 grid(DD / 128, ROWS / 128, 1);
        gemm_f16<1><<<grid, 128, GEMM_SMEM>>>(at, Wo_h, Wo_h, Wo_h,
                                              x1, x1, x1, bo, x, DD, DD);
    }

    // 5. rmsnorm(x1, g_ff) -> xa (fp16)
    rmsnorm_kernel<<<ROWS, 256>>>(x1, gff, xa);

    // 6. h = silu(xa @ W1 + b1) -> hb (fp16)
    {
        dim3 grid(FF / 128, ROWS / 128, 1);
        gemm_f16<2><<<grid, 128, GEMM_SMEM>>>(xa, W1_h, W1_h, W1_h,
                                              hb, hb, hb, b1, nullptr, FF, DD);
    }

    // 7. out = x1 + hb @ W2 + b2
    {
        dim3 grid(DD / 128, ROWS / 128, 1);
        gemm_f16<1><<<grid, 128, GEMM_SMEM>>>(hb, W2_h, W2_h, W2_h,
                                              out, out, out, b2, x1, DD, FF);
    }
}

// round 12
// speedup vs baseline: 11.4999x; 1.0122x over previous
#include <cuda_runtime.h>
#include <cuda_fp16.h>
#include <cstdint>

// ---------------- problem constants ----------------
#define BB   2
#define TT   2048
#define DD   1024
#define HH   16
#define HDIM 64
#define FF   4096
#define ROWS (BB*TT)          // 4096

// ---------------- scratch (device globals) ----------------
__device__ __half g_xa [ROWS*DD];            // rmsnorm out (fp16)
__device__ __half g_q  [ROWS*DD];            // Q (pre-scaled by 0.125, fp16)
__device__ __half g_k  [ROWS*DD];
__device__ __half g_v  [ROWS*DD];
__device__ __half g_at [ROWS*DD];            // attention out (fp16)
__device__ float  g_x1 [ROWS*DD];
__device__ __half g_h  [(size_t)ROWS*FF];    // silu out (fp16)
__device__ __half g_wh [(size_t)12*1024*1024]; // fp16 weights, [K,N] layout, packed

// ---------------- helpers ----------------
__device__ __forceinline__ uint32_t smem_u32(const void* p) {
    return (uint32_t)__cvta_generic_to_shared(p);
}
__device__ __forceinline__ void mma_f16(float* c, const uint32_t* a,
                                        uint32_t b0, uint32_t b1) {
    asm volatile(
        "mma.sync.aligned.m16n8k16.row.col.f32.f16.f16.f32 "
        "{%0,%1,%2,%3},{%4,%5,%6,%7},{%8,%9},{%0,%1,%2,%3};\n"
        : "+f"(c[0]), "+f"(c[1]), "+f"(c[2]), "+f"(c[3])
        : "r"(a[0]), "r"(a[1]), "r"(a[2]), "r"(a[3]), "r"(b0), "r"(b1));
}
__device__ __forceinline__ void ldsm_x4(uint32_t* r, uint32_t saddr) {
    asm volatile("ldmatrix.sync.aligned.m8n8.x4.shared.b16 {%0,%1,%2,%3}, [%4];"
                 : "=r"(r[0]), "=r"(r[1]), "=r"(r[2]), "=r"(r[3]) : "r"(saddr));
}
__device__ __forceinline__ void ldsm_x4_t(uint32_t* r, uint32_t saddr) {
    asm volatile("ldmatrix.sync.aligned.m8n8.x4.trans.shared.b16 {%0,%1,%2,%3}, [%4];"
                 : "=r"(r[0]), "=r"(r[1]), "=r"(r[2]), "=r"(r[3]) : "r"(saddr));
}
__device__ __forceinline__ void cp16(uint32_t saddr, const void* g) {
    asm volatile("cp.async.cg.shared.global [%0], [%1], 16;\n" :: "r"(saddr), "l"(g));
}

// ---------------- fused weight convert fp32 -> fp16 (all 6 weights, 1 launch) --
#define CVT_TOTAL 1572864
__global__ __launch_bounds__(256)
void convert_all(const float4* __restrict__ wq, const float4* __restrict__ wk,
                 const float4* __restrict__ wv, const float4* __restrict__ wo,
                 const float4* __restrict__ w1, const float4* __restrict__ w2,
                 uint4* __restrict__ dst) {
    const int nth = gridDim.x * 256;
    for (int i = blockIdx.x * 256 + threadIdx.x; i < CVT_TOTAL; i += nth) {
        const float4* src;
        int off;
        if (i < 524288) {
            int r = i >> 17;
            src = (r == 0) ? wq : (r == 1) ? wk : (r == 2) ? wv : wo;
            off = i & 131071;
        } else if (i < 1048576) {
            src = w1; off = i - 524288;
        } else {
            src = w2; off = i - 1048576;
        }
        float4 a = src[2 * off], b = src[2 * off + 1];
        __half2 h0 = __floats2half2_rn(a.x, a.y);
        __half2 h1 = __floats2half2_rn(a.z, a.w);
        __half2 h2 = __floats2half2_rn(b.x, b.y);
        __half2 h3 = __floats2half2_rn(b.z, b.w);
        uint4 o;
        o.x = *(uint32_t*)&h0; o.y = *(uint32_t*)&h1;
        o.z = *(uint32_t*)&h2; o.w = *(uint32_t*)&h3;
        dst[i] = o;
    }
}

// ---------------- rmsnorm (fp16 output) ----------------
__global__ __launch_bounds__(256)
void rmsnorm_kernel(const float* __restrict__ x, const float* __restrict__ g,
                    __half* __restrict__ out) {
    __shared__ float red[256];
    const int row = blockIdx.x;
    const int tid = threadIdx.x;
    const float4 v = ((const float4*)(x + (size_t)row * DD))[tid];
    float ss = v.x*v.x + v.y*v.y + v.z*v.z + v.w*v.w;
    red[tid] = ss;
    __syncthreads();
    #pragma unroll
    for (int s = 128; s > 0; s >>= 1) {
        if (tid < s) red[tid] += red[tid + s];
        __syncthreads();
    }
    const float norm = rsqrtf(red[0] * (1.0f / DD) + 1e-5f);
    const float4 gv = ((const float4*)g)[tid];
    __half2 h01 = __floats2half2_rn(v.x * norm * gv.x, v.y * norm * gv.y);
    __half2 h23 = __floats2half2_rn(v.z * norm * gv.z, v.w * norm * gv.w);
    uint2 pk; pk.x = *(uint32_t*)&h01; pk.y = *(uint32_t*)&h23;
    ((uint2*)(out + (size_t)row * DD))[tid] = pk;
}

// ---------------- fp16 tensor-core GEMM, 3-stage cp.async pipeline ----------
// C[M,N] = A[M,K] @ W[K,N]. 128 threads, 2x2 warps, 64x64 warp tile.
#define SGS3 3
#define STG_BYTES 32768
#define GEMM_SMEM (SGS3 * STG_BYTES)

template <int EPI>
__global__ __launch_bounds__(128, 2)
void gemm_f16(const __half* __restrict__ A,
              const __half* __restrict__ B0, const __half* __restrict__ B1,
              const __half* __restrict__ B2,
              void* C0v, void* C1v, void* C2v,
              const float* __restrict__ bias, const float* __restrict__ res,
              int N, int K) {
    extern __shared__ __align__(16) char dynsm[];
    const uint32_t sb = smem_u32(dynsm);

    const __half* Bw = (blockIdx.z == 0) ? B0 : (blockIdx.z == 1 ? B1 : B2);
    void* Cv = (blockIdx.z == 0) ? C0v : (blockIdx.z == 1 ? C1v : C2v);

    const int tid   = threadIdx.x;
    const int lane  = tid & 31;
    const int warp  = tid >> 5;
    const int warpM = warp & 1;
    const int warpN = warp >> 1;
    const int g8    = lane >> 3;
    const int i7    = lane & 7;

    const int bm = blockIdx.y, bn = blockIdx.x;
    const __half* Aq = A  + (size_t)bm * 128 * K;
    const __half* Bq = Bw + bn * 128;

    const int aRow = warpM * 64 + (g8 & 1) * 8 + i7;
    const int aHi  = g8 >> 1;

    const int arow0 = tid >> 3, ach = tid & 7;
    const int brow0 = tid >> 4, bch = tid & 15;
    const uint32_t AdOff = arow0 * 128 + ((ach ^ (arow0 & 7)) << 4);
    const uint32_t BdOff = brow0 * 256 + ((((bch & 8) | ((bch ^ brow0) & 7))) << 4);

#define ISSUE_STAGE(st, kb)                                                    \
    {                                                                          \
        uint32_t Ad = sb + (st) * STG_BYTES + AdOff;                           \
        uint32_t Bd = sb + (st) * STG_BYTES + 16384 + BdOff;                   \
        const __half* As = Aq + (size_t)arow0 * K + (kb) + ach * 8;            \
        const __half* Bs = Bq + (size_t)((kb) + brow0) * N + bch * 8;          \
        _Pragma("unroll")                                                      \
        for (int p = 0; p < 8; p++) {                                          \
            cp16(Ad + p * 2048, As + (size_t)p * 16 * K);                      \
            cp16(Bd + p * 2048, Bs + (size_t)p * 8 * N);                       \
        }                                                                      \
        asm volatile("cp.async.commit_group;\n");                              \
    }

    float c[4][8][4];
    #pragma unroll
    for (int mi = 0; mi < 4; mi++)
        #pragma unroll
        for (int ni = 0; ni < 8; ni++)
            #pragma unroll
            for (int u = 0; u < 4; u++) c[mi][ni][u] = 0.f;

    const int ktiles = K >> 6;

    ISSUE_STAGE(0, 0);
    ISSUE_STAGE(1, 64);

    for (int u = 0; u < ktiles; u++) {
        asm volatile("cp.async.wait_group 1;\n");
        __syncthreads();

        if (u + 2 < ktiles) {
            const int stn = (u + 2) % SGS3;
            ISSUE_STAGE(stn, (u + 2) * 64);
        } else {
            asm volatile("cp.async.commit_group;\n");
        }

        const int st = u % SGS3;
        const uint32_t Ab = sb + st * STG_BYTES;
        const uint32_t Bb = Ab + 16384;

        #pragma unroll
        for (int s = 0; s < 4; s++) {
            uint32_t af[4][4], bf[4][4];
            const int ac = ((2 * s + aHi) ^ i7) << 4;
            #pragma unroll
            for (int mi = 0; mi < 4; mi++)
                ldsm_x4(af[mi], Ab + (aRow + mi * 16) * 128 + ac);
            const int rowB = s * 16 + (g8 & 1) * 8 + i7;
            #pragma unroll
            for (int db = 0; db < 4; db++) {
                const int nc = warpN * 8 + 2 * db + (g8 >> 1);
                uint32_t addr = Bb + rowB * 256 +
                                (((nc & 8) | ((nc ^ rowB) & 7)) << 4);
                ldsm_x4_t(bf[db], addr);
            }
            #pragma unroll
            for (int mi = 0; mi < 4; mi++)
                #pragma unroll
                for (int ni = 0; ni < 8; ni++)
                    mma_f16(c[mi][ni], af[mi],
                            bf[ni >> 1][(ni & 1) * 2], bf[ni >> 1][(ni & 1) * 2 + 1]);
        }
    }
#undef ISSUE_STAGE

    const int gid = lane >> 2, tig = lane & 3;
    #pragma unroll
    for (int mi = 0; mi < 4; mi++) {
        const int r0 = bm * 128 + warpM * 64 + mi * 16 + gid;
        const int r1 = r0 + 8;
        #pragma unroll
        for (int ni = 0; ni < 8; ni++) {
            const int col = bn * 128 + warpN * 64 + ni * 8 + 2 * tig;
            float v0 = c[mi][ni][0], v1 = c[mi][ni][1];
            float v2 = c[mi][ni][2], v3 = c[mi][ni][3];
            if (EPI == 0) {
                float* C = (float*)Cv;
                float2 o0; o0.x = v0; o0.y = v1;
                float2 o1; o1.x = v2; o1.y = v3;
                *(float2*)(C + (size_t)r0 * N + col) = o0;
                *(float2*)(C + (size_t)r1 * N + col) = o1;
            } else if (EPI == 1) {
                float* C = (float*)Cv;
                const float b0 = bias[col], b1 = bias[col + 1];
                const float2 rA = *(const float2*)(res + (size_t)r0 * N + col);
                const float2 rB = *(const float2*)(res + (size_t)r1 * N + col);
                float2 o0; o0.x = v0 + b0 + rA.x; o0.y = v1 + b1 + rA.y;
                float2 o1; o1.x = v2 + b0 + rB.x; o1.y = v3 + b1 + rB.y;
                *(float2*)(C + (size_t)r0 * N + col) = o0;
                *(float2*)(C + (size_t)r1 * N + col) = o1;
            } else if (EPI == 2) {
                __half* C = (__half*)Cv;
                const float b0 = bias[col], b1 = bias[col + 1];
                v0 += b0; v1 += b1; v2 += b0; v3 += b1;
                v0 = v0 / (1.0f + __expf(-v0));
                v1 = v1 / (1.0f + __expf(-v1));
                v2 = v2 / (1.0f + __expf(-v2));
                v3 = v3 / (1.0f + __expf(-v3));
                *(__half2*)(C + (size_t)r0 * N + col) = __floats2half2_rn(v0, v1);
                *(__half2*)(C + (size_t)r1 * N + col) = __floats2half2_rn(v2, v3);
            } else {
                __half* C = (__half*)Cv;
                const float sc = (blockIdx.z == 0) ? 0.125f : 1.0f;
                *(__half2*)(C + (size_t)r0 * N + col) = __floats2half2_rn(v0*sc, v1*sc);
                *(__half2*)(C + (size_t)r1 * N + col) = __floats2half2_rn(v2*sc, v3*sc);
            }
        }
    }
}

// ---------------- fp16 flash attention (causal, balanced: 2 q-tiles/CTA) ------
// blockIdx.x = i in [0,16): pass 0 handles qt=i, pass 1 handles qt=31-i.
// BYTE layout: Q [0,8K), K0 [8K,16K), K1 [16K,24K), V0 [24K,32K), V1 [32K,40K),
//              P [40K,48K)
#define NQT (TT / 64)     // 32
__global__ __launch_bounds__(128)
void attn_f16(const __half* __restrict__ q, const __half* __restrict__ k,
              const __half* __restrict__ v, __half* __restrict__ o) {
    __shared__ __align__(16) __half sm[24576];
    const uint32_t sb = smem_u32(sm);
    const uint32_t Kb[2] = { sb + 8192,  sb + 16384 };
    const uint32_t Vb[2] = { sb + 24576, sb + 32768 };

    const int tid  = threadIdx.x;
    const int lane = tid & 31;
    const int warp = tid >> 5;
    const int g8   = lane >> 3;
    const int i7   = lane & 7;
    const int gid  = lane >> 2;
    const int tig  = lane & 3;
    const int h = blockIdx.y, b = blockIdx.z;
    const size_t base = ((size_t)b * TT) * DD + (size_t)h * HDIM;

    const __half* kg = k + base;
    const __half* vg = v + base;
    const uint32_t Pw = sb + 40960 + warp * 2048;           // asm reads
    char* Pg = (char*)sm + 40960 + warp * 2048;             // C++ stores

    #pragma unroll
    for (int pass = 0; pass < 2; pass++) {
        const int qt = (pass == 0) ? blockIdx.x : (NQT - 1 - blockIdx.x);
        const __half* qg = q + base + (size_t)qt * 64 * DD;

        // prologue: Q + K/V tile 0 in one group
        #pragma unroll
        for (int p = 0; p < 4; p++) {
            int idx = tid + p * 128;
            int row = idx >> 3, ch = idx & 7;
            uint32_t dst = (row * 64 + ((ch ^ (row & 7)) << 3)) * 2;   // bytes
            cp16(sb + dst,    qg + (size_t)row * DD + ch * 8);
            cp16(Kb[0] + dst, kg + (size_t)row * DD + ch * 8);
            cp16(Vb[0] + dst, vg + (size_t)row * DD + ch * 8);
        }
        asm volatile("cp.async.commit_group;\n");

        uint32_t qf[4][4];
        float oacc[8][4];
        #pragma unroll
        for (int nt = 0; nt < 8; nt++)
            #pragma unroll
            for (int u = 0; u < 4; u++) oacc[nt][u] = 0.f;

        float m0 = -INFINITY, m1 = -INFINITY, l0 = 0.f, l1 = 0.f;
        const int r0 = qt * 64 + warp * 16 + gid;
        const int r1 = r0 + 8;

        for (int kt = 0; kt <= qt; kt++) {
            const int cur = kt & 1;
            if (kt < qt) {
                const int nxt = (kt + 1) & 1;
                #pragma unroll
                for (int p = 0; p < 4; p++) {
                    int idx = tid + p * 128;
                    int row = idx >> 3, ch = idx & 7;
                    uint32_t dst = (row * 64 + ((ch ^ (row & 7)) << 3)) * 2;
                    const size_t gro = (size_t)((kt + 1) * 64 + row) * DD + ch * 8;
                    cp16(Kb[nxt] + dst, kg + gro);
                    cp16(Vb[nxt] + dst, vg + gro);
                }
                asm volatile("cp.async.commit_group;\n");
                asm volatile("cp.async.wait_group 1;\n");
            } else {
                asm volatile("cp.async.wait_group 0;\n");
            }
            __syncthreads();

            if (kt == 0) {
                const int rowQ = warp * 16 + (g8 & 1) * 8 + i7;
                #pragma unroll
                for (int s4 = 0; s4 < 4; s4++) {
                    uint32_t addr = sb +
                        (rowQ * 64 + (((2 * s4 + (g8 >> 1)) ^ (rowQ & 7)) << 3)) * 2;
                    ldsm_x4(qf[s4], addr);
                }
            }

            // ---- S = Q @ K^T ----
            float s[8][4];
            #pragma unroll
            for (int nt = 0; nt < 8; nt++)
                s[nt][0] = s[nt][1] = s[nt][2] = s[nt][3] = 0.f;
            #pragma unroll
            for (int s4 = 0; s4 < 4; s4++) {
                #pragma unroll
                for (int ntb = 0; ntb < 4; ntb++) {
                    const int rowK = ntb * 16 + (g8 >> 1) * 8 + i7;
                    uint32_t addr = Kb[cur] + (rowK * 64 +
                                    (((2 * s4 + (g8 & 1)) ^ (rowK & 7)) << 3)) * 2;
                    uint32_t bf[4];
                    ldsm_x4(bf, addr);
                    mma_f16(s[2 * ntb],     qf[s4], bf[0], bf[1]);
                    mma_f16(s[2 * ntb + 1], qf[s4], bf[2], bf[3]);
                }
            }

            if (kt == qt) {
                #pragma unroll
                for (int nt = 0; nt < 8; nt++) {
                    int cc = kt * 64 + nt * 8 + 2 * tig;
                    if (cc     > r0) s[nt][0] = -INFINITY;
                    if (cc + 1 > r0) s[nt][1] = -INFINITY;
                    if (cc     > r1) s[nt][2] = -INFINITY;
                    if (cc + 1 > r1) s[nt][3] = -INFINITY;
                }
            }

            // ---- online softmax ----
            float mt0 = -INFINITY, mt1 = -INFINITY;
            #pragma unroll
            for (int nt = 0; nt < 8; nt++) {
                mt0 = fmaxf(mt0, fmaxf(s[nt][0], s[nt][1]));
                mt1 = fmaxf(mt1, fmaxf(s[nt][2], s[nt][3]));
            }
            mt0 = fmaxf(mt0, __shfl_xor_sync(0xFFFFFFFFu, mt0, 1));
            mt0 = fmaxf(mt0, __shfl_xor_sync(0xFFFFFFFFu, mt0, 2));
            mt1 = fmaxf(mt1, __shfl_xor_sync(0xFFFFFFFFu, mt1, 1));
            mt1 = fmaxf(mt1, __shfl_xor_sync(0xFFFFFFFFu, mt1, 2));
            const float mn0 = fmaxf(m0, mt0), mn1 = fmaxf(m1, mt1);
            const float a0 = __expf(m0 - mn0), a1 = __expf(m1 - mn1);

            float ls0 = 0.f, ls1 = 0.f;
            #pragma unroll
            for (int nt = 0; nt < 8; nt++) {
                float p0 = __expf(s[nt][0] - mn0);
                float p1 = __expf(s[nt][1] - mn0);
                float p2 = __expf(s[nt][2] - mn1);
                float p3 = __expf(s[nt][3] - mn1);
                ls0 += p0 + p1; ls1 += p2 + p3;
                const int rA = gid, rB = gid + 8;
                *(__half2*)(Pg + (rA * 64 + ((nt ^ (rA & 7)) << 3) + 2 * tig) * 2) =
                    __floats2half2_rn(p0, p1);
                *(__half2*)(Pg + (rB * 64 + ((nt ^ (rB & 7)) << 3) + 2 * tig) * 2) =
                    __floats2half2_rn(p2, p3);
            }
            ls0 += __shfl_xor_sync(0xFFFFFFFFu, ls0, 1);
            ls0 += __shfl_xor_sync(0xFFFFFFFFu, ls0, 2);
            ls1 += __shfl_xor_sync(0xFFFFFFFFu, ls1, 1);
            ls1 += __shfl_xor_sync(0xFFFFFFFFu, ls1, 2);
            l0 = l0 * a0 + ls0;
            l1 = l1 * a1 + ls1;
            m0 = mn0; m1 = mn1;

            #pragma unroll
            for (int nt = 0; nt < 8; nt++) {
                oacc[nt][0] *= a0; oacc[nt][1] *= a0;
                oacc[nt][2] *= a1; oacc[nt][3] *= a1;
            }
            __syncwarp();

            // ---- O += P @ V ----
            #pragma unroll
            for (int s4 = 0; s4 < 4; s4++) {
                uint32_t pf[4];
                const int rowP = (g8 & 1) * 8 + i7;
                ldsm_x4(pf, Pw + (rowP * 64 +
                        (((2 * s4 + (g8 >> 1)) ^ (rowP & 7)) << 3)) * 2);
                const int rowV = s4 * 16 + (g8 & 1) * 8 + i7;
                #pragma unroll
                for (int db = 0; db < 4; db++) {
                    uint32_t bf[4];
                    uint32_t addr = Vb[cur] + (rowV * 64 +
                                    (((2 * db + (g8 >> 1)) ^ (rowV & 7)) << 3)) * 2;
                    ldsm_x4_t(bf, addr);
                    mma_f16(oacc[2 * db],     pf, bf[0], bf[1]);
                    mma_f16(oacc[2 * db + 1], pf, bf[2], bf[3]);
                }
            }
            __syncthreads();   // protect buffer reuse (next prefetch / next pass)
        }

        // write O as fp16
        const float li0 = 1.0f / l0, li1 = 1.0f / l1;
        __half* og = o + base;
        #pragma unroll
        for (int nt = 0; nt < 8; nt++) {
            const int col = nt * 8 + 2 * tig;
            *(__half2*)(og + (size_t)r0 * DD + col) =
                __floats2half2_rn(oacc[nt][0] * li0, oacc[nt][1] * li0);
            *(__half2*)(og + (size_t)r1 * DD + col) =
                __floats2half2_rn(oacc[nt][2] * li1, oacc[nt][3] * li1);
        }
    }
}

// ---------------- launch ----------------
extern "C" void kernel_launch(void* const* d_in, const int* in_sizes, int n_in,
                              void* d_out, int out_size) {
    const float* x     = (const float*)d_in[0];
    const float* Wq    = (const float*)d_in[2];
    const float* Wk    = (const float*)d_in[3];
    const float* Wv    = (const float*)d_in[4];
    const float* Wo    = (const float*)d_in[5];
    const float* bo    = (const float*)d_in[6];
    const float* W1    = (const float*)d_in[7];
    const float* b1    = (const float*)d_in[8];
    const float* W2    = (const float*)d_in[9];
    const float* b2    = (const float*)d_in[10];
    const float* gattn = (const float*)d_in[11];
    const float* gff   = (const float*)d_in[12];
    float* out = (float*)d_out;

    __half *xa, *q, *k, *v, *at, *hb, *wh;
    float *x1;
    cudaGetSymbolAddress((void**)&xa, g_xa);
    cudaGetSymbolAddress((void**)&q,  g_q);
    cudaGetSymbolAddress((void**)&k,  g_k);
    cudaGetSymbolAddress((void**)&v,  g_v);
    cudaGetSymbolAddress((void**)&at, g_at);
    cudaGetSymbolAddress((void**)&x1, g_x1);
    cudaGetSymbolAddress((void**)&hb, g_h);
    cudaGetSymbolAddress((void**)&wh, g_wh);

    __half* Wq_h = wh;                               // [K,N] fp16, packed arena
    __half* Wk_h = wh + (size_t)1*1024*1024;
    __half* Wv_h = wh + (size_t)2*1024*1024;
    __half* Wo_h = wh + (size_t)3*1024*1024;
    __half* W1_h = wh + (size_t)4*1024*1024;
    __half* W2_h = wh + (size_t)8*1024*1024;

    cudaFuncSetAttribute(gemm_f16<1>, cudaFuncAttributeMaxDynamicSharedMemorySize, GEMM_SMEM);
    cudaFuncSetAttribute(gemm_f16<2>, cudaFuncAttributeMaxDynamicSharedMemorySize, GEMM_SMEM);
    cudaFuncSetAttribute(gemm_f16<3>, cudaFuncAttributeMaxDynamicSharedMemorySize, GEMM_SMEM);

    // 0. fused fp32 -> fp16 weight convert (one launch)
    convert_all<<<2048, 256>>>((const float4*)Wq, (const float4*)Wk,
                               (const float4*)Wv, (const float4*)Wo,
                               (const float4*)W1, (const float4*)W2,
                               (uint4*)wh);

    // 1. rmsnorm(x, g_attn) -> xa (fp16)
    rmsnorm_kernel<<<ROWS, 256>>>(x, gattn, xa);

    // 2. QKV projections (fp16 out; Q pre-scaled by 0.125)
    {
        dim3 grid(DD / 128, ROWS / 128, 3);
        gemm_f16<3><<<grid, 128, GEMM_SMEM>>>(xa, Wq_h, Wk_h, Wv_h,
                                              q, k, v, nullptr, nullptr, DD, DD);
    }

    // 3. causal attention (balanced 2 q-tiles per CTA) -> at (fp16)
    {
        dim3 grid(TT / 128, HH, BB);
        attn_f16<<<grid, 128>>>(q, k, v, at);
    }

    // 4. x1 = x + at @ Wo + bo
    {
        dim3 grid(DD / 128, ROWS / 128, 1);
        gemm_f16<1><<<grid, 128, GEMM_SMEM>>>(at, Wo_h, Wo_h, Wo_h,
                                              x1, x1, x1, bo, x, DD, DD);
    }

    // 5. rmsnorm(x1, g_ff) -> xa (fp16)
    rmsnorm_kernel<<<ROWS, 256>>>(x1, gff, xa);

    // 6. h = silu(xa @ W1 + b1) -> hb (fp16)
    {
        dim3 grid(FF / 128, ROWS / 128, 1);
        gemm_f16<2><<<grid, 128, GEMM_SMEM>>>(xa, W1_h, W1_h, W1_h,
                                              hb, hb, hb, b1, nullptr, FF, DD);
    }

    // 7. out = x1 + hb @ W2 + b2
    {
        dim3 grid(DD / 128, ROWS / 128, 1);
        gemm_f16<1><<<grid, 128, GEMM_SMEM>>>(hb, W2_h, W2_h, W2_h,
                                              out, out, out, b2, x1, DD, FF);
    }
}